// round 1
// baseline (speedup 1.0000x reference)
#include <cuda_runtime.h>
#include <math.h>

#define D 64
#define NMAX 100000
#define EMAX 1200000

typedef unsigned long long ull;

// ---------------- scratch (device globals; no allocation allowed) ----------------
__device__ float g_node[NMAX * D];
__device__ float g_xh[NMAX * D];
__device__ float g_P[NMAX * D];
__device__ float g_Q[NMAX * D];
__device__ float g_agg[NMAX * D];
__device__ float g_asrc[NMAX * 4];
__device__ float g_adst[NMAX * 4];
__device__ float g_m[NMAX * 4];
__device__ float g_den[NMAX * 4];
__device__ float g_edge[EMAX * D];
__device__ float g_h[EMAX * D];
__device__ float g_logits[EMAX * 4];
__device__ float g_v[D * 4 + 4];

// ---------------- f32x2 helpers (FFMA2 only reachable via PTX) ----------------
__device__ __forceinline__ ull pk2(float x, float y) {
    ull r; asm("mov.b64 %0,{%1,%2};" : "=l"(r) : "f"(x), "f"(y)); return r;
}
__device__ __forceinline__ float2 upk(ull a) {
    float2 r; asm("mov.b64 {%0,%1},%2;" : "=f"(r.x), "=f"(r.y) : "l"(a)); return r;
}
__device__ __forceinline__ ull f2fma(ull a, ull b, ull c) {
    ull d; asm("fma.rn.f32x2 %0,%1,%2,%3;" : "=l"(d) : "l"(a), "l"(b), "l"(c)); return d;
}
__device__ __forceinline__ void redv4(float* p, float a, float b, float c, float d) {
    asm volatile("red.global.add.v4.f32 [%0], {%1,%2,%3,%4};"
                 :: "l"(p), "f"(a), "f"(b), "f"(c), "f"(d) : "memory");
}
__device__ __forceinline__ void atomicMaxF(float* a, float v) {
    if (v >= 0.f) atomicMax((int*)a, __float_as_int(v));
    else          atomicMin((unsigned int*)a, __float_as_uint(v));
}

// 64-wide row GEMM mainloop: acc[32] (f32x2) += in_row[k] * sW[k][:]
#define GEMM_MAINLOOP(A4, SW) do {                                                  \
    _Pragma("unroll 2")                                                             \
    for (int k4 = 0; k4 < 16; ++k4) {                                               \
        float4 aa4 = (A4)[k4];                                                      \
        const float* wr = (SW) + k4 * 256;                                          \
        { ull aa = pk2(aa4.x, aa4.x); const ull* w = (const ull*)(wr);              \
          _Pragma("unroll") for (int j = 0; j < 32; ++j) acc[j] = f2fma(aa, w[j], acc[j]); } \
        { ull aa = pk2(aa4.y, aa4.y); const ull* w = (const ull*)(wr + 64);         \
          _Pragma("unroll") for (int j = 0; j < 32; ++j) acc[j] = f2fma(aa, w[j], acc[j]); } \
        { ull aa = pk2(aa4.z, aa4.z); const ull* w = (const ull*)(wr + 128);        \
          _Pragma("unroll") for (int j = 0; j < 32; ++j) acc[j] = f2fma(aa, w[j], acc[j]); } \
        { ull aa = pk2(aa4.w, aa4.w); const ull* w = (const ull*)(wr + 192);        \
          _Pragma("unroll") for (int j = 0; j < 32; ++j) acc[j] = f2fma(aa, w[j], acc[j]); } \
    }                                                                               \
} while (0)

// ---------------- encoders ----------------
__global__ void k_node_enc(const int* __restrict__ x, const float* __restrict__ at,
                           float* __restrict__ node, int Nn) {
    int t = blockIdx.x * blockDim.x + threadIdx.x;
    if (t >= Nn * D) return;
    int i = t >> 6, j = t & 63;
    const int* xi = x + i * 9;
    float s = 0.f;
#pragma unroll
    for (int f = 0; f < 9; ++f) { int v = xi[f]; s += at[(f * 16 + v) * 64 + j]; }
    node[t] = s;
}

__global__ void k_edge_enc(const int* __restrict__ ea, const float* __restrict__ bt,
                           float* __restrict__ edge, int E) {
    int t = blockIdx.x * blockDim.x + threadIdx.x;
    if (t >= E * 64) return;
    int e = t >> 6, j = t & 63;
    const int* ei = ea + e * 3;
    float s = 0.f;
#pragma unroll
    for (int f = 0; f < 3; ++f) { int v = ei[f]; s += bt[(f * 8 + v) * 64 + j]; }
    edge[t] = s;
}

// ---------------- per-layer prep: fold edgeproj into a [64,4] vector ----------------
__global__ void k_prep(const float* __restrict__ epW, const float* __restrict__ epb,
                       const float* __restrict__ attE, float* __restrict__ vout) {
    int t = threadIdx.x;
    if (t < 256) {
        int k = t >> 2, h = t & 3;
        float s = 0.f;
#pragma unroll
        for (int c = 0; c < 16; ++c) s += epW[k * 64 + h * 16 + c] * attE[h * 16 + c];
        vout[k * 4 + h] = s;
    }
    if (t < 4) {
        float s = 0.f;
#pragma unroll
        for (int c = 0; c < 16; ++c) s += epb[t * 16 + c] * attE[t * 16 + c];
        vout[256 + t] = s;
    }
}

// ---------------- xh = node @ W, plus a_src/a_dst, plus inits ----------------
__global__ void __launch_bounds__(128) k_xh(const float* __restrict__ node, const float* __restrict__ W,
        const float* __restrict__ attS, const float* __restrict__ attD,
        float* __restrict__ xh, float* __restrict__ asrc, float* __restrict__ adst,
        float4* __restrict__ m4, float4* __restrict__ den4, float* __restrict__ agg, int Nn) {
    __shared__ __align__(16) float sW[4096];
    __shared__ float sAS[64], sAD[64];
    for (int i = threadIdx.x; i < 4096; i += 128) sW[i] = W[i];
    if (threadIdx.x < 64) { sAS[threadIdx.x] = attS[threadIdx.x]; sAD[threadIdx.x] = attD[threadIdx.x]; }
    __syncthreads();
    int row = blockIdx.x * 128 + threadIdx.x;
    if (row >= Nn) return;
    const float4* a4 = (const float4*)node + row * 16;
    ull acc[32];
#pragma unroll
    for (int j = 0; j < 32; ++j) acc[j] = 0ull;
    GEMM_MAINLOOP(a4, sW);
    float as[4] = {0, 0, 0, 0}, ad[4] = {0, 0, 0, 0};
    float* xr = xh + row * 64;
    float* ar = agg + row * 64;
#pragma unroll
    for (int j = 0; j < 32; ++j) {
        float2 v = upk(acc[j]);
        int c = 2 * j, h = c >> 4;
        as[h] += v.x * sAS[c] + v.y * sAS[c + 1];
        ad[h] += v.x * sAD[c] + v.y * sAD[c + 1];
        ((float2*)xr)[j] = v;
        ((float2*)ar)[j] = make_float2(0.f, 0.f);
    }
    ((float4*)asrc)[row] = make_float4(as[0], as[1], as[2], as[3]);
    ((float4*)adst)[row] = make_float4(ad[0], ad[1], ad[2], ad[3]);
    float ninf = __int_as_float(0xff800000);
    m4[row] = make_float4(ninf, ninf, ninf, ninf);
    den4[row] = make_float4(0.f, 0.f, 0.f, 0.f);
}

// ---------------- attention pass 1: logits + segment max ----------------
__global__ void __launch_bounds__(256) k_logits(const float* __restrict__ edge,
        const int* __restrict__ src, const int* __restrict__ dst,
        const float4* __restrict__ asrc4, const float4* __restrict__ adst4,
        const float* __restrict__ vedge, float4* __restrict__ logits4,
        float* __restrict__ m, int E) {
    __shared__ float sv[260];
    for (int i = threadIdx.x; i < 260; i += 256) sv[i] = vedge[i];
    __syncthreads();
    int e = blockIdx.x * 256 + threadIdx.x;
    if (e >= E) return;
    int s = src[e], d = dst[e];
    float a0 = sv[256], a1 = sv[257], a2 = sv[258], a3 = sv[259];
    const float4* er = (const float4*)edge + e * 16;
#pragma unroll 4
    for (int k4 = 0; k4 < 16; ++k4) {
        float4 a = er[k4];
        const float* v0 = sv + k4 * 16;
        a0 += a.x * v0[0] + a.y * v0[4] + a.z * v0[8]  + a.w * v0[12];
        a1 += a.x * v0[1] + a.y * v0[5] + a.z * v0[9]  + a.w * v0[13];
        a2 += a.x * v0[2] + a.y * v0[6] + a.z * v0[10] + a.w * v0[14];
        a3 += a.x * v0[3] + a.y * v0[7] + a.z * v0[11] + a.w * v0[15];
    }
    float4 as = asrc4[s], ad = adst4[d];
    float t0 = as.x + ad.x + a0, t1 = as.y + ad.y + a1;
    float t2 = as.z + ad.z + a2, t3 = as.w + ad.w + a3;
    t0 = t0 > 0.f ? t0 : 0.2f * t0;
    t1 = t1 > 0.f ? t1 : 0.2f * t1;
    t2 = t2 > 0.f ? t2 : 0.2f * t2;
    t3 = t3 > 0.f ? t3 : 0.2f * t3;
    logits4[e] = make_float4(t0, t1, t2, t3);
    float* md = m + d * 4;
    atomicMaxF(md + 0, t0); atomicMaxF(md + 1, t1);
    atomicMaxF(md + 2, t2); atomicMaxF(md + 3, t3);
}

// ---------------- attention pass 2: exp + segment sum ----------------
__global__ void __launch_bounds__(256) k_expsum(const int* __restrict__ dst,
        float4* __restrict__ logits4, const float4* __restrict__ m4,
        float* __restrict__ den, int E) {
    int e = blockIdx.x * 256 + threadIdx.x;
    if (e >= E) return;
    int d = dst[e];
    float4 lg = logits4[e];
    float4 mm = m4[d];
    float e0 = expf(lg.x - mm.x), e1 = expf(lg.y - mm.y);
    float e2 = expf(lg.z - mm.z), e3 = expf(lg.w - mm.w);
    logits4[e] = make_float4(e0, e1, e2, e3);
    redv4(den + d * 4, e0, e1, e2, e3);
}

// ---------------- attention pass 3: weighted scatter ----------------
__global__ void __launch_bounds__(256) k_agg(const int* __restrict__ src, const int* __restrict__ dst,
        const float4* __restrict__ logits4, const float4* __restrict__ den4,
        const float* __restrict__ xh, float* __restrict__ agg, int E) {
    int e = blockIdx.x * 256 + threadIdx.x;
    if (e >= E) return;
    int s = src[e], d = dst[e];
    float4 ex = logits4[e];
    float4 dn = den4[d];
    float al[4];
    al[0] = ex.x / (dn.x + 1e-16f); al[1] = ex.y / (dn.y + 1e-16f);
    al[2] = ex.z / (dn.z + 1e-16f); al[3] = ex.w / (dn.w + 1e-16f);
    const float4* xs = (const float4*)xh + s * 16;
    float* ag = agg + d * 64;
#pragma unroll
    for (int h = 0; h < 4; ++h) {
        float a = al[h];
#pragma unroll
        for (int q = 0; q < 4; ++q) {
            float4 v = xs[h * 4 + q];
            redv4(ag + h * 16 + q * 4, a * v.x, a * v.y, a * v.z, a * v.w);
        }
    }
}

// ---------------- node update: conv = agg + b -> LN -> relu -> residual ----------------
__global__ void __launch_bounds__(256) k_nodeup(const float* __restrict__ agg,
        const float* __restrict__ gatb, const float* __restrict__ lng,
        const float* __restrict__ lnb, float* __restrict__ node, int Nn) {
    int warp = blockIdx.x * 8 + (threadIdx.x >> 5);
    int lane = threadIdx.x & 31;
    if (warp >= Nn) return;
    float2 cv = ((const float2*)agg)[warp * 32 + lane];
    float2 gb = __ldg((const float2*)gatb + lane);
    cv.x += gb.x; cv.y += gb.y;
    float s = cv.x + cv.y, ss = cv.x * cv.x + cv.y * cv.y;
#pragma unroll
    for (int o = 16; o; o >>= 1) {
        s  += __shfl_xor_sync(0xffffffffu, s, o);
        ss += __shfl_xor_sync(0xffffffffu, ss, o);
    }
    float mu = s * (1.f / 64.f);
    float var = ss * (1.f / 64.f) - mu * mu;
    float r = rsqrtf(var + 1e-5f);
    float2 g = __ldg((const float2*)lng + lane), b = __ldg((const float2*)lnb + lane);
    float y0 = fmaxf((cv.x - mu) * r * g.x + b.x, 0.f);
    float y1 = fmaxf((cv.y - mu) * r * g.y + b.y, 0.f);
    float2* np = (float2*)node + warp * 32 + lane;
    float2 old = *np;
    *np = make_float2(old.x + y0, old.y + y1);
}

// ---------------- generic row GEMM: out = act(in @ W + bias), W is 64x64 ----------------
__global__ void __launch_bounds__(128) k_gemm64(const float* __restrict__ in,
        const float* __restrict__ W, const float* __restrict__ bias,
        float* __restrict__ out, int M, int act) {
    __shared__ __align__(16) float sW[4096];
    __shared__ __align__(16) float sB[64];
    for (int i = threadIdx.x; i < 4096; i += 128) sW[i] = W[i];
    if (threadIdx.x < 64) sB[threadIdx.x] = bias ? bias[threadIdx.x] : 0.f;
    __syncthreads();
    int row = blockIdx.x * 128 + threadIdx.x;
    if (row >= M) return;
    const float4* a4 = (const float4*)in + row * 16;
    ull acc[32];
#pragma unroll
    for (int j = 0; j < 32; ++j) acc[j] = pk2(sB[2 * j], sB[2 * j + 1]);
    GEMM_MAINLOOP(a4, sW);
    float* o = out + row * 64;
#pragma unroll
    for (int j = 0; j < 32; ++j) {
        float2 v = upk(acc[j]);
        if (act) { v.x = fmaxf(v.x, 0.f); v.y = fmaxf(v.y, 0.f); }
        ((float2*)o)[j] = v;
    }
}

// ---------------- edge-update stage 1: h = relu(P[src] + Q[dst] + edge @ W1c + b1) ----------------
__global__ void __launch_bounds__(128) k_eu1(const float* __restrict__ edge,
        const float* __restrict__ P, const float* __restrict__ Q,
        const int* __restrict__ src, const int* __restrict__ dst,
        const float* __restrict__ W1c, const float* __restrict__ b1,
        float* __restrict__ h, int E) {
    __shared__ __align__(16) float sW[4096];
    __shared__ __align__(16) float sB[64];
    for (int i = threadIdx.x; i < 4096; i += 128) sW[i] = W1c[i];
    if (threadIdx.x < 64) sB[threadIdx.x] = b1[threadIdx.x];
    __syncthreads();
    int e = blockIdx.x * 128 + threadIdx.x;
    if (e >= E) return;
    int s = src[e], d = dst[e];
    const float4* pr = (const float4*)P + s * 16;
    const float4* qr = (const float4*)Q + d * 16;
    ull acc[32];
#pragma unroll
    for (int q = 0; q < 16; ++q) {
        float4 pv = pr[q], qv = qr[q];
        acc[2 * q]     = pk2(pv.x + qv.x + sB[4 * q],     pv.y + qv.y + sB[4 * q + 1]);
        acc[2 * q + 1] = pk2(pv.z + qv.z + sB[4 * q + 2], pv.w + qv.w + sB[4 * q + 3]);
    }
    const float4* a4 = (const float4*)edge + e * 16;
    GEMM_MAINLOOP(a4, sW);
    float* o = h + e * 64;
#pragma unroll
    for (int j = 0; j < 32; ++j) {
        float2 v = upk(acc[j]);
        v.x = fmaxf(v.x, 0.f); v.y = fmaxf(v.y, 0.f);
        ((float2*)o)[j] = v;
    }
}

__global__ void k_copy(const float4* __restrict__ s, float4* __restrict__ d, int n4) {
    int i = blockIdx.x * blockDim.x + threadIdx.x;
    if (i < n4) d[i] = s[i];
}

// ---------------- launch ----------------
extern "C" void kernel_launch(void* const* d_in, const int* in_sizes, int n_in,
                              void* d_out, int out_size) {
    const int*   x     = (const int*)d_in[0];
    const int*   ea    = (const int*)d_in[1];
    const int*   ei    = (const int*)d_in[2];
    const float* atomT = (const float*)d_in[3];
    const float* bondT = (const float*)d_in[4];
    const float* gatW  = (const float*)d_in[5];
    const float* gatb  = (const float*)d_in[6];
    const float* attS  = (const float*)d_in[7];
    const float* attD  = (const float*)d_in[8];
    const float* attE  = (const float*)d_in[9];
    const float* epW   = (const float*)d_in[10];
    const float* epb   = (const float*)d_in[11];
    const float* lng   = (const float*)d_in[12];
    const float* lnb   = (const float*)d_in[13];
    const float* euW1  = (const float*)d_in[14];
    const float* eub1  = (const float*)d_in[15];
    const float* euW2  = (const float*)d_in[16];
    const float* eub2  = (const float*)d_in[17];

    int N = in_sizes[0] / 9;
    int E = in_sizes[1] / 3;
    const int* src  = ei;
    const int* dstp = ei + E;
    float* out = (float*)d_out;

    float *node, *xh, *P, *Q, *agg, *asrc, *adst, *m, *den, *edge, *h, *logits, *v;
    cudaGetSymbolAddress((void**)&node,   g_node);
    cudaGetSymbolAddress((void**)&xh,     g_xh);
    cudaGetSymbolAddress((void**)&P,      g_P);
    cudaGetSymbolAddress((void**)&Q,      g_Q);
    cudaGetSymbolAddress((void**)&agg,    g_agg);
    cudaGetSymbolAddress((void**)&asrc,   g_asrc);
    cudaGetSymbolAddress((void**)&adst,   g_adst);
    cudaGetSymbolAddress((void**)&m,      g_m);
    cudaGetSymbolAddress((void**)&den,    g_den);
    cudaGetSymbolAddress((void**)&edge,   g_edge);
    cudaGetSymbolAddress((void**)&h,      g_h);
    cudaGetSymbolAddress((void**)&logits, g_logits);
    cudaGetSymbolAddress((void**)&v,      g_v);

    k_node_enc<<<(N * 64 + 255) / 256, 256>>>(x, atomT, node, N);
    k_edge_enc<<<(E * 64 + 255) / 256, 256>>>(ea, bondT, edge, E);

    int gN128 = (N + 127) / 128;
    int gE128 = (E + 127) / 128;
    int gE256 = (E + 255) / 256;

    for (int l = 0; l < 4; ++l) {
        k_prep<<<1, 256>>>(epW + l * 4096, epb + l * 64, attE + l * 64, v);
        k_xh<<<gN128, 128>>>(node, gatW + l * 4096, attS + l * 64, attD + l * 64,
                             xh, asrc, adst, (float4*)m, (float4*)den, agg, N);
        k_logits<<<gE256, 256>>>(edge, src, dstp, (const float4*)asrc, (const float4*)adst,
                                 v, (float4*)logits, m, E);
        k_expsum<<<gE256, 256>>>(dstp, (float4*)logits, (const float4*)m, den, E);
        k_agg<<<gE256, 256>>>(src, dstp, (const float4*)logits, (const float4*)den, xh, agg, E);
        k_nodeup<<<(N + 7) / 8, 256>>>(agg, gatb + l * 64, lng + l * 64, lnb + l * 64, node, N);
        // edge update: P = node@W1a, Q = node@W1b (per-node), then per-edge MLP
        k_gemm64<<<gN128, 128>>>(node, euW1 + l * 12288,            nullptr, P, N, 0);
        k_gemm64<<<gN128, 128>>>(node, euW1 + l * 12288 + 4096,     nullptr, Q, N, 0);
        k_eu1<<<gE128, 128>>>(edge, P, Q, src, dstp,
                              euW1 + l * 12288 + 8192, eub1 + l * 64, h, E);
        float* eout = (l == 3) ? (out + (size_t)N * 64) : edge;
        k_gemm64<<<gE128, 128>>>(h, euW2 + l * 4096, eub2 + l * 64, eout, E, 1);
    }

    k_copy<<<(N * 16 + 255) / 256, 256>>>((const float4*)node, (float4*)out, N * 16);
}

// round 2
// speedup vs baseline: 1.1107x; 1.1107x over previous
#include <cuda_runtime.h>
#include <math.h>

#define D 64
#define NMAX 100000
#define EMAX 1200000

typedef unsigned long long ull;

// ---------------- scratch (device globals; no allocation allowed) ----------------
__device__ float g_node[NMAX * D];
__device__ float g_xh[NMAX * D];
__device__ float g_P[NMAX * D];
__device__ float g_Q[NMAX * D];
__device__ float g_agg[NMAX * D];
__device__ float g_asrc[NMAX * 4];
__device__ float g_adst[NMAX * 4];
__device__ float g_m[NMAX * 4];
__device__ float g_den[NMAX * 4];
__device__ float g_edge[EMAX * D];
__device__ float g_h[EMAX * D];
__device__ float g_logits[EMAX * 4];
__device__ float g_aE[EMAX * 4];
__device__ float g_v[4 * 260];

// ---------------- f32x2 helpers (FFMA2 only reachable via PTX) ----------------
__device__ __forceinline__ ull pk2(float x, float y) {
    ull r; asm("mov.b64 %0,{%1,%2};" : "=l"(r) : "f"(x), "f"(y)); return r;
}
__device__ __forceinline__ float2 upk(ull a) {
    float2 r; asm("mov.b64 {%0,%1},%2;" : "=f"(r.x), "=f"(r.y) : "l"(a)); return r;
}
__device__ __forceinline__ ull f2fma(ull a, ull b, ull c) {
    ull d; asm("fma.rn.f32x2 %0,%1,%2,%3;" : "=l"(d) : "l"(a), "l"(b), "l"(c)); return d;
}
__device__ __forceinline__ void redv4(float* p, float a, float b, float c, float d) {
    asm volatile("red.global.add.v4.f32 [%0], {%1,%2,%3,%4};"
                 :: "l"(p), "f"(a), "f"(b), "f"(c), "f"(d) : "memory");
}
__device__ __forceinline__ void atomicMaxF(float* a, float v) {
    if (v >= 0.f) atomicMax((int*)a, __float_as_int(v));
    else          atomicMin((unsigned int*)a, __float_as_uint(v));
}

// ============ register-blocked mainloop: 4 rows x 16 cols per thread =========
// sWu layout: ull sWu[k*32 + col/2]; thread owns cols [cg*16, cg*16+16)
__device__ __forceinline__ void rb_mainloop(const float* __restrict__ in,
        int r0, int M, const ull* __restrict__ sWu, int cg8, ull acc[4][8]) {
    const float4* in4 = (const float4*)in;
    int ri[4];
#pragma unroll
    for (int t = 0; t < 4; ++t) { int rr = r0 + t; ri[t] = (rr < M ? rr : M - 1) * 16; }
#pragma unroll 2
    for (int k4 = 0; k4 < 16; ++k4) {
        float4 a[4];
#pragma unroll
        for (int t = 0; t < 4; ++t) a[t] = in4[ri[t] + k4];
        const ull* wb = sWu + k4 * 128 + cg8;
#pragma unroll
        for (int kk = 0; kk < 4; ++kk) {
            ull wv[8];
            const ull* w = wb + kk * 32;
#pragma unroll
            for (int j = 0; j < 8; ++j) wv[j] = w[j];
#pragma unroll
            for (int t = 0; t < 4; ++t) {
                float av = (kk == 0) ? a[t].x : (kk == 1) ? a[t].y : (kk == 2) ? a[t].z : a[t].w;
                ull a2 = pk2(av, av);
#pragma unroll
                for (int j = 0; j < 8; ++j) acc[t][j] = f2fma(a2, wv[j], acc[t][j]);
            }
        }
    }
}

// ---------------- encoders ----------------
__global__ void k_node_enc(const int* __restrict__ x, const float* __restrict__ at,
                           float* __restrict__ node, int Nn) {
    int t = blockIdx.x * blockDim.x + threadIdx.x;
    if (t >= Nn * D) return;
    int i = t >> 6, j = t & 63;
    const int* xi = x + i * 9;
    float s = 0.f;
#pragma unroll
    for (int f = 0; f < 9; ++f) { int v = xi[f]; s += at[(f * 16 + v) * 64 + j]; }
    node[t] = s;
}

// warp-per-edge encoder: writes edge row AND a_edge (layer 0) via folded v
__global__ void __launch_bounds__(256) k_edge_enc2(const int* __restrict__ ea,
        const float* __restrict__ bt, const float* __restrict__ v0,
        float* __restrict__ edge, float4* __restrict__ aE4, int E) {
    int e = blockIdx.x * 8 + (threadIdx.x >> 5);
    int lane = threadIdx.x & 31;
    if (e >= E) return;
    int f0 = ea[e * 3], f1 = ea[e * 3 + 1], f2 = ea[e * 3 + 2];
    int c0 = 2 * lane, c1 = c0 + 1;
    float s0 = bt[f0 * 64 + c0] + bt[(8 + f1) * 64 + c0] + bt[(16 + f2) * 64 + c0];
    float s1 = bt[f0 * 64 + c1] + bt[(8 + f1) * 64 + c1] + bt[(16 + f2) * 64 + c1];
    ((float2*)(edge + e * 64))[lane] = make_float2(s0, s1);
    float p[4];
#pragma unroll
    for (int h = 0; h < 4; ++h) p[h] = s0 * v0[c0 * 4 + h] + s1 * v0[c1 * 4 + h];
#pragma unroll
    for (int o = 16; o; o >>= 1) {
#pragma unroll
        for (int h = 0; h < 4; ++h) p[h] += __shfl_xor_sync(0xffffffffu, p[h], o);
    }
    if (lane == 0)
        aE4[e] = make_float4(p[0] + v0[256], p[1] + v0[257], p[2] + v0[258], p[3] + v0[259]);
}

// ---------------- per-layer prep: fold edgeproj into [64,4] + bias[4] --------
__global__ void k_prep(const float* __restrict__ epW, const float* __restrict__ epb,
                       const float* __restrict__ attE, float* __restrict__ vall) {
    int l = blockIdx.x;
    const float* W = epW + l * 4096;
    const float* b = epb + l * 64;
    const float* aEv = attE + l * 64;
    float* vout = vall + l * 260;
    int t = threadIdx.x;
    if (t < 256) {
        int k = t >> 2, h = t & 3;
        float s = 0.f;
#pragma unroll
        for (int c = 0; c < 16; ++c) s += W[k * 64 + h * 16 + c] * aEv[h * 16 + c];
        vout[k * 4 + h] = s;
    }
    if (t < 4) {
        float s = 0.f;
#pragma unroll
        for (int c = 0; c < 16; ++c) s += b[t * 16 + c] * aEv[t * 16 + c];
        vout[256 + t] = s;
    }
}

// ---------------- xh = node @ W, a_src/a_dst, init m/den/agg -----------------
__global__ void __launch_bounds__(256) k_xh_rb(const float* __restrict__ node,
        const float* __restrict__ W, const float* __restrict__ attS,
        const float* __restrict__ attD, float* __restrict__ xh,
        float* __restrict__ asrc, float* __restrict__ adst,
        float* __restrict__ m, float* __restrict__ den, float* __restrict__ agg, int M) {
    __shared__ __align__(16) float sW[4096];
    __shared__ float sAS[64], sAD[64];
    for (int i = threadIdx.x; i < 4096; i += 256) sW[i] = W[i];
    if (threadIdx.x < 64) { sAS[threadIdx.x] = attS[threadIdx.x]; sAD[threadIdx.x] = attD[threadIdx.x]; }
    __syncthreads();
    int cg = threadIdx.x & 3, tq = threadIdx.x >> 2;
    int r0 = blockIdx.x * 256 + tq * 4;
    if (r0 >= M) return;
    ull acc[4][8];
#pragma unroll
    for (int t = 0; t < 4; ++t)
#pragma unroll
        for (int j = 0; j < 8; ++j) acc[t][j] = 0ull;
    rb_mainloop(node, r0, M, (const ull*)sW, cg * 8, acc);
    float ninf = __int_as_float(0xff800000);
#pragma unroll
    for (int t = 0; t < 4; ++t) {
        int r = r0 + t;
        if (r >= M) break;
        float as = 0.f, ad = 0.f;
        float4 o[4];
#pragma unroll
        for (int q = 0; q < 4; ++q) {
            float2 v0 = upk(acc[t][2 * q]), v1 = upk(acc[t][2 * q + 1]);
            o[q] = make_float4(v0.x, v0.y, v1.x, v1.y);
            int c = cg * 16 + 4 * q;
            as += v0.x * sAS[c] + v0.y * sAS[c + 1] + v1.x * sAS[c + 2] + v1.y * sAS[c + 3];
            ad += v0.x * sAD[c] + v0.y * sAD[c + 1] + v1.x * sAD[c + 2] + v1.y * sAD[c + 3];
        }
        float4* xp = (float4*)(xh + (size_t)r * 64 + cg * 16);
        float4* ap = (float4*)(agg + (size_t)r * 64 + cg * 16);
        float4 z = make_float4(0.f, 0.f, 0.f, 0.f);
#pragma unroll
        for (int q = 0; q < 4; ++q) { xp[q] = o[q]; ap[q] = z; }
        asrc[r * 4 + cg] = as;
        adst[r * 4 + cg] = ad;
        m[r * 4 + cg] = ninf;
        den[r * 4 + cg] = 0.f;
    }
}

// ---------------- generic row GEMM: out = act(in @ W + bias) [+ aE] ----------
template <int RELU, int AEDGE>
__global__ void __launch_bounds__(256) k_gemm_rb(const float* __restrict__ in,
        const float* __restrict__ W, const float* __restrict__ bias,
        float* __restrict__ out, const float* __restrict__ vE,
        float* __restrict__ aE, int M) {
    __shared__ __align__(16) float sW[4096];
    __shared__ float sB[64];
    __shared__ float sV[260];
    for (int i = threadIdx.x; i < 4096; i += 256) sW[i] = W[i];
    if (threadIdx.x < 64) sB[threadIdx.x] = bias ? bias[threadIdx.x] : 0.f;
    if (AEDGE) { for (int i = threadIdx.x; i < 260; i += 256) sV[i] = vE[i]; }
    __syncthreads();
    int cg = threadIdx.x & 3, tq = threadIdx.x >> 2;
    int r0 = blockIdx.x * 256 + tq * 4;
    if (r0 >= M) return;
    ull acc[4][8];
#pragma unroll
    for (int j = 0; j < 8; ++j) {
        ull bi = pk2(sB[cg * 16 + 2 * j], sB[cg * 16 + 2 * j + 1]);
#pragma unroll
        for (int t = 0; t < 4; ++t) acc[t][j] = bi;
    }
    rb_mainloop(in, r0, M, (const ull*)sW, cg * 8, acc);
#pragma unroll
    for (int t = 0; t < 4; ++t) {
        int r = r0 + t;
        float4 o[4];
#pragma unroll
        for (int q = 0; q < 4; ++q) {
            float2 v0 = upk(acc[t][2 * q]), v1 = upk(acc[t][2 * q + 1]);
            if (RELU) {
                v0.x = fmaxf(v0.x, 0.f); v0.y = fmaxf(v0.y, 0.f);
                v1.x = fmaxf(v1.x, 0.f); v1.y = fmaxf(v1.y, 0.f);
            }
            o[q] = make_float4(v0.x, v0.y, v1.x, v1.y);
        }
        if (r < M) {
            float4* op = (float4*)(out + (size_t)r * 64 + cg * 16);
#pragma unroll
            for (int q = 0; q < 4; ++q) op[q] = o[q];
        }
        if (AEDGE) {
            float p[4] = {0.f, 0.f, 0.f, 0.f};
#pragma unroll
            for (int q = 0; q < 4; ++q) {
                const float* vv = sV + (cg * 16 + 4 * q) * 4;
#pragma unroll
                for (int h = 0; h < 4; ++h)
                    p[h] += o[q].x * vv[h] + o[q].y * vv[4 + h] + o[q].z * vv[8 + h] + o[q].w * vv[12 + h];
            }
#pragma unroll
            for (int h = 0; h < 4; ++h) {
                p[h] += __shfl_xor_sync(0xffffffffu, p[h], 1);
                p[h] += __shfl_xor_sync(0xffffffffu, p[h], 2);
            }
            if (r < M) aE[r * 4 + cg] = p[cg] + sV[256 + cg];
        }
    }
}

// ------- edge-update stage 1: h = relu(P[src] + Q[dst] + edge @ W1c + b1) ----
__global__ void __launch_bounds__(256) k_eu1_rb(const float* __restrict__ edge,
        const float* __restrict__ P, const float* __restrict__ Q,
        const int* __restrict__ src, const int* __restrict__ dst,
        const float* __restrict__ W1c, const float* __restrict__ b1,
        float* __restrict__ h, int E) {
    __shared__ __align__(16) float sW[4096];
    __shared__ float sB[64];
    for (int i = threadIdx.x; i < 4096; i += 256) sW[i] = W1c[i];
    if (threadIdx.x < 64) sB[threadIdx.x] = b1[threadIdx.x];
    __syncthreads();
    int cg = threadIdx.x & 3, tq = threadIdx.x >> 2;
    int r0 = blockIdx.x * 256 + tq * 4;
    if (r0 >= E) return;
    int ss[4], dd[4];
    if (r0 + 3 < E) {
        int4 sv = *(const int4*)(src + r0);
        int4 dv = *(const int4*)(dst + r0);
        ss[0] = sv.x; ss[1] = sv.y; ss[2] = sv.z; ss[3] = sv.w;
        dd[0] = dv.x; dd[1] = dv.y; dd[2] = dv.z; dd[3] = dv.w;
    } else {
#pragma unroll
        for (int t = 0; t < 4; ++t) {
            int r = r0 + t; if (r >= E) r = E - 1;
            ss[t] = src[r]; dd[t] = dst[r];
        }
    }
    ull acc[4][8];
#pragma unroll
    for (int t = 0; t < 4; ++t) {
        const float4* Pp = (const float4*)P + (size_t)ss[t] * 16 + cg * 4;
        const float4* Qp = (const float4*)Q + (size_t)dd[t] * 16 + cg * 4;
#pragma unroll
        for (int q = 0; q < 4; ++q) {
            float4 pv = Pp[q], qv = Qp[q];
            const float* b = sB + cg * 16 + 4 * q;
            acc[t][2 * q]     = pk2(pv.x + qv.x + b[0], pv.y + qv.y + b[1]);
            acc[t][2 * q + 1] = pk2(pv.z + qv.z + b[2], pv.w + qv.w + b[3]);
        }
    }
    rb_mainloop(edge, r0, E, (const ull*)sW, cg * 8, acc);
#pragma unroll
    for (int t = 0; t < 4; ++t) {
        int r = r0 + t;
        if (r >= E) break;
        float4* op = (float4*)(h + (size_t)r * 64 + cg * 16);
#pragma unroll
        for (int q = 0; q < 4; ++q) {
            float2 v0 = upk(acc[t][2 * q]), v1 = upk(acc[t][2 * q + 1]);
            op[q] = make_float4(fmaxf(v0.x, 0.f), fmaxf(v0.y, 0.f),
                                fmaxf(v1.x, 0.f), fmaxf(v1.y, 0.f));
        }
    }
}

// ---------------- attention pass 1: logits + segment max (light) -------------
__global__ void __launch_bounds__(256) k_logits2(const int* __restrict__ src,
        const int* __restrict__ dst, const float4* __restrict__ asrc4,
        const float4* __restrict__ adst4, const float4* __restrict__ aE4,
        float4* __restrict__ logits4, float* __restrict__ m, int E) {
    int e = blockIdx.x * 256 + threadIdx.x;
    if (e >= E) return;
    int s = src[e], d = dst[e];
    float4 ae = aE4[e];
    float4 as = asrc4[s], ad = adst4[d];
    float t0 = as.x + ad.x + ae.x, t1 = as.y + ad.y + ae.y;
    float t2 = as.z + ad.z + ae.z, t3 = as.w + ad.w + ae.w;
    t0 = t0 > 0.f ? t0 : 0.2f * t0;
    t1 = t1 > 0.f ? t1 : 0.2f * t1;
    t2 = t2 > 0.f ? t2 : 0.2f * t2;
    t3 = t3 > 0.f ? t3 : 0.2f * t3;
    logits4[e] = make_float4(t0, t1, t2, t3);
    float* md = m + d * 4;
    atomicMaxF(md + 0, t0); atomicMaxF(md + 1, t1);
    atomicMaxF(md + 2, t2); atomicMaxF(md + 3, t3);
}

// ---------------- attention pass 2: exp + segment sum ------------------------
__global__ void __launch_bounds__(256) k_expsum(const int* __restrict__ dst,
        float4* __restrict__ logits4, const float4* __restrict__ m4,
        float* __restrict__ den, int E) {
    int e = blockIdx.x * 256 + threadIdx.x;
    if (e >= E) return;
    int d = dst[e];
    float4 lg = logits4[e];
    float4 mm = m4[d];
    float e0 = expf(lg.x - mm.x), e1 = expf(lg.y - mm.y);
    float e2 = expf(lg.z - mm.z), e3 = expf(lg.w - mm.w);
    logits4[e] = make_float4(e0, e1, e2, e3);
    redv4(den + d * 4, e0, e1, e2, e3);
}

// ---------------- attention pass 3: weighted scatter --------------------------
__global__ void __launch_bounds__(256) k_agg(const int* __restrict__ src, const int* __restrict__ dst,
        const float4* __restrict__ logits4, const float4* __restrict__ den4,
        const float* __restrict__ xh, float* __restrict__ agg, int E) {
    int e = blockIdx.x * 256 + threadIdx.x;
    if (e >= E) return;
    int s = src[e], d = dst[e];
    float4 ex = logits4[e];
    float4 dn = den4[d];
    float al[4];
    al[0] = ex.x / (dn.x + 1e-16f); al[1] = ex.y / (dn.y + 1e-16f);
    al[2] = ex.z / (dn.z + 1e-16f); al[3] = ex.w / (dn.w + 1e-16f);
    const float4* xs = (const float4*)xh + (size_t)s * 16;
    float* ag = agg + (size_t)d * 64;
#pragma unroll
    for (int h = 0; h < 4; ++h) {
        float a = al[h];
#pragma unroll
        for (int q = 0; q < 4; ++q) {
            float4 v = xs[h * 4 + q];
            redv4(ag + h * 16 + q * 4, a * v.x, a * v.y, a * v.z, a * v.w);
        }
    }
}

// ---------------- node update: conv = agg + b -> LN -> relu -> residual ------
__global__ void __launch_bounds__(256) k_nodeup(const float* __restrict__ agg,
        const float* __restrict__ gatb, const float* __restrict__ lng,
        const float* __restrict__ lnb, float* __restrict__ node, int Nn) {
    int warp = blockIdx.x * 8 + (threadIdx.x >> 5);
    int lane = threadIdx.x & 31;
    if (warp >= Nn) return;
    float2 cv = ((const float2*)agg)[warp * 32 + lane];
    float2 gb = __ldg((const float2*)gatb + lane);
    cv.x += gb.x; cv.y += gb.y;
    float s = cv.x + cv.y, ss = cv.x * cv.x + cv.y * cv.y;
#pragma unroll
    for (int o = 16; o; o >>= 1) {
        s  += __shfl_xor_sync(0xffffffffu, s, o);
        ss += __shfl_xor_sync(0xffffffffu, ss, o);
    }
    float mu = s * (1.f / 64.f);
    float var = ss * (1.f / 64.f) - mu * mu;
    float r = rsqrtf(var + 1e-5f);
    float2 g = __ldg((const float2*)lng + lane), b = __ldg((const float2*)lnb + lane);
    float y0 = fmaxf((cv.x - mu) * r * g.x + b.x, 0.f);
    float y1 = fmaxf((cv.y - mu) * r * g.y + b.y, 0.f);
    float2* np = (float2*)node + warp * 32 + lane;
    float2 old = *np;
    *np = make_float2(old.x + y0, old.y + y1);
}

__global__ void k_copy(const float4* __restrict__ s, float4* __restrict__ d, int n4) {
    int i = blockIdx.x * blockDim.x + threadIdx.x;
    if (i < n4) d[i] = s[i];
}

// ---------------- launch ----------------
extern "C" void kernel_launch(void* const* d_in, const int* in_sizes, int n_in,
                              void* d_out, int out_size) {
    const int*   x     = (const int*)d_in[0];
    const int*   ea    = (const int*)d_in[1];
    const int*   ei    = (const int*)d_in[2];
    const float* atomT = (const float*)d_in[3];
    const float* bondT = (const float*)d_in[4];
    const float* gatW  = (const float*)d_in[5];
    const float* gatb  = (const float*)d_in[6];
    const float* attS  = (const float*)d_in[7];
    const float* attD  = (const float*)d_in[8];
    const float* attE  = (const float*)d_in[9];
    const float* epW   = (const float*)d_in[10];
    const float* epb   = (const float*)d_in[11];
    const float* lng   = (const float*)d_in[12];
    const float* lnb   = (const float*)d_in[13];
    const float* euW1  = (const float*)d_in[14];
    const float* eub1  = (const float*)d_in[15];
    const float* euW2  = (const float*)d_in[16];
    const float* eub2  = (const float*)d_in[17];

    int N = in_sizes[0] / 9;
    int E = in_sizes[1] / 3;
    const int* src  = ei;
    const int* dstp = ei + E;
    float* out = (float*)d_out;

    float *node, *xh, *P, *Q, *agg, *asrc, *adst, *m, *den, *edge, *h, *logits, *v, *aE;
    cudaGetSymbolAddress((void**)&node,   g_node);
    cudaGetSymbolAddress((void**)&xh,     g_xh);
    cudaGetSymbolAddress((void**)&P,      g_P);
    cudaGetSymbolAddress((void**)&Q,      g_Q);
    cudaGetSymbolAddress((void**)&agg,    g_agg);
    cudaGetSymbolAddress((void**)&asrc,   g_asrc);
    cudaGetSymbolAddress((void**)&adst,   g_adst);
    cudaGetSymbolAddress((void**)&m,      g_m);
    cudaGetSymbolAddress((void**)&den,    g_den);
    cudaGetSymbolAddress((void**)&edge,   g_edge);
    cudaGetSymbolAddress((void**)&h,      g_h);
    cudaGetSymbolAddress((void**)&logits, g_logits);
    cudaGetSymbolAddress((void**)&v,      g_v);
    cudaGetSymbolAddress((void**)&aE,     g_aE);

    // fold edgeproj for all layers upfront
    k_prep<<<4, 256>>>(epW, epb, attE, v);
    k_node_enc<<<(N * 64 + 255) / 256, 256>>>(x, atomT, node, N);
    k_edge_enc2<<<(E + 7) / 8, 256>>>(ea, bondT, v, edge, (float4*)aE, E);

    int gN = (N + 255) / 256;
    int gE = (E + 255) / 256;

    for (int l = 0; l < 4; ++l) {
        k_xh_rb<<<gN, 256>>>(node, gatW + l * 4096, attS + l * 64, attD + l * 64,
                             xh, asrc, adst, m, den, agg, N);
        k_logits2<<<gE, 256>>>(src, dstp, (const float4*)asrc, (const float4*)adst,
                               (const float4*)aE, (float4*)logits, m, E);
        k_expsum<<<gE, 256>>>(dstp, (float4*)logits, (const float4*)m, den, E);
        k_agg<<<gE, 256>>>(src, dstp, (const float4*)logits, (const float4*)den, xh, agg, E);
        k_nodeup<<<(N + 7) / 8, 256>>>(agg, gatb + l * 64, lng + l * 64, lnb + l * 64, node, N);
        // edge update: P = node@W1a, Q = node@W1b (per-node), then per-edge MLP
        k_gemm_rb<0, 0><<<gN, 256>>>(node, euW1 + l * 12288,        nullptr, P, nullptr, nullptr, N);
        k_gemm_rb<0, 0><<<gN, 256>>>(node, euW1 + l * 12288 + 4096, nullptr, Q, nullptr, nullptr, N);
        k_eu1_rb<<<gE, 256>>>(edge, P, Q, src, dstp,
                              euW1 + l * 12288 + 8192, eub1 + l * 64, h, E);
        if (l < 3) {
            // produce next edge AND its a_edge (folded with layer l+1 params)
            k_gemm_rb<1, 1><<<gE, 256>>>(h, euW2 + l * 4096, eub2 + l * 64, edge,
                                         v + (l + 1) * 260, aE, E);
        } else {
            k_gemm_rb<1, 0><<<gE, 256>>>(h, euW2 + l * 4096, eub2 + l * 64,
                                         out + (size_t)N * 64, nullptr, nullptr, E);
        }
    }

    k_copy<<<(N * 16 + 255) / 256, 256>>>((const float4*)node, (float4*)out, N * 16);
}

// round 3
// speedup vs baseline: 1.1829x; 1.0650x over previous
#include <cuda_runtime.h>
#include <math.h>

#define D 64
#define NMAX 100000
#define EMAX 1200000

typedef unsigned long long ull;

// ---------------- scratch (device globals; no allocation allowed) ----------------
__device__ float g_node[NMAX * D];
__device__ float g_xh[NMAX * D];
__device__ float g_P[NMAX * D];
__device__ float g_Q[NMAX * D];
__device__ float g_agg[NMAX * D];
__device__ float g_asrc[NMAX * 4];
__device__ float g_adst[NMAX * 4];
__device__ float g_m[NMAX * 4];
__device__ float g_den[NMAX * 4];
__device__ float g_edge[EMAX * D];
__device__ float g_h[EMAX * D];
__device__ float g_logits[EMAX * 4];
__device__ float g_aE[EMAX * 4];
__device__ float g_v[4 * 260];

// ---------------- f32x2 helpers ----------------
__device__ __forceinline__ ull pk2(float x, float y) {
    ull r; asm("mov.b64 %0,{%1,%2};" : "=l"(r) : "f"(x), "f"(y)); return r;
}
__device__ __forceinline__ float2 upk(ull a) {
    float2 r; asm("mov.b64 {%0,%1},%2;" : "=f"(r.x), "=f"(r.y) : "l"(a)); return r;
}
__device__ __forceinline__ ull f2fma(ull a, ull b, ull c) {
    ull d; asm("fma.rn.f32x2 %0,%1,%2,%3;" : "=l"(d) : "l"(a), "l"(b), "l"(c)); return d;
}
__device__ __forceinline__ void redv4(float* p, float a, float b, float c, float d) {
    asm volatile("red.global.add.v4.f32 [%0], {%1,%2,%3,%4};"
                 :: "l"(p), "f"(a), "f"(b), "f"(c), "f"(d) : "memory");
}
__device__ __forceinline__ void atomicMaxF(float* a, float v) {
    if (v >= 0.f) atomicMax((int*)a, __float_as_int(v));
    else          atomicMin((unsigned int*)a, __float_as_uint(v));
}

// ============ register-blocked mainloop: 4 rows x 8 cols per thread ==========
// sWu layout: ull sWu[k*32 + col/2]; thread (cg in 0..7) owns cols [cg*8, cg*8+8)
__device__ __forceinline__ void rb8_mainloop(const float* __restrict__ in,
        int r0, int M, const ull* __restrict__ sWu, int cg4, ull acc[4][4]) {
    const float4* in4 = (const float4*)in;
    int ri[4];
#pragma unroll
    for (int t = 0; t < 4; ++t) { int rr = r0 + t; ri[t] = (rr < M ? rr : M - 1) * 16; }
#pragma unroll 4
    for (int k4 = 0; k4 < 16; ++k4) {
        float4 a[4];
#pragma unroll
        for (int t = 0; t < 4; ++t) a[t] = in4[ri[t] + k4];
        const ull* wb = sWu + k4 * 128 + cg4;
#pragma unroll
        for (int kk = 0; kk < 4; ++kk) {
            ull wv[4];
            const ull* w = wb + kk * 32;
#pragma unroll
            for (int j = 0; j < 4; ++j) wv[j] = w[j];
#pragma unroll
            for (int t = 0; t < 4; ++t) {
                float av = (kk == 0) ? a[t].x : (kk == 1) ? a[t].y : (kk == 2) ? a[t].z : a[t].w;
                ull a2 = pk2(av, av);
#pragma unroll
                for (int j = 0; j < 4; ++j) acc[t][j] = f2fma(a2, wv[j], acc[t][j]);
            }
        }
    }
}

// ---------------- encoders ----------------
__global__ void k_node_enc(const int* __restrict__ x, const float* __restrict__ at,
                           float* __restrict__ node, int Nn) {
    int t = blockIdx.x * blockDim.x + threadIdx.x;
    if (t >= Nn * D) return;
    int i = t >> 6, j = t & 63;
    const int* xi = x + i * 9;
    float s = 0.f;
#pragma unroll
    for (int f = 0; f < 9; ++f) { int v = xi[f]; s += at[(f * 16 + v) * 64 + j]; }
    node[t] = s;
}

// warp-per-edge encoder: writes edge row AND a_edge (layer 0) via folded v
__global__ void __launch_bounds__(256) k_edge_enc2(const int* __restrict__ ea,
        const float* __restrict__ bt, const float* __restrict__ v0,
        float* __restrict__ edge, float4* __restrict__ aE4, int E) {
    int e = blockIdx.x * 8 + (threadIdx.x >> 5);
    int lane = threadIdx.x & 31;
    if (e >= E) return;
    int f0 = ea[e * 3], f1 = ea[e * 3 + 1], f2 = ea[e * 3 + 2];
    int c0 = 2 * lane, c1 = c0 + 1;
    float s0 = bt[f0 * 64 + c0] + bt[(8 + f1) * 64 + c0] + bt[(16 + f2) * 64 + c0];
    float s1 = bt[f0 * 64 + c1] + bt[(8 + f1) * 64 + c1] + bt[(16 + f2) * 64 + c1];
    ((float2*)(edge + e * 64))[lane] = make_float2(s0, s1);
    float p[4];
#pragma unroll
    for (int h = 0; h < 4; ++h) p[h] = s0 * v0[c0 * 4 + h] + s1 * v0[c1 * 4 + h];
#pragma unroll
    for (int o = 16; o; o >>= 1) {
#pragma unroll
        for (int h = 0; h < 4; ++h) p[h] += __shfl_xor_sync(0xffffffffu, p[h], o);
    }
    if (lane == 0)
        aE4[e] = make_float4(p[0] + v0[256], p[1] + v0[257], p[2] + v0[258], p[3] + v0[259]);
}

// ---------------- per-layer prep: fold edgeproj into [64,4] + bias[4] --------
__global__ void k_prep(const float* __restrict__ epW, const float* __restrict__ epb,
                       const float* __restrict__ attE, float* __restrict__ vall) {
    int l = blockIdx.x;
    const float* W = epW + l * 4096;
    const float* b = epb + l * 64;
    const float* aEv = attE + l * 64;
    float* vout = vall + l * 260;
    int t = threadIdx.x;
    if (t < 256) {
        int k = t >> 2, h = t & 3;
        float s = 0.f;
#pragma unroll
        for (int c = 0; c < 16; ++c) s += W[k * 64 + h * 16 + c] * aEv[h * 16 + c];
        vout[k * 4 + h] = s;
    }
    if (t < 4) {
        float s = 0.f;
#pragma unroll
        for (int c = 0; c < 16; ++c) s += b[t * 16 + c] * aEv[t * 16 + c];
        vout[256 + t] = s;
    }
}

// ---------------- xh = node @ W, a_src/a_dst, init m/den/agg -----------------
__global__ void __launch_bounds__(256, 2) k_xh_rb(const float* __restrict__ node,
        const float* __restrict__ W, const float* __restrict__ attS,
        const float* __restrict__ attD, float* __restrict__ xh,
        float* __restrict__ asrc, float* __restrict__ adst,
        float* __restrict__ m, float* __restrict__ den, float* __restrict__ agg, int M) {
    __shared__ __align__(16) float sW[4096];
    __shared__ float sAS[64], sAD[64];
    for (int i = threadIdx.x; i < 4096; i += 256) sW[i] = W[i];
    if (threadIdx.x < 64) { sAS[threadIdx.x] = attS[threadIdx.x]; sAD[threadIdx.x] = attD[threadIdx.x]; }
    __syncthreads();
    int cg = threadIdx.x & 7, tq = threadIdx.x >> 3;
    int r0 = blockIdx.x * 128 + tq * 4;
    if (r0 >= M) return;
    ull acc[4][4];
#pragma unroll
    for (int t = 0; t < 4; ++t)
#pragma unroll
        for (int j = 0; j < 4; ++j) acc[t][j] = 0ull;
    rb8_mainloop(node, r0, M, (const ull*)sW, cg * 4, acc);
    float ninf = __int_as_float(0xff800000);
    int c0 = cg * 8;
#pragma unroll
    for (int t = 0; t < 4; ++t) {
        int r = r0 + t;
        float as = 0.f, ad = 0.f;
        float4 o[2];
#pragma unroll
        for (int q = 0; q < 2; ++q) {
            float2 v0 = upk(acc[t][2 * q]), v1 = upk(acc[t][2 * q + 1]);
            o[q] = make_float4(v0.x, v0.y, v1.x, v1.y);
            int c = c0 + 4 * q;
            as += v0.x * sAS[c] + v0.y * sAS[c + 1] + v1.x * sAS[c + 2] + v1.y * sAS[c + 3];
            ad += v0.x * sAD[c] + v0.y * sAD[c + 1] + v1.x * sAD[c + 2] + v1.y * sAD[c + 3];
        }
        // head h = cg>>1 spans cg pairs: reduce with partner lane
        as += __shfl_xor_sync(0xffffffffu, as, 1);
        ad += __shfl_xor_sync(0xffffffffu, ad, 1);
        if (r < M) {
            float4* xp = (float4*)(xh + (size_t)r * 64 + c0);
            float4* ap = (float4*)(agg + (size_t)r * 64 + c0);
            float4 z = make_float4(0.f, 0.f, 0.f, 0.f);
            xp[0] = o[0]; xp[1] = o[1];
            ap[0] = z;    ap[1] = z;
            if ((cg & 1) == 0) {
                int h = cg >> 1;
                asrc[r * 4 + h] = as;
                adst[r * 4 + h] = ad;
            }
            if (cg < 4) { m[r * 4 + cg] = ninf; den[r * 4 + cg] = 0.f; }
        }
    }
}

// ---------------- generic row GEMM: out = act(in @ W + bias) [+ aE] ----------
template <int RELU, int AEDGE>
__global__ void __launch_bounds__(256, 2) k_gemm_rb(const float* __restrict__ in,
        const float* __restrict__ W, const float* __restrict__ bias,
        float* __restrict__ out, const float* __restrict__ vE,
        float* __restrict__ aE, int M) {
    __shared__ __align__(16) float sW[4096];
    __shared__ float sB[64];
    __shared__ float sV[260];
    for (int i = threadIdx.x; i < 4096; i += 256) sW[i] = W[i];
    if (threadIdx.x < 64) sB[threadIdx.x] = bias ? bias[threadIdx.x] : 0.f;
    if (AEDGE) { for (int i = threadIdx.x; i < 260; i += 256) sV[i] = vE[i]; }
    __syncthreads();
    int cg = threadIdx.x & 7, tq = threadIdx.x >> 3;
    int r0 = blockIdx.x * 128 + tq * 4;
    if (r0 >= M) return;
    int c0 = cg * 8;
    ull acc[4][4];
#pragma unroll
    for (int j = 0; j < 4; ++j) {
        ull bi = pk2(sB[c0 + 2 * j], sB[c0 + 2 * j + 1]);
#pragma unroll
        for (int t = 0; t < 4; ++t) acc[t][j] = bi;
    }
    rb8_mainloop(in, r0, M, (const ull*)sW, cg * 4, acc);
#pragma unroll
    for (int t = 0; t < 4; ++t) {
        int r = r0 + t;
        float4 o[2];
#pragma unroll
        for (int q = 0; q < 2; ++q) {
            float2 v0 = upk(acc[t][2 * q]), v1 = upk(acc[t][2 * q + 1]);
            if (RELU) {
                v0.x = fmaxf(v0.x, 0.f); v0.y = fmaxf(v0.y, 0.f);
                v1.x = fmaxf(v1.x, 0.f); v1.y = fmaxf(v1.y, 0.f);
            }
            o[q] = make_float4(v0.x, v0.y, v1.x, v1.y);
        }
        if (r < M) {
            float4* op = (float4*)(out + (size_t)r * 64 + c0);
            op[0] = o[0]; op[1] = o[1];
        }
        if (AEDGE) {
            float p[4] = {0.f, 0.f, 0.f, 0.f};
#pragma unroll
            for (int q = 0; q < 2; ++q) {
                const float* vv = sV + (c0 + 4 * q) * 4;
#pragma unroll
                for (int h = 0; h < 4; ++h)
                    p[h] += o[q].x * vv[h] + o[q].y * vv[4 + h] + o[q].z * vv[8 + h] + o[q].w * vv[12 + h];
            }
#pragma unroll
            for (int h = 0; h < 4; ++h) {
                p[h] += __shfl_xor_sync(0xffffffffu, p[h], 1);
                p[h] += __shfl_xor_sync(0xffffffffu, p[h], 2);
                p[h] += __shfl_xor_sync(0xffffffffu, p[h], 4);
            }
            if (r < M && cg < 4) aE[r * 4 + cg] = p[cg] + sV[256 + cg];
        }
    }
}

// ------- edge-update stage 1: h = relu(P[src] + Q[dst] + edge @ W1c + b1) ----
__global__ void __launch_bounds__(256, 2) k_eu1_rb(const float* __restrict__ edge,
        const float* __restrict__ P, const float* __restrict__ Q,
        const int* __restrict__ src, const int* __restrict__ dst,
        const float* __restrict__ W1c, const float* __restrict__ b1,
        float* __restrict__ h, int E) {
    __shared__ __align__(16) float sW[4096];
    __shared__ float sB[64];
    for (int i = threadIdx.x; i < 4096; i += 256) sW[i] = W1c[i];
    if (threadIdx.x < 64) sB[threadIdx.x] = b1[threadIdx.x];
    __syncthreads();
    int cg = threadIdx.x & 7, tq = threadIdx.x >> 3;
    int r0 = blockIdx.x * 128 + tq * 4;
    if (r0 >= E) return;
    int c0 = cg * 8;
    int ss[4], dd[4];
    if (r0 + 3 < E) {
        int4 sv = *(const int4*)(src + r0);
        int4 dv = *(const int4*)(dst + r0);
        ss[0] = sv.x; ss[1] = sv.y; ss[2] = sv.z; ss[3] = sv.w;
        dd[0] = dv.x; dd[1] = dv.y; dd[2] = dv.z; dd[3] = dv.w;
    } else {
#pragma unroll
        for (int t = 0; t < 4; ++t) {
            int r = r0 + t; if (r >= E) r = E - 1;
            ss[t] = src[r]; dd[t] = dst[r];
        }
    }
    ull acc[4][4];
#pragma unroll
    for (int t = 0; t < 4; ++t) {
        const float4* Pp = (const float4*)(P + (size_t)ss[t] * 64 + c0);
        const float4* Qp = (const float4*)(Q + (size_t)dd[t] * 64 + c0);
#pragma unroll
        for (int q = 0; q < 2; ++q) {
            float4 pv = Pp[q], qv = Qp[q];
            const float* b = sB + c0 + 4 * q;
            acc[t][2 * q]     = pk2(pv.x + qv.x + b[0], pv.y + qv.y + b[1]);
            acc[t][2 * q + 1] = pk2(pv.z + qv.z + b[2], pv.w + qv.w + b[3]);
        }
    }
    rb8_mainloop(edge, r0, E, (const ull*)sW, cg * 4, acc);
#pragma unroll
    for (int t = 0; t < 4; ++t) {
        int r = r0 + t;
        if (r >= E) break;
        float4* op = (float4*)(h + (size_t)r * 64 + c0);
#pragma unroll
        for (int q = 0; q < 2; ++q) {
            float2 v0 = upk(acc[t][2 * q]), v1 = upk(acc[t][2 * q + 1]);
            op[q] = make_float4(fmaxf(v0.x, 0.f), fmaxf(v0.y, 0.f),
                                fmaxf(v1.x, 0.f), fmaxf(v1.y, 0.f));
        }
    }
}

// ---------------- attention pass 1: logits + segment max (light) -------------
__global__ void __launch_bounds__(256) k_logits2(const int* __restrict__ src,
        const int* __restrict__ dst, const float4* __restrict__ asrc4,
        const float4* __restrict__ adst4, const float4* __restrict__ aE4,
        float4* __restrict__ logits4, float* __restrict__ m, int E) {
    int e = blockIdx.x * 256 + threadIdx.x;
    if (e >= E) return;
    int s = src[e], d = dst[e];
    float4 ae = aE4[e];
    float4 as = asrc4[s], ad = adst4[d];
    float t0 = as.x + ad.x + ae.x, t1 = as.y + ad.y + ae.y;
    float t2 = as.z + ad.z + ae.z, t3 = as.w + ad.w + ae.w;
    t0 = t0 > 0.f ? t0 : 0.2f * t0;
    t1 = t1 > 0.f ? t1 : 0.2f * t1;
    t2 = t2 > 0.f ? t2 : 0.2f * t2;
    t3 = t3 > 0.f ? t3 : 0.2f * t3;
    logits4[e] = make_float4(t0, t1, t2, t3);
    float* md = m + d * 4;
    atomicMaxF(md + 0, t0); atomicMaxF(md + 1, t1);
    atomicMaxF(md + 2, t2); atomicMaxF(md + 3, t3);
}

// ---------------- attention pass 2: exp + segment sum ------------------------
__global__ void __launch_bounds__(256) k_expsum(const int* __restrict__ dst,
        float4* __restrict__ logits4, const float4* __restrict__ m4,
        float* __restrict__ den, int E) {
    int e = blockIdx.x * 256 + threadIdx.x;
    if (e >= E) return;
    int d = dst[e];
    float4 lg = logits4[e];
    float4 mm = m4[d];
    float e0 = expf(lg.x - mm.x), e1 = expf(lg.y - mm.y);
    float e2 = expf(lg.z - mm.z), e3 = expf(lg.w - mm.w);
    logits4[e] = make_float4(e0, e1, e2, e3);
    redv4(den + d * 4, e0, e1, e2, e3);
}

// ---------------- attention pass 3: weighted scatter --------------------------
__global__ void __launch_bounds__(256) k_agg(const int* __restrict__ src, const int* __restrict__ dst,
        const float4* __restrict__ logits4, const float4* __restrict__ den4,
        const float* __restrict__ xh, float* __restrict__ agg, int E) {
    int e = blockIdx.x * 256 + threadIdx.x;
    if (e >= E) return;
    int s = src[e], d = dst[e];
    float4 ex = logits4[e];
    float4 dn = den4[d];
    float al[4];
    al[0] = ex.x / (dn.x + 1e-16f); al[1] = ex.y / (dn.y + 1e-16f);
    al[2] = ex.z / (dn.z + 1e-16f); al[3] = ex.w / (dn.w + 1e-16f);
    const float4* xs = (const float4*)xh + (size_t)s * 16;
    float* ag = agg + (size_t)d * 64;
#pragma unroll
    for (int h = 0; h < 4; ++h) {
        float a = al[h];
#pragma unroll
        for (int q = 0; q < 4; ++q) {
            float4 v = xs[h * 4 + q];
            redv4(ag + h * 16 + q * 4, a * v.x, a * v.y, a * v.z, a * v.w);
        }
    }
}

// ---------------- node update: conv = agg + b -> LN -> relu -> residual ------
__global__ void __launch_bounds__(256) k_nodeup(const float* __restrict__ agg,
        const float* __restrict__ gatb, const float* __restrict__ lng,
        const float* __restrict__ lnb, float* __restrict__ node, int Nn) {
    int warp = blockIdx.x * 8 + (threadIdx.x >> 5);
    int lane = threadIdx.x & 31;
    if (warp >= Nn) return;
    float2 cv = ((const float2*)agg)[warp * 32 + lane];
    float2 gb = __ldg((const float2*)gatb + lane);
    cv.x += gb.x; cv.y += gb.y;
    float s = cv.x + cv.y, ss = cv.x * cv.x + cv.y * cv.y;
#pragma unroll
    for (int o = 16; o; o >>= 1) {
        s  += __shfl_xor_sync(0xffffffffu, s, o);
        ss += __shfl_xor_sync(0xffffffffu, ss, o);
    }
    float mu = s * (1.f / 64.f);
    float var = ss * (1.f / 64.f) - mu * mu;
    float r = rsqrtf(var + 1e-5f);
    float2 g = __ldg((const float2*)lng + lane), b = __ldg((const float2*)lnb + lane);
    float y0 = fmaxf((cv.x - mu) * r * g.x + b.x, 0.f);
    float y1 = fmaxf((cv.y - mu) * r * g.y + b.y, 0.f);
    float2* np = (float2*)node + warp * 32 + lane;
    float2 old = *np;
    *np = make_float2(old.x + y0, old.y + y1);
}

__global__ void k_copy(const float4* __restrict__ s, float4* __restrict__ d, int n4) {
    int i = blockIdx.x * blockDim.x + threadIdx.x;
    if (i < n4) d[i] = s[i];
}

// ---------------- launch ----------------
extern "C" void kernel_launch(void* const* d_in, const int* in_sizes, int n_in,
                              void* d_out, int out_size) {
    const int*   x     = (const int*)d_in[0];
    const int*   ea    = (const int*)d_in[1];
    const int*   ei    = (const int*)d_in[2];
    const float* atomT = (const float*)d_in[3];
    const float* bondT = (const float*)d_in[4];
    const float* gatW  = (const float*)d_in[5];
    const float* gatb  = (const float*)d_in[6];
    const float* attS  = (const float*)d_in[7];
    const float* attD  = (const float*)d_in[8];
    const float* attE  = (const float*)d_in[9];
    const float* epW   = (const float*)d_in[10];
    const float* epb   = (const float*)d_in[11];
    const float* lng   = (const float*)d_in[12];
    const float* lnb   = (const float*)d_in[13];
    const float* euW1  = (const float*)d_in[14];
    const float* eub1  = (const float*)d_in[15];
    const float* euW2  = (const float*)d_in[16];
    const float* eub2  = (const float*)d_in[17];

    int N = in_sizes[0] / 9;
    int E = in_sizes[1] / 3;
    const int* src  = ei;
    const int* dstp = ei + E;
    float* out = (float*)d_out;

    float *node, *xh, *P, *Q, *agg, *asrc, *adst, *m, *den, *edge, *h, *logits, *v, *aE;
    cudaGetSymbolAddress((void**)&node,   g_node);
    cudaGetSymbolAddress((void**)&xh,     g_xh);
    cudaGetSymbolAddress((void**)&P,      g_P);
    cudaGetSymbolAddress((void**)&Q,      g_Q);
    cudaGetSymbolAddress((void**)&agg,    g_agg);
    cudaGetSymbolAddress((void**)&asrc,   g_asrc);
    cudaGetSymbolAddress((void**)&adst,   g_adst);
    cudaGetSymbolAddress((void**)&m,      g_m);
    cudaGetSymbolAddress((void**)&den,    g_den);
    cudaGetSymbolAddress((void**)&edge,   g_edge);
    cudaGetSymbolAddress((void**)&h,      g_h);
    cudaGetSymbolAddress((void**)&logits, g_logits);
    cudaGetSymbolAddress((void**)&v,      g_v);
    cudaGetSymbolAddress((void**)&aE,     g_aE);

    // fold edgeproj for all layers upfront
    k_prep<<<4, 256>>>(epW, epb, attE, v);
    k_node_enc<<<(N * 64 + 255) / 256, 256>>>(x, atomT, node, N);
    k_edge_enc2<<<(E + 7) / 8, 256>>>(ea, bondT, v, edge, (float4*)aE, E);

    int gN = (N + 127) / 128;
    int gE = (E + 127) / 128;
    int gE256 = (E + 255) / 256;

    for (int l = 0; l < 4; ++l) {
        k_xh_rb<<<gN, 256>>>(node, gatW + l * 4096, attS + l * 64, attD + l * 64,
                             xh, asrc, adst, m, den, agg, N);
        k_logits2<<<gE256, 256>>>(src, dstp, (const float4*)asrc, (const float4*)adst,
                                  (const float4*)aE, (float4*)logits, m, E);
        k_expsum<<<gE256, 256>>>(dstp, (float4*)logits, (const float4*)m, den, E);
        k_agg<<<gE256, 256>>>(src, dstp, (const float4*)logits, (const float4*)den, xh, agg, E);
        k_nodeup<<<(N + 7) / 8, 256>>>(agg, gatb + l * 64, lng + l * 64, lnb + l * 64, node, N);
        // edge update: P = node@W1a, Q = node@W1b (per-node), then per-edge MLP
        k_gemm_rb<0, 0><<<gN, 256>>>(node, euW1 + l * 12288,        nullptr, P, nullptr, nullptr, N);
        k_gemm_rb<0, 0><<<gN, 256>>>(node, euW1 + l * 12288 + 4096, nullptr, Q, nullptr, nullptr, N);
        k_eu1_rb<<<gE, 256>>>(edge, P, Q, src, dstp,
                              euW1 + l * 12288 + 8192, eub1 + l * 64, h, E);
        if (l < 3) {
            // produce next edge AND its a_edge (folded with layer l+1 params)
            k_gemm_rb<1, 1><<<gE, 256>>>(h, euW2 + l * 4096, eub2 + l * 64, edge,
                                         v + (l + 1) * 260, aE, E);
        } else {
            k_gemm_rb<1, 0><<<gE, 256>>>(h, euW2 + l * 4096, eub2 + l * 64,
                                         out + (size_t)N * 64, nullptr, nullptr, E);
        }
    }

    k_copy<<<(N * 16 + 255) / 256, 256>>>((const float4*)node, (float4*)out, N * 16);
}

// round 4
// speedup vs baseline: 1.2662x; 1.0705x over previous
#include <cuda_runtime.h>
#include <math.h>

#define D 64
#define NMAX 100000
#define EMAX 1200000

typedef unsigned long long ull;

// ---------------- scratch (device globals; no allocation allowed) ----------------
__device__ float g_node[NMAX * D];
__device__ float g_xh[NMAX * D];
__device__ float g_P[NMAX * D];
__device__ float g_Q[NMAX * D];
__device__ float g_agg[NMAX * D];
__device__ float g_asrc[NMAX * 4];
__device__ float g_adst[NMAX * 4];
__device__ float g_m[NMAX * 4];
__device__ float g_den[NMAX * 4];
__device__ float g_edge[EMAX * D];
__device__ float g_logits[EMAX * 4];
__device__ float g_aE[EMAX * 4];
__device__ float g_v[4 * 260];

// ---------------- f32x2 helpers ----------------
__device__ __forceinline__ ull pk2(float x, float y) {
    ull r; asm("mov.b64 %0,{%1,%2};" : "=l"(r) : "f"(x), "f"(y)); return r;
}
__device__ __forceinline__ float2 upk(ull a) {
    float2 r; asm("mov.b64 {%0,%1},%2;" : "=f"(r.x), "=f"(r.y) : "l"(a)); return r;
}
__device__ __forceinline__ ull f2fma(ull a, ull b, ull c) {
    ull d; asm("fma.rn.f32x2 %0,%1,%2,%3;" : "=l"(d) : "l"(a), "l"(b), "l"(c)); return d;
}
__device__ __forceinline__ void redv4(float* p, float a, float b, float c, float d) {
    asm volatile("red.global.add.v4.f32 [%0], {%1,%2,%3,%4};"
                 :: "l"(p), "f"(a), "f"(b), "f"(c), "f"(d) : "memory");
}
__device__ __forceinline__ void atomicMaxF(float* a, float v) {
    if (v >= 0.f) atomicMax((int*)a, __float_as_int(v));
    else          atomicMin((unsigned int*)a, __float_as_uint(v));
}

// ============ register-blocked mainloop: 4 rows x 8 cols per thread ==========
__device__ __forceinline__ void rb8_mainloop(const float* __restrict__ in,
        int r0, int M, const ull* __restrict__ sWu, int cg4, ull acc[4][4]) {
    const float4* in4 = (const float4*)in;
    int ri[4];
#pragma unroll
    for (int t = 0; t < 4; ++t) { int rr = r0 + t; ri[t] = (rr < M ? rr : M - 1) * 16; }
#pragma unroll 4
    for (int k4 = 0; k4 < 16; ++k4) {
        float4 a[4];
#pragma unroll
        for (int t = 0; t < 4; ++t) a[t] = in4[ri[t] + k4];
        const ull* wb = sWu + k4 * 128 + cg4;
#pragma unroll
        for (int kk = 0; kk < 4; ++kk) {
            ull wv[4];
            const ull* w = wb + kk * 32;
#pragma unroll
            for (int j = 0; j < 4; ++j) wv[j] = w[j];
#pragma unroll
            for (int t = 0; t < 4; ++t) {
                float av = (kk == 0) ? a[t].x : (kk == 1) ? a[t].y : (kk == 2) ? a[t].z : a[t].w;
                ull a2 = pk2(av, av);
#pragma unroll
                for (int j = 0; j < 4; ++j) acc[t][j] = f2fma(a2, wv[j], acc[t][j]);
            }
        }
    }
}

// smem-input variant (row stride 68 floats, tile-local rows)
__device__ __forceinline__ void rb8_mainloop_sm(const float* __restrict__ sH,
        int lr0, const ull* __restrict__ sWu, int cg4, ull acc[4][4]) {
#pragma unroll 4
    for (int k4 = 0; k4 < 16; ++k4) {
        float4 a[4];
#pragma unroll
        for (int t = 0; t < 4; ++t) a[t] = *(const float4*)(sH + (lr0 + t) * 68 + k4 * 4);
        const ull* wb = sWu + k4 * 128 + cg4;
#pragma unroll
        for (int kk = 0; kk < 4; ++kk) {
            ull wv[4];
            const ull* w = wb + kk * 32;
#pragma unroll
            for (int j = 0; j < 4; ++j) wv[j] = w[j];
#pragma unroll
            for (int t = 0; t < 4; ++t) {
                float av = (kk == 0) ? a[t].x : (kk == 1) ? a[t].y : (kk == 2) ? a[t].z : a[t].w;
                ull a2 = pk2(av, av);
#pragma unroll
                for (int j = 0; j < 4; ++j) acc[t][j] = f2fma(a2, wv[j], acc[t][j]);
            }
        }
    }
}

// ---------------- encoders ----------------
__global__ void k_node_enc(const int* __restrict__ x, const float* __restrict__ at,
                           float* __restrict__ node, int Nn) {
    int t = blockIdx.x * blockDim.x + threadIdx.x;
    if (t >= Nn * D) return;
    int i = t >> 6, j = t & 63;
    const int* xi = x + i * 9;
    float s = 0.f;
#pragma unroll
    for (int f = 0; f < 9; ++f) { int v = xi[f]; s += at[(f * 16 + v) * 64 + j]; }
    node[t] = s;
}

__global__ void __launch_bounds__(256) k_edge_enc2(const int* __restrict__ ea,
        const float* __restrict__ bt, const float* __restrict__ v0,
        float* __restrict__ edge, float4* __restrict__ aE4, int E) {
    int e = blockIdx.x * 8 + (threadIdx.x >> 5);
    int lane = threadIdx.x & 31;
    if (e >= E) return;
    int f0 = ea[e * 3], f1 = ea[e * 3 + 1], f2 = ea[e * 3 + 2];
    int c0 = 2 * lane, c1 = c0 + 1;
    float s0 = bt[f0 * 64 + c0] + bt[(8 + f1) * 64 + c0] + bt[(16 + f2) * 64 + c0];
    float s1 = bt[f0 * 64 + c1] + bt[(8 + f1) * 64 + c1] + bt[(16 + f2) * 64 + c1];
    ((float2*)(edge + e * 64))[lane] = make_float2(s0, s1);
    float p[4];
#pragma unroll
    for (int h = 0; h < 4; ++h) p[h] = s0 * v0[c0 * 4 + h] + s1 * v0[c1 * 4 + h];
#pragma unroll
    for (int o = 16; o; o >>= 1) {
#pragma unroll
        for (int h = 0; h < 4; ++h) p[h] += __shfl_xor_sync(0xffffffffu, p[h], o);
    }
    if (lane == 0)
        aE4[e] = make_float4(p[0] + v0[256], p[1] + v0[257], p[2] + v0[258], p[3] + v0[259]);
}

// ---------------- per-layer prep ----------------
__global__ void k_prep(const float* __restrict__ epW, const float* __restrict__ epb,
                       const float* __restrict__ attE, float* __restrict__ vall) {
    int l = blockIdx.x;
    const float* W = epW + l * 4096;
    const float* b = epb + l * 64;
    const float* aEv = attE + l * 64;
    float* vout = vall + l * 260;
    int t = threadIdx.x;
    if (t < 256) {
        int k = t >> 2, h = t & 3;
        float s = 0.f;
#pragma unroll
        for (int c = 0; c < 16; ++c) s += W[k * 64 + h * 16 + c] * aEv[h * 16 + c];
        vout[k * 4 + h] = s;
    }
    if (t < 4) {
        float s = 0.f;
#pragma unroll
        for (int c = 0; c < 16; ++c) s += b[t * 16 + c] * aEv[t * 16 + c];
        vout[256 + t] = s;
    }
}

// ---------------- xh = node @ W, a_src/a_dst, init m/den/agg -----------------
__global__ void __launch_bounds__(256, 2) k_xh_rb(const float* __restrict__ node,
        const float* __restrict__ W, const float* __restrict__ attS,
        const float* __restrict__ attD, float* __restrict__ xh,
        float* __restrict__ asrc, float* __restrict__ adst,
        float* __restrict__ m, float* __restrict__ den, float* __restrict__ agg, int M) {
    __shared__ __align__(16) float sW[4096];
    __shared__ float sAS[64], sAD[64];
    for (int i = threadIdx.x; i < 4096; i += 256) sW[i] = W[i];
    if (threadIdx.x < 64) { sAS[threadIdx.x] = attS[threadIdx.x]; sAD[threadIdx.x] = attD[threadIdx.x]; }
    __syncthreads();
    int cg = threadIdx.x & 7, tq = threadIdx.x >> 3;
    int r0 = blockIdx.x * 128 + tq * 4;
    if (r0 >= M) return;
    ull acc[4][4];
#pragma unroll
    for (int t = 0; t < 4; ++t)
#pragma unroll
        for (int j = 0; j < 4; ++j) acc[t][j] = 0ull;
    rb8_mainloop(node, r0, M, (const ull*)sW, cg * 4, acc);
    float ninf = __int_as_float(0xff800000);
    int c0 = cg * 8;
#pragma unroll
    for (int t = 0; t < 4; ++t) {
        int r = r0 + t;
        float as = 0.f, ad = 0.f;
        float4 o[2];
#pragma unroll
        for (int q = 0; q < 2; ++q) {
            float2 v0 = upk(acc[t][2 * q]), v1 = upk(acc[t][2 * q + 1]);
            o[q] = make_float4(v0.x, v0.y, v1.x, v1.y);
            int c = c0 + 4 * q;
            as += v0.x * sAS[c] + v0.y * sAS[c + 1] + v1.x * sAS[c + 2] + v1.y * sAS[c + 3];
            ad += v0.x * sAD[c] + v0.y * sAD[c + 1] + v1.x * sAD[c + 2] + v1.y * sAD[c + 3];
        }
        as += __shfl_xor_sync(0xffffffffu, as, 1);
        ad += __shfl_xor_sync(0xffffffffu, ad, 1);
        if (r < M) {
            float4* xp = (float4*)(xh + (size_t)r * 64 + c0);
            float4* ap = (float4*)(agg + (size_t)r * 64 + c0);
            float4 z = make_float4(0.f, 0.f, 0.f, 0.f);
            xp[0] = o[0]; xp[1] = o[1];
            ap[0] = z;    ap[1] = z;
            if ((cg & 1) == 0) {
                int h = cg >> 1;
                asrc[r * 4 + h] = as;
                adst[r * 4 + h] = ad;
            }
            if (cg < 4) { m[r * 4 + cg] = ninf; den[r * 4 + cg] = 0.f; }
        }
    }
}

// ---------------- fused P+Q: both node @ W over same input -------------------
__global__ void __launch_bounds__(256, 2) k_pq(const float* __restrict__ node,
        const float* __restrict__ Wa, const float* __restrict__ Wb,
        float* __restrict__ P, float* __restrict__ Q, int M) {
    __shared__ __align__(16) float sWa[4096];
    __shared__ __align__(16) float sWb[4096];
    for (int i = threadIdx.x; i < 4096; i += 256) { sWa[i] = Wa[i]; sWb[i] = Wb[i]; }
    __syncthreads();
    int cg = threadIdx.x & 7, tq = threadIdx.x >> 3;
    int r0 = blockIdx.x * 128 + tq * 4;
    if (r0 >= M) return;
    int c0 = cg * 8;
    ull acc[4][4];
#pragma unroll
    for (int t = 0; t < 4; ++t)
#pragma unroll
        for (int j = 0; j < 4; ++j) acc[t][j] = 0ull;
    rb8_mainloop(node, r0, M, (const ull*)sWa, cg * 4, acc);
#pragma unroll
    for (int t = 0; t < 4; ++t) {
        int r = r0 + t;
        if (r < M) {
            float4* op = (float4*)(P + (size_t)r * 64 + c0);
            float2 v0 = upk(acc[t][0]), v1 = upk(acc[t][1]);
            op[0] = make_float4(v0.x, v0.y, v1.x, v1.y);
            v0 = upk(acc[t][2]); v1 = upk(acc[t][3]);
            op[1] = make_float4(v0.x, v0.y, v1.x, v1.y);
        }
    }
#pragma unroll
    for (int t = 0; t < 4; ++t)
#pragma unroll
        for (int j = 0; j < 4; ++j) acc[t][j] = 0ull;
    rb8_mainloop(node, r0, M, (const ull*)sWb, cg * 4, acc);
#pragma unroll
    for (int t = 0; t < 4; ++t) {
        int r = r0 + t;
        if (r < M) {
            float4* op = (float4*)(Q + (size_t)r * 64 + c0);
            float2 v0 = upk(acc[t][0]), v1 = upk(acc[t][1]);
            op[0] = make_float4(v0.x, v0.y, v1.x, v1.y);
            v0 = upk(acc[t][2]); v1 = upk(acc[t][3]);
            op[1] = make_float4(v0.x, v0.y, v1.x, v1.y);
        }
    }
}

// ---------------- fused edge update: two GEMMs, h tile in smem ---------------
// dyn smem: sW1[4096] sW2[4096] sB[128] sV[260] sH[128*68]
template <int AEDGE>
__global__ void __launch_bounds__(256) k_eu_fused(const float* __restrict__ edge,
        const float* __restrict__ P, const float* __restrict__ Q,
        const int* __restrict__ src, const int* __restrict__ dst,
        const float* __restrict__ W1c, const float* __restrict__ b1,
        const float* __restrict__ W2, const float* __restrict__ b2,
        float* __restrict__ out, const float* __restrict__ vE,
        float* __restrict__ aE, int E) {
    extern __shared__ float sm[];
    float* sW1 = sm;
    float* sW2 = sm + 4096;
    float* sB  = sm + 8192;   // [0:64) b1, [64:128) b2
    float* sV  = sm + 8320;
    float* sH  = sm + 8580;
    for (int i = threadIdx.x; i < 4096; i += 256) { sW1[i] = W1c[i]; sW2[i] = W2[i]; }
    if (threadIdx.x < 64) sB[threadIdx.x] = b1[threadIdx.x];
    else if (threadIdx.x < 128) sB[threadIdx.x] = b2[threadIdx.x - 64];
    if (AEDGE) { for (int i = threadIdx.x; i < 260; i += 256) sV[i] = vE[i]; }
    __syncthreads();
    int cg = threadIdx.x & 7, tq = threadIdx.x >> 3;
    int r0 = blockIdx.x * 128 + tq * 4;
    int c0 = cg * 8;
    int lr0 = tq * 4;
    // indices (clamped)
    int ss[4], dd[4];
#pragma unroll
    for (int t = 0; t < 4; ++t) {
        int r = r0 + t; if (r >= E) r = E - 1;
        ss[t] = src[r]; dd[t] = dst[r];
    }
    // ---- GEMM1: h = relu(P[src] + Q[dst] + edge@W1c + b1) ----
    ull acc[4][4];
#pragma unroll
    for (int t = 0; t < 4; ++t) {
        const float4* Pp = (const float4*)(P + (size_t)ss[t] * 64 + c0);
        const float4* Qp = (const float4*)(Q + (size_t)dd[t] * 64 + c0);
#pragma unroll
        for (int q = 0; q < 2; ++q) {
            float4 pv = Pp[q], qv = Qp[q];
            const float* b = sB + c0 + 4 * q;
            acc[t][2 * q]     = pk2(pv.x + qv.x + b[0], pv.y + qv.y + b[1]);
            acc[t][2 * q + 1] = pk2(pv.z + qv.z + b[2], pv.w + qv.w + b[3]);
        }
    }
    rb8_mainloop(edge, r0, E, (const ull*)sW1, cg * 4, acc);
#pragma unroll
    for (int t = 0; t < 4; ++t) {
        float* hp = sH + (lr0 + t) * 68 + c0;
#pragma unroll
        for (int q = 0; q < 2; ++q) {
            float2 v0 = upk(acc[t][2 * q]), v1 = upk(acc[t][2 * q + 1]);
            *(float4*)(hp + 4 * q) = make_float4(fmaxf(v0.x, 0.f), fmaxf(v0.y, 0.f),
                                                 fmaxf(v1.x, 0.f), fmaxf(v1.y, 0.f));
        }
    }
    __syncthreads();
    // ---- GEMM2: out = relu(h @ W2 + b2) ----
#pragma unroll
    for (int j = 0; j < 4; ++j) {
        ull bi = pk2(sB[64 + c0 + 2 * j], sB[64 + c0 + 2 * j + 1]);
#pragma unroll
        for (int t = 0; t < 4; ++t) acc[t][j] = bi;
    }
    rb8_mainloop_sm(sH, lr0, (const ull*)sW2, cg * 4, acc);
#pragma unroll
    for (int t = 0; t < 4; ++t) {
        int r = r0 + t;
        float4 o[2];
#pragma unroll
        for (int q = 0; q < 2; ++q) {
            float2 v0 = upk(acc[t][2 * q]), v1 = upk(acc[t][2 * q + 1]);
            o[q] = make_float4(fmaxf(v0.x, 0.f), fmaxf(v0.y, 0.f),
                               fmaxf(v1.x, 0.f), fmaxf(v1.y, 0.f));
        }
        if (r < E) {
            float4* op = (float4*)(out + (size_t)r * 64 + c0);
            op[0] = o[0]; op[1] = o[1];
        }
        if (AEDGE) {
            float p[4] = {0.f, 0.f, 0.f, 0.f};
#pragma unroll
            for (int q = 0; q < 2; ++q) {
                const float* vv = sV + (c0 + 4 * q) * 4;
#pragma unroll
                for (int h = 0; h < 4; ++h)
                    p[h] += o[q].x * vv[h] + o[q].y * vv[4 + h] + o[q].z * vv[8 + h] + o[q].w * vv[12 + h];
            }
#pragma unroll
            for (int h = 0; h < 4; ++h) {
                p[h] += __shfl_xor_sync(0xffffffffu, p[h], 1);
                p[h] += __shfl_xor_sync(0xffffffffu, p[h], 2);
                p[h] += __shfl_xor_sync(0xffffffffu, p[h], 4);
            }
            if (r < E && cg < 4) aE[r * 4 + cg] = p[cg] + sV[256 + cg];
        }
    }
}

// ---------------- attention pass 1: logits + segment max ---------------------
__global__ void __launch_bounds__(256) k_logits2(const int* __restrict__ src,
        const int* __restrict__ dst, const float4* __restrict__ asrc4,
        const float4* __restrict__ adst4, const float4* __restrict__ aE4,
        float4* __restrict__ logits4, float* __restrict__ m, int E) {
    int e = blockIdx.x * 256 + threadIdx.x;
    if (e >= E) return;
    int s = src[e], d = dst[e];
    float4 ae = aE4[e];
    float4 as = asrc4[s], ad = adst4[d];
    float t0 = as.x + ad.x + ae.x, t1 = as.y + ad.y + ae.y;
    float t2 = as.z + ad.z + ae.z, t3 = as.w + ad.w + ae.w;
    t0 = t0 > 0.f ? t0 : 0.2f * t0;
    t1 = t1 > 0.f ? t1 : 0.2f * t1;
    t2 = t2 > 0.f ? t2 : 0.2f * t2;
    t3 = t3 > 0.f ? t3 : 0.2f * t3;
    logits4[e] = make_float4(t0, t1, t2, t3);
    float* md = m + d * 4;
    atomicMaxF(md + 0, t0); atomicMaxF(md + 1, t1);
    atomicMaxF(md + 2, t2); atomicMaxF(md + 3, t3);
}

// ---------------- fused pass 2+3: ex, den-RED, agg-RED of ex*xh --------------
__global__ void __launch_bounds__(256) k_aggfused(const int* __restrict__ src,
        const int* __restrict__ dst, const float4* __restrict__ logits4,
        const float4* __restrict__ m4, float* __restrict__ den,
        const float* __restrict__ xh, float* __restrict__ agg, int E) {
    int e = blockIdx.x * 256 + threadIdx.x;
    if (e >= E) return;
    int s = src[e], d = dst[e];
    float4 lg = logits4[e];
    float4 mm = m4[d];
    float e0 = expf(lg.x - mm.x), e1 = expf(lg.y - mm.y);
    float e2 = expf(lg.z - mm.z), e3 = expf(lg.w - mm.w);
    redv4(den + d * 4, e0, e1, e2, e3);
    float al[4] = {e0, e1, e2, e3};
    const float4* xs = (const float4*)xh + (size_t)s * 16;
    float* ag = agg + (size_t)d * 64;
#pragma unroll
    for (int h = 0; h < 4; ++h) {
        float a = al[h];
#pragma unroll
        for (int q = 0; q < 4; ++q) {
            float4 v = xs[h * 4 + q];
            redv4(ag + h * 16 + q * 4, a * v.x, a * v.y, a * v.z, a * v.w);
        }
    }
}

// -------- node update: conv = agg/den + b -> LN -> relu -> residual ----------
__global__ void __launch_bounds__(256) k_nodeup2(const float* __restrict__ agg,
        const float* __restrict__ den, const float* __restrict__ gatb,
        const float* __restrict__ lng, const float* __restrict__ lnb,
        float* __restrict__ node, int Nn) {
    int warp = blockIdx.x * 8 + (threadIdx.x >> 5);
    int lane = threadIdx.x & 31;
    if (warp >= Nn) return;
    float2 cv = ((const float2*)agg)[warp * 32 + lane];
    float dh = den[warp * 4 + (lane >> 3)] + 1e-16f;
    float inv = 1.f / dh;
    float2 gb = __ldg((const float2*)gatb + lane);
    cv.x = cv.x * inv + gb.x; cv.y = cv.y * inv + gb.y;
    float s = cv.x + cv.y, ss = cv.x * cv.x + cv.y * cv.y;
#pragma unroll
    for (int o = 16; o; o >>= 1) {
        s  += __shfl_xor_sync(0xffffffffu, s, o);
        ss += __shfl_xor_sync(0xffffffffu, ss, o);
    }
    float mu = s * (1.f / 64.f);
    float var = ss * (1.f / 64.f) - mu * mu;
    float r = rsqrtf(var + 1e-5f);
    float2 g = __ldg((const float2*)lng + lane), b = __ldg((const float2*)lnb + lane);
    float y0 = fmaxf((cv.x - mu) * r * g.x + b.x, 0.f);
    float y1 = fmaxf((cv.y - mu) * r * g.y + b.y, 0.f);
    float2* np = (float2*)node + warp * 32 + lane;
    float2 old = *np;
    *np = make_float2(old.x + y0, old.y + y1);
}

__global__ void k_copy(const float4* __restrict__ s, float4* __restrict__ d, int n4) {
    int i = blockIdx.x * blockDim.x + threadIdx.x;
    if (i < n4) d[i] = s[i];
}

// ---------------- launch ----------------
extern "C" void kernel_launch(void* const* d_in, const int* in_sizes, int n_in,
                              void* d_out, int out_size) {
    const int*   x     = (const int*)d_in[0];
    const int*   ea    = (const int*)d_in[1];
    const int*   ei    = (const int*)d_in[2];
    const float* atomT = (const float*)d_in[3];
    const float* bondT = (const float*)d_in[4];
    const float* gatW  = (const float*)d_in[5];
    const float* gatb  = (const float*)d_in[6];
    const float* attS  = (const float*)d_in[7];
    const float* attD  = (const float*)d_in[8];
    const float* attE  = (const float*)d_in[9];
    const float* epW   = (const float*)d_in[10];
    const float* epb   = (const float*)d_in[11];
    const float* lng   = (const float*)d_in[12];
    const float* lnb   = (const float*)d_in[13];
    const float* euW1  = (const float*)d_in[14];
    const float* eub1  = (const float*)d_in[15];
    const float* euW2  = (const float*)d_in[16];
    const float* eub2  = (const float*)d_in[17];

    int N = in_sizes[0] / 9;
    int E = in_sizes[1] / 3;
    const int* src  = ei;
    const int* dstp = ei + E;
    float* out = (float*)d_out;

    float *node, *xh, *P, *Q, *agg, *asrc, *adst, *m, *den, *edge, *logits, *v, *aE;
    cudaGetSymbolAddress((void**)&node,   g_node);
    cudaGetSymbolAddress((void**)&xh,     g_xh);
    cudaGetSymbolAddress((void**)&P,      g_P);
    cudaGetSymbolAddress((void**)&Q,      g_Q);
    cudaGetSymbolAddress((void**)&agg,    g_agg);
    cudaGetSymbolAddress((void**)&asrc,   g_asrc);
    cudaGetSymbolAddress((void**)&adst,   g_adst);
    cudaGetSymbolAddress((void**)&m,      g_m);
    cudaGetSymbolAddress((void**)&den,    g_den);
    cudaGetSymbolAddress((void**)&edge,   g_edge);
    cudaGetSymbolAddress((void**)&logits, g_logits);
    cudaGetSymbolAddress((void**)&v,      g_v);
    cudaGetSymbolAddress((void**)&aE,     g_aE);

    const int EU_SMEM = (8580 + 128 * 68) * 4;  // 69136 bytes
    cudaFuncSetAttribute(k_eu_fused<0>, cudaFuncAttributeMaxDynamicSharedMemorySize, EU_SMEM);
    cudaFuncSetAttribute(k_eu_fused<1>, cudaFuncAttributeMaxDynamicSharedMemorySize, EU_SMEM);

    k_prep<<<4, 256>>>(epW, epb, attE, v);
    k_node_enc<<<(N * 64 + 255) / 256, 256>>>(x, atomT, node, N);
    k_edge_enc2<<<(E + 7) / 8, 256>>>(ea, bondT, v, edge, (float4*)aE, E);

    int gN = (N + 127) / 128;
    int gE = (E + 127) / 128;
    int gE256 = (E + 255) / 256;

    for (int l = 0; l < 4; ++l) {
        k_xh_rb<<<gN, 256>>>(node, gatW + l * 4096, attS + l * 64, attD + l * 64,
                             xh, asrc, adst, m, den, agg, N);
        k_logits2<<<gE256, 256>>>(src, dstp, (const float4*)asrc, (const float4*)adst,
                                  (const float4*)aE, (float4*)logits, m, E);
        k_aggfused<<<gE256, 256>>>(src, dstp, (const float4*)logits, (const float4*)m,
                                   den, xh, agg, E);
        k_nodeup2<<<(N + 7) / 8, 256>>>(agg, den, gatb + l * 64, lng + l * 64,
                                        lnb + l * 64, node, N);
        k_pq<<<gN, 256>>>(node, euW1 + l * 12288, euW1 + l * 12288 + 4096, P, Q, N);
        if (l < 3) {
            k_eu_fused<1><<<gE, 256, EU_SMEM>>>(edge, P, Q, src, dstp,
                    euW1 + l * 12288 + 8192, eub1 + l * 64,
                    euW2 + l * 4096, eub2 + l * 64,
                    edge, v + (l + 1) * 260, aE, E);
        } else {
            k_eu_fused<0><<<gE, 256, EU_SMEM>>>(edge, P, Q, src, dstp,
                    euW1 + l * 12288 + 8192, eub1 + l * 64,
                    euW2 + l * 4096, eub2 + l * 64,
                    out + (size_t)N * 64, nullptr, nullptr, E);
        }
    }

    k_copy<<<(N * 16 + 255) / 256, 256>>>((const float4*)node, (float4*)out, N * 16);
}

// round 5
// speedup vs baseline: 1.3573x; 1.0720x over previous
#include <cuda_runtime.h>
#include <math.h>

#define D 64
#define NMAX 100000
#define EMAX 1200000

typedef unsigned long long ull;

// ---------------- scratch (device globals; no allocation allowed) ----------------
__device__ float g_node[NMAX * D];
__device__ float g_xh[NMAX * D];
__device__ float g_P[NMAX * D];
__device__ float g_Q[NMAX * D];
__device__ float g_agg[NMAX * D];
__device__ float g_asrc[NMAX * 4];
__device__ float g_adst[NMAX * 4];
__device__ float g_den[NMAX * 4];
__device__ float g_edge[EMAX * D];
__device__ float g_aE[EMAX * 4];
__device__ float g_v[4 * 260];
// CSR scratch
__device__ int  g_deg[NMAX];
__device__ int  g_off[NMAX];
__device__ int  g_cur[NMAX];
__device__ int  g_bsum[512];
__device__ int2 g_pay[EMAX];

// ---------------- f32x2 helpers ----------------
__device__ __forceinline__ ull pk2(float x, float y) {
    ull r; asm("mov.b64 %0,{%1,%2};" : "=l"(r) : "f"(x), "f"(y)); return r;
}
__device__ __forceinline__ float2 upk(ull a) {
    float2 r; asm("mov.b64 {%0,%1},%2;" : "=f"(r.x), "=f"(r.y) : "l"(a)); return r;
}
__device__ __forceinline__ ull f2fma(ull a, ull b, ull c) {
    ull d; asm("fma.rn.f32x2 %0,%1,%2,%3;" : "=l"(d) : "l"(a), "l"(b), "l"(c)); return d;
}

// ============ register-blocked mainloop: 4 rows x 8 cols per thread ==========
__device__ __forceinline__ void rb8_mainloop(const float* __restrict__ in,
        int r0, int M, const ull* __restrict__ sWu, int cg4, ull acc[4][4]) {
    const float4* in4 = (const float4*)in;
    int ri[4];
#pragma unroll
    for (int t = 0; t < 4; ++t) { int rr = r0 + t; ri[t] = (rr < M ? rr : M - 1) * 16; }
#pragma unroll 4
    for (int k4 = 0; k4 < 16; ++k4) {
        float4 a[4];
#pragma unroll
        for (int t = 0; t < 4; ++t) a[t] = in4[ri[t] + k4];
        const ull* wb = sWu + k4 * 128 + cg4;
#pragma unroll
        for (int kk = 0; kk < 4; ++kk) {
            ull wv[4];
            const ull* w = wb + kk * 32;
#pragma unroll
            for (int j = 0; j < 4; ++j) wv[j] = w[j];
#pragma unroll
            for (int t = 0; t < 4; ++t) {
                float av = (kk == 0) ? a[t].x : (kk == 1) ? a[t].y : (kk == 2) ? a[t].z : a[t].w;
                ull a2 = pk2(av, av);
#pragma unroll
                for (int j = 0; j < 4; ++j) acc[t][j] = f2fma(a2, wv[j], acc[t][j]);
            }
        }
    }
}

__device__ __forceinline__ void rb8_mainloop_sm(const float* __restrict__ sH,
        int lr0, const ull* __restrict__ sWu, int cg4, ull acc[4][4]) {
#pragma unroll 4
    for (int k4 = 0; k4 < 16; ++k4) {
        float4 a[4];
#pragma unroll
        for (int t = 0; t < 4; ++t) a[t] = *(const float4*)(sH + (lr0 + t) * 68 + k4 * 4);
        const ull* wb = sWu + k4 * 128 + cg4;
#pragma unroll
        for (int kk = 0; kk < 4; ++kk) {
            ull wv[4];
            const ull* w = wb + kk * 32;
#pragma unroll
            for (int j = 0; j < 4; ++j) wv[j] = w[j];
#pragma unroll
            for (int t = 0; t < 4; ++t) {
                float av = (kk == 0) ? a[t].x : (kk == 1) ? a[t].y : (kk == 2) ? a[t].z : a[t].w;
                ull a2 = pk2(av, av);
#pragma unroll
                for (int j = 0; j < 4; ++j) acc[t][j] = f2fma(a2, wv[j], acc[t][j]);
            }
        }
    }
}

// ---------------- CSR build ----------------
__global__ void k_zero(int* __restrict__ a, int n) {
    int i = blockIdx.x * blockDim.x + threadIdx.x;
    if (i < n) a[i] = 0;
}
__global__ void k_hist(const int* __restrict__ dst, int* __restrict__ deg, int E) {
    int e = blockIdx.x * blockDim.x + threadIdx.x;
    if (e < E) atomicAdd(&deg[dst[e]], 1);
}
__global__ void k_scan1(const int* __restrict__ deg, int* __restrict__ bsum, int Nn) {
    __shared__ int s[256];
    int i = blockIdx.x * 256 + threadIdx.x;
    s[threadIdx.x] = (i < Nn) ? deg[i] : 0;
    __syncthreads();
    for (int o = 128; o; o >>= 1) {
        if (threadIdx.x < o) s[threadIdx.x] += s[threadIdx.x + o];
        __syncthreads();
    }
    if (threadIdx.x == 0) bsum[blockIdx.x] = s[0];
}
__global__ void k_scan2(int* __restrict__ bsum, int nb) {
    __shared__ int s[512];
    int t = threadIdx.x;
    int v = (t < nb) ? bsum[t] : 0;
    s[t] = v;
    __syncthreads();
    for (int o = 1; o < 512; o <<= 1) {
        int x = (t >= o) ? s[t - o] : 0;
        __syncthreads();
        s[t] += x;
        __syncthreads();
    }
    if (t < nb) bsum[t] = s[t] - v;  // exclusive
}
__global__ void k_scan3(const int* __restrict__ deg, const int* __restrict__ bsum,
                        int* __restrict__ off, int* __restrict__ cur, int Nn) {
    __shared__ int s[256];
    int i = blockIdx.x * 256 + threadIdx.x;
    int t = threadIdx.x;
    int v = (i < Nn) ? deg[i] : 0;
    s[t] = v;
    __syncthreads();
    for (int o = 1; o < 256; o <<= 1) {
        int x = (t >= o) ? s[t - o] : 0;
        __syncthreads();
        s[t] += x;
        __syncthreads();
    }
    if (i < Nn) {
        int excl = s[t] - v + bsum[blockIdx.x];
        off[i] = excl;
        cur[i] = excl;
    }
}
__global__ void k_scatter(const int* __restrict__ src, const int* __restrict__ dst,
                          int* __restrict__ cur, int2* __restrict__ pay, int E) {
    int e = blockIdx.x * blockDim.x + threadIdx.x;
    if (e >= E) return;
    int p = atomicAdd(&cur[dst[e]], 1);
    pay[p] = make_int2(src[e], e);
}

// ---------------- encoders ----------------
__global__ void k_node_enc(const int* __restrict__ x, const float* __restrict__ at,
                           float* __restrict__ node, int Nn) {
    int t = blockIdx.x * blockDim.x + threadIdx.x;
    if (t >= Nn * D) return;
    int i = t >> 6, j = t & 63;
    const int* xi = x + i * 9;
    float s = 0.f;
#pragma unroll
    for (int f = 0; f < 9; ++f) { int v = xi[f]; s += at[(f * 16 + v) * 64 + j]; }
    node[t] = s;
}

__global__ void __launch_bounds__(256) k_edge_enc2(const int* __restrict__ ea,
        const float* __restrict__ bt, const float* __restrict__ v0,
        float* __restrict__ edge, float4* __restrict__ aE4, int E) {
    int e = blockIdx.x * 8 + (threadIdx.x >> 5);
    int lane = threadIdx.x & 31;
    if (e >= E) return;
    int f0 = ea[e * 3], f1 = ea[e * 3 + 1], f2 = ea[e * 3 + 2];
    int c0 = 2 * lane, c1 = c0 + 1;
    float s0 = bt[f0 * 64 + c0] + bt[(8 + f1) * 64 + c0] + bt[(16 + f2) * 64 + c0];
    float s1 = bt[f0 * 64 + c1] + bt[(8 + f1) * 64 + c1] + bt[(16 + f2) * 64 + c1];
    ((float2*)(edge + e * 64))[lane] = make_float2(s0, s1);
    float p[4];
#pragma unroll
    for (int h = 0; h < 4; ++h) p[h] = s0 * v0[c0 * 4 + h] + s1 * v0[c1 * 4 + h];
#pragma unroll
    for (int o = 16; o; o >>= 1) {
#pragma unroll
        for (int h = 0; h < 4; ++h) p[h] += __shfl_xor_sync(0xffffffffu, p[h], o);
    }
    if (lane == 0)
        aE4[e] = make_float4(p[0] + v0[256], p[1] + v0[257], p[2] + v0[258], p[3] + v0[259]);
}

// ---------------- per-layer prep ----------------
__global__ void k_prep(const float* __restrict__ epW, const float* __restrict__ epb,
                       const float* __restrict__ attE, float* __restrict__ vall) {
    int l = blockIdx.x;
    const float* W = epW + l * 4096;
    const float* b = epb + l * 64;
    const float* aEv = attE + l * 64;
    float* vout = vall + l * 260;
    int t = threadIdx.x;
    if (t < 256) {
        int k = t >> 2, h = t & 3;
        float s = 0.f;
#pragma unroll
        for (int c = 0; c < 16; ++c) s += W[k * 64 + h * 16 + c] * aEv[h * 16 + c];
        vout[k * 4 + h] = s;
    }
    if (t < 4) {
        float s = 0.f;
#pragma unroll
        for (int c = 0; c < 16; ++c) s += b[t * 16 + c] * aEv[t * 16 + c];
        vout[256 + t] = s;
    }
}

// ---------------- xh = node @ W + a_src/a_dst --------------------------------
__global__ void __launch_bounds__(256, 2) k_xh_rb(const float* __restrict__ node,
        const float* __restrict__ W, const float* __restrict__ attS,
        const float* __restrict__ attD, float* __restrict__ xh,
        float* __restrict__ asrc, float* __restrict__ adst, int M) {
    __shared__ __align__(16) float sW[4096];
    __shared__ float sAS[64], sAD[64];
    for (int i = threadIdx.x; i < 4096; i += 256) sW[i] = W[i];
    if (threadIdx.x < 64) { sAS[threadIdx.x] = attS[threadIdx.x]; sAD[threadIdx.x] = attD[threadIdx.x]; }
    __syncthreads();
    int cg = threadIdx.x & 7, tq = threadIdx.x >> 3;
    int r0 = blockIdx.x * 128 + tq * 4;
    if (r0 >= M) return;
    ull acc[4][4];
#pragma unroll
    for (int t = 0; t < 4; ++t)
#pragma unroll
        for (int j = 0; j < 4; ++j) acc[t][j] = 0ull;
    rb8_mainloop(node, r0, M, (const ull*)sW, cg * 4, acc);
    int c0 = cg * 8;
#pragma unroll
    for (int t = 0; t < 4; ++t) {
        int r = r0 + t;
        float as = 0.f, ad = 0.f;
        float4 o[2];
#pragma unroll
        for (int q = 0; q < 2; ++q) {
            float2 v0 = upk(acc[t][2 * q]), v1 = upk(acc[t][2 * q + 1]);
            o[q] = make_float4(v0.x, v0.y, v1.x, v1.y);
            int c = c0 + 4 * q;
            as += v0.x * sAS[c] + v0.y * sAS[c + 1] + v1.x * sAS[c + 2] + v1.y * sAS[c + 3];
            ad += v0.x * sAD[c] + v0.y * sAD[c + 1] + v1.x * sAD[c + 2] + v1.y * sAD[c + 3];
        }
        as += __shfl_xor_sync(0xffffffffu, as, 1);
        ad += __shfl_xor_sync(0xffffffffu, ad, 1);
        if (r < M) {
            float4* xp = (float4*)(xh + (size_t)r * 64 + c0);
            xp[0] = o[0]; xp[1] = o[1];
            if ((cg & 1) == 0) {
                int h = cg >> 1;
                asrc[r * 4 + h] = as;
                adst[r * 4 + h] = ad;
            }
        }
    }
}

// ---------------- CSR attention: warp per dst node, no atomics ---------------
__global__ void __launch_bounds__(256) k_attn(const int* __restrict__ off,
        const int* __restrict__ deg, const int2* __restrict__ pay,
        const float* __restrict__ asrc, const float* __restrict__ adst,
        const float* __restrict__ aE, const float* __restrict__ xh,
        float* __restrict__ agg, float* __restrict__ den, int Nn) {
    int w = blockIdx.x * 8 + (threadIdx.x >> 5);
    int l = threadIdx.x & 31;
    if (w >= Nn) return;
    int beg = off[w], dg = deg[w];
    int h = l >> 3;
    float ad = adst[w * 4 + h];
    // pass 1: segment max of leaky(logit) for this lane's head
    float mh = __int_as_float(0xff800000);
    for (int i = 0; i < dg; ++i) {
        int2 p = pay[beg + i];
        float a = asrc[p.x * 4 + h] + ad + aE[p.y * 4 + h];
        a = a > 0.f ? a : 0.2f * a;
        mh = fmaxf(mh, a);
    }
    // pass 2: exp, den, weighted accumulation of xh[src]
    float dh = 0.f;
    float2 acc = make_float2(0.f, 0.f);
    for (int i = 0; i < dg; ++i) {
        int2 p = pay[beg + i];
        float a = asrc[p.x * 4 + h] + ad + aE[p.y * 4 + h];
        a = a > 0.f ? a : 0.2f * a;
        float ex = expf(a - mh);
        dh += ex;
        float2 xv = ((const float2*)xh)[p.x * 32 + l];
        acc.x += ex * xv.x;
        acc.y += ex * xv.y;
    }
    ((float2*)agg)[w * 32 + l] = acc;
    if ((l & 7) == 0) den[w * 4 + h] = dh;
}

// ---------------- fused P+Q ----------------
__global__ void __launch_bounds__(256, 2) k_pq(const float* __restrict__ node,
        const float* __restrict__ Wa, const float* __restrict__ Wb,
        float* __restrict__ P, float* __restrict__ Q, int M) {
    __shared__ __align__(16) float sWa[4096];
    __shared__ __align__(16) float sWb[4096];
    for (int i = threadIdx.x; i < 4096; i += 256) { sWa[i] = Wa[i]; sWb[i] = Wb[i]; }
    __syncthreads();
    int cg = threadIdx.x & 7, tq = threadIdx.x >> 3;
    int r0 = blockIdx.x * 128 + tq * 4;
    if (r0 >= M) return;
    int c0 = cg * 8;
    ull acc[4][4];
#pragma unroll
    for (int t = 0; t < 4; ++t)
#pragma unroll
        for (int j = 0; j < 4; ++j) acc[t][j] = 0ull;
    rb8_mainloop(node, r0, M, (const ull*)sWa, cg * 4, acc);
#pragma unroll
    for (int t = 0; t < 4; ++t) {
        int r = r0 + t;
        if (r < M) {
            float4* op = (float4*)(P + (size_t)r * 64 + c0);
            float2 v0 = upk(acc[t][0]), v1 = upk(acc[t][1]);
            op[0] = make_float4(v0.x, v0.y, v1.x, v1.y);
            v0 = upk(acc[t][2]); v1 = upk(acc[t][3]);
            op[1] = make_float4(v0.x, v0.y, v1.x, v1.y);
        }
    }
#pragma unroll
    for (int t = 0; t < 4; ++t)
#pragma unroll
        for (int j = 0; j < 4; ++j) acc[t][j] = 0ull;
    rb8_mainloop(node, r0, M, (const ull*)sWb, cg * 4, acc);
#pragma unroll
    for (int t = 0; t < 4; ++t) {
        int r = r0 + t;
        if (r < M) {
            float4* op = (float4*)(Q + (size_t)r * 64 + c0);
            float2 v0 = upk(acc[t][0]), v1 = upk(acc[t][1]);
            op[0] = make_float4(v0.x, v0.y, v1.x, v1.y);
            v0 = upk(acc[t][2]); v1 = upk(acc[t][3]);
            op[1] = make_float4(v0.x, v0.y, v1.x, v1.y);
        }
    }
}

// ---------------- fused edge update ----------------
template <int AEDGE>
__global__ void __launch_bounds__(256) k_eu_fused(const float* __restrict__ edge,
        const float* __restrict__ P, const float* __restrict__ Q,
        const int* __restrict__ src, const int* __restrict__ dst,
        const float* __restrict__ W1c, const float* __restrict__ b1,
        const float* __restrict__ W2, const float* __restrict__ b2,
        float* __restrict__ out, const float* __restrict__ vE,
        float* __restrict__ aE, int E) {
    extern __shared__ float sm[];
    float* sW1 = sm;
    float* sW2 = sm + 4096;
    float* sB  = sm + 8192;
    float* sV  = sm + 8320;
    float* sH  = sm + 8580;
    for (int i = threadIdx.x; i < 4096; i += 256) { sW1[i] = W1c[i]; sW2[i] = W2[i]; }
    if (threadIdx.x < 64) sB[threadIdx.x] = b1[threadIdx.x];
    else if (threadIdx.x < 128) sB[threadIdx.x] = b2[threadIdx.x - 64];
    if (AEDGE) { for (int i = threadIdx.x; i < 260; i += 256) sV[i] = vE[i]; }
    __syncthreads();
    int cg = threadIdx.x & 7, tq = threadIdx.x >> 3;
    int r0 = blockIdx.x * 128 + tq * 4;
    int c0 = cg * 8;
    int lr0 = tq * 4;
    int ss[4], dd[4];
#pragma unroll
    for (int t = 0; t < 4; ++t) {
        int r = r0 + t; if (r >= E) r = E - 1;
        ss[t] = src[r]; dd[t] = dst[r];
    }
    ull acc[4][4];
#pragma unroll
    for (int t = 0; t < 4; ++t) {
        const float4* Pp = (const float4*)(P + (size_t)ss[t] * 64 + c0);
        const float4* Qp = (const float4*)(Q + (size_t)dd[t] * 64 + c0);
#pragma unroll
        for (int q = 0; q < 2; ++q) {
            float4 pv = Pp[q], qv = Qp[q];
            const float* b = sB + c0 + 4 * q;
            acc[t][2 * q]     = pk2(pv.x + qv.x + b[0], pv.y + qv.y + b[1]);
            acc[t][2 * q + 1] = pk2(pv.z + qv.z + b[2], pv.w + qv.w + b[3]);
        }
    }
    rb8_mainloop(edge, r0, E, (const ull*)sW1, cg * 4, acc);
#pragma unroll
    for (int t = 0; t < 4; ++t) {
        float* hp = sH + (lr0 + t) * 68 + c0;
#pragma unroll
        for (int q = 0; q < 2; ++q) {
            float2 v0 = upk(acc[t][2 * q]), v1 = upk(acc[t][2 * q + 1]);
            *(float4*)(hp + 4 * q) = make_float4(fmaxf(v0.x, 0.f), fmaxf(v0.y, 0.f),
                                                 fmaxf(v1.x, 0.f), fmaxf(v1.y, 0.f));
        }
    }
    __syncthreads();
#pragma unroll
    for (int j = 0; j < 4; ++j) {
        ull bi = pk2(sB[64 + c0 + 2 * j], sB[64 + c0 + 2 * j + 1]);
#pragma unroll
        for (int t = 0; t < 4; ++t) acc[t][j] = bi;
    }
    rb8_mainloop_sm(sH, lr0, (const ull*)sW2, cg * 4, acc);
#pragma unroll
    for (int t = 0; t < 4; ++t) {
        int r = r0 + t;
        float4 o[2];
#pragma unroll
        for (int q = 0; q < 2; ++q) {
            float2 v0 = upk(acc[t][2 * q]), v1 = upk(acc[t][2 * q + 1]);
            o[q] = make_float4(fmaxf(v0.x, 0.f), fmaxf(v0.y, 0.f),
                               fmaxf(v1.x, 0.f), fmaxf(v1.y, 0.f));
        }
        if (r < E) {
            float4* op = (float4*)(out + (size_t)r * 64 + c0);
            op[0] = o[0]; op[1] = o[1];
        }
        if (AEDGE) {
            float p[4] = {0.f, 0.f, 0.f, 0.f};
#pragma unroll
            for (int q = 0; q < 2; ++q) {
                const float* vv = sV + (c0 + 4 * q) * 4;
#pragma unroll
                for (int h = 0; h < 4; ++h)
                    p[h] += o[q].x * vv[h] + o[q].y * vv[4 + h] + o[q].z * vv[8 + h] + o[q].w * vv[12 + h];
            }
#pragma unroll
            for (int h = 0; h < 4; ++h) {
                p[h] += __shfl_xor_sync(0xffffffffu, p[h], 1);
                p[h] += __shfl_xor_sync(0xffffffffu, p[h], 2);
                p[h] += __shfl_xor_sync(0xffffffffu, p[h], 4);
            }
            if (r < E && cg < 4) aE[r * 4 + cg] = p[cg] + sV[256 + cg];
        }
    }
}

// -------- node update: conv = agg/den + b -> LN -> relu -> residual ----------
__global__ void __launch_bounds__(256) k_nodeup2(const float* __restrict__ agg,
        const float* __restrict__ den, const float* __restrict__ gatb,
        const float* __restrict__ lng, const float* __restrict__ lnb,
        float* __restrict__ node, int Nn) {
    int warp = blockIdx.x * 8 + (threadIdx.x >> 5);
    int lane = threadIdx.x & 31;
    if (warp >= Nn) return;
    float2 cv = ((const float2*)agg)[warp * 32 + lane];
    float dh = den[warp * 4 + (lane >> 3)] + 1e-16f;
    float inv = 1.f / dh;
    float2 gb = __ldg((const float2*)gatb + lane);
    cv.x = cv.x * inv + gb.x; cv.y = cv.y * inv + gb.y;
    float s = cv.x + cv.y, ss = cv.x * cv.x + cv.y * cv.y;
#pragma unroll
    for (int o = 16; o; o >>= 1) {
        s  += __shfl_xor_sync(0xffffffffu, s, o);
        ss += __shfl_xor_sync(0xffffffffu, ss, o);
    }
    float mu = s * (1.f / 64.f);
    float var = ss * (1.f / 64.f) - mu * mu;
    float r = rsqrtf(var + 1e-5f);
    float2 g = __ldg((const float2*)lng + lane), b = __ldg((const float2*)lnb + lane);
    float y0 = fmaxf((cv.x - mu) * r * g.x + b.x, 0.f);
    float y1 = fmaxf((cv.y - mu) * r * g.y + b.y, 0.f);
    float2* np = (float2*)node + warp * 32 + lane;
    float2 old = *np;
    *np = make_float2(old.x + y0, old.y + y1);
}

__global__ void k_copy(const float4* __restrict__ s, float4* __restrict__ d, int n4) {
    int i = blockIdx.x * blockDim.x + threadIdx.x;
    if (i < n4) d[i] = s[i];
}

// ---------------- launch ----------------
extern "C" void kernel_launch(void* const* d_in, const int* in_sizes, int n_in,
                              void* d_out, int out_size) {
    const int*   x     = (const int*)d_in[0];
    const int*   ea    = (const int*)d_in[1];
    const int*   ei    = (const int*)d_in[2];
    const float* atomT = (const float*)d_in[3];
    const float* bondT = (const float*)d_in[4];
    const float* gatW  = (const float*)d_in[5];
    const float* gatb  = (const float*)d_in[6];
    const float* attS  = (const float*)d_in[7];
    const float* attD  = (const float*)d_in[8];
    const float* attE  = (const float*)d_in[9];
    const float* epW   = (const float*)d_in[10];
    const float* epb   = (const float*)d_in[11];
    const float* lng   = (const float*)d_in[12];
    const float* lnb   = (const float*)d_in[13];
    const float* euW1  = (const float*)d_in[14];
    const float* eub1  = (const float*)d_in[15];
    const float* euW2  = (const float*)d_in[16];
    const float* eub2  = (const float*)d_in[17];

    int N = in_sizes[0] / 9;
    int E = in_sizes[1] / 3;
    const int* src  = ei;
    const int* dstp = ei + E;
    float* out = (float*)d_out;

    float *node, *xh, *P, *Q, *agg, *asrc, *adst, *den, *edge, *v, *aE;
    int *deg, *off, *cur, *bsum;
    int2* pay;
    cudaGetSymbolAddress((void**)&node, g_node);
    cudaGetSymbolAddress((void**)&xh,   g_xh);
    cudaGetSymbolAddress((void**)&P,    g_P);
    cudaGetSymbolAddress((void**)&Q,    g_Q);
    cudaGetSymbolAddress((void**)&agg,  g_agg);
    cudaGetSymbolAddress((void**)&asrc, g_asrc);
    cudaGetSymbolAddress((void**)&adst, g_adst);
    cudaGetSymbolAddress((void**)&den,  g_den);
    cudaGetSymbolAddress((void**)&edge, g_edge);
    cudaGetSymbolAddress((void**)&v,    g_v);
    cudaGetSymbolAddress((void**)&aE,   g_aE);
    cudaGetSymbolAddress((void**)&deg,  g_deg);
    cudaGetSymbolAddress((void**)&off,  g_off);
    cudaGetSymbolAddress((void**)&cur,  g_cur);
    cudaGetSymbolAddress((void**)&bsum, g_bsum);
    cudaGetSymbolAddress((void**)&pay,  g_pay);

    const int EU_SMEM = (8580 + 128 * 68) * 4;
    cudaFuncSetAttribute(k_eu_fused<0>, cudaFuncAttributeMaxDynamicSharedMemorySize, EU_SMEM);
    cudaFuncSetAttribute(k_eu_fused<1>, cudaFuncAttributeMaxDynamicSharedMemorySize, EU_SMEM);

    int nbN = (N + 255) / 256;
    int nbE = (E + 255) / 256;

    // CSR build (once per call)
    k_zero<<<nbN, 256>>>(deg, N);
    k_hist<<<nbE, 256>>>(dstp, deg, E);
    k_scan1<<<nbN, 256>>>(deg, bsum, N);
    k_scan2<<<1, 512>>>(bsum, nbN);
    k_scan3<<<nbN, 256>>>(deg, bsum, off, cur, N);
    k_scatter<<<nbE, 256>>>(src, dstp, cur, pay, E);

    k_prep<<<4, 256>>>(epW, epb, attE, v);
    k_node_enc<<<(N * 64 + 255) / 256, 256>>>(x, atomT, node, N);
    k_edge_enc2<<<(E + 7) / 8, 256>>>(ea, bondT, v, edge, (float4*)aE, E);

    int gN = (N + 127) / 128;
    int gE = (E + 127) / 128;
    int gW = (N + 7) / 8;

    for (int l = 0; l < 4; ++l) {
        k_xh_rb<<<gN, 256>>>(node, gatW + l * 4096, attS + l * 64, attD + l * 64,
                             xh, asrc, adst, N);
        k_attn<<<gW, 256>>>(off, deg, pay, asrc, adst, aE, xh, agg, den, N);
        k_nodeup2<<<gW, 256>>>(agg, den, gatb + l * 64, lng + l * 64, lnb + l * 64, node, N);
        k_pq<<<gN, 256>>>(node, euW1 + l * 12288, euW1 + l * 12288 + 4096, P, Q, N);
        if (l < 3) {
            k_eu_fused<1><<<gE, 256, EU_SMEM>>>(edge, P, Q, src, dstp,
                    euW1 + l * 12288 + 8192, eub1 + l * 64,
                    euW2 + l * 4096, eub2 + l * 64,
                    edge, v + (l + 1) * 260, aE, E);
        } else {
            k_eu_fused<0><<<gE, 256, EU_SMEM>>>(edge, P, Q, src, dstp,
                    euW1 + l * 12288 + 8192, eub1 + l * 64,
                    euW2 + l * 4096, eub2 + l * 64,
                    out + (size_t)N * 64, nullptr, nullptr, E);
        }
    }

    k_copy<<<(N * 16 + 255) / 256, 256>>>((const float4*)node, (float4*)out, N * 16);
}

// round 6
// speedup vs baseline: 1.4440x; 1.0638x over previous
#include <cuda_runtime.h>
#include <math.h>

#define D 64
#define NMAX 100000
#define EMAX 1200000

typedef unsigned long long ull;

// ---------------- scratch (device globals; no allocation allowed) ----------------
__device__ float g_node[NMAX * D];
__device__ float g_xh[NMAX * D];
__device__ float g_P[NMAX * D];
__device__ float g_Q[NMAX * D];
__device__ float g_asrc[NMAX * 4];
__device__ float g_adst[NMAX * 4];
__device__ float g_edge[EMAX * D];
__device__ float g_aE[EMAX * 4];
__device__ float g_v[4 * 260];
// CSR scratch
__device__ int  g_deg[NMAX];
__device__ int  g_off[NMAX];
__device__ int  g_cur[NMAX];
__device__ int  g_bsum[512];
__device__ int2 g_pay[EMAX];

// ---------------- f32x2 helpers ----------------
__device__ __forceinline__ ull pk2(float x, float y) {
    ull r; asm("mov.b64 %0,{%1,%2};" : "=l"(r) : "f"(x), "f"(y)); return r;
}
__device__ __forceinline__ float2 upk(ull a) {
    float2 r; asm("mov.b64 {%0,%1},%2;" : "=f"(r.x), "=f"(r.y) : "l"(a)); return r;
}
__device__ __forceinline__ ull f2fma(ull a, ull b, ull c) {
    ull d; asm("fma.rn.f32x2 %0,%1,%2,%3;" : "=l"(d) : "l"(a), "l"(b), "l"(c)); return d;
}

// ============ register-blocked mainloops: 4 rows x 8 cols per thread =========
// smem weights
__device__ __forceinline__ void rb8_mainloop(const float* __restrict__ in,
        int r0, int M, const ull* __restrict__ sWu, int cg4, ull acc[4][4]) {
    const float4* in4 = (const float4*)in;
    int ri[4];
#pragma unroll
    for (int t = 0; t < 4; ++t) { int rr = r0 + t; ri[t] = (rr < M ? rr : M - 1) * 16; }
#pragma unroll 4
    for (int k4 = 0; k4 < 16; ++k4) {
        float4 a[4];
#pragma unroll
        for (int t = 0; t < 4; ++t) a[t] = in4[ri[t] + k4];
        const ull* wb = sWu + k4 * 128 + cg4;
#pragma unroll
        for (int kk = 0; kk < 4; ++kk) {
            ull wv[4];
            const ull* w = wb + kk * 32;
#pragma unroll
            for (int j = 0; j < 4; ++j) wv[j] = w[j];
#pragma unroll
            for (int t = 0; t < 4; ++t) {
                float av = (kk == 0) ? a[t].x : (kk == 1) ? a[t].y : (kk == 2) ? a[t].z : a[t].w;
                ull a2 = pk2(av, av);
#pragma unroll
                for (int j = 0; j < 4; ++j) acc[t][j] = f2fma(a2, wv[j], acc[t][j]);
            }
        }
    }
}

// global (L1-cached, broadcast) weights, global input
__device__ __forceinline__ void rb8_mainloop_gw(const float* __restrict__ in,
        int r0, int M, const ull* __restrict__ Wg, int cg2, ull acc[4][4]) {
    const float4* in4 = (const float4*)in;
    const ulonglong2* Wg2 = (const ulonglong2*)Wg;
    int ri[4];
#pragma unroll
    for (int t = 0; t < 4; ++t) { int rr = r0 + t; ri[t] = (rr < M ? rr : M - 1) * 16; }
#pragma unroll 4
    for (int k4 = 0; k4 < 16; ++k4) {
        float4 a[4];
#pragma unroll
        for (int t = 0; t < 4; ++t) a[t] = in4[ri[t] + k4];
        const ulonglong2* wb = Wg2 + k4 * 64 + cg2;
#pragma unroll
        for (int kk = 0; kk < 4; ++kk) {
            ulonglong2 w0 = __ldg(wb + kk * 16);
            ulonglong2 w1 = __ldg(wb + kk * 16 + 1);
            ull wv[4] = {w0.x, w0.y, w1.x, w1.y};
#pragma unroll
            for (int t = 0; t < 4; ++t) {
                float av = (kk == 0) ? a[t].x : (kk == 1) ? a[t].y : (kk == 2) ? a[t].z : a[t].w;
                ull a2 = pk2(av, av);
#pragma unroll
                for (int j = 0; j < 4; ++j) acc[t][j] = f2fma(a2, wv[j], acc[t][j]);
            }
        }
    }
}

// global weights, smem input (row stride 68 floats)
__device__ __forceinline__ void rb8_mainloop_sm_gw(const float* __restrict__ sH,
        int lr0, const ull* __restrict__ Wg, int cg2, ull acc[4][4]) {
    const ulonglong2* Wg2 = (const ulonglong2*)Wg;
#pragma unroll 4
    for (int k4 = 0; k4 < 16; ++k4) {
        float4 a[4];
#pragma unroll
        for (int t = 0; t < 4; ++t) a[t] = *(const float4*)(sH + (lr0 + t) * 68 + k4 * 4);
        const ulonglong2* wb = Wg2 + k4 * 64 + cg2;
#pragma unroll
        for (int kk = 0; kk < 4; ++kk) {
            ulonglong2 w0 = __ldg(wb + kk * 16);
            ulonglong2 w1 = __ldg(wb + kk * 16 + 1);
            ull wv[4] = {w0.x, w0.y, w1.x, w1.y};
#pragma unroll
            for (int t = 0; t < 4; ++t) {
                float av = (kk == 0) ? a[t].x : (kk == 1) ? a[t].y : (kk == 2) ? a[t].z : a[t].w;
                ull a2 = pk2(av, av);
#pragma unroll
                for (int j = 0; j < 4; ++j) acc[t][j] = f2fma(a2, wv[j], acc[t][j]);
            }
        }
    }
}

// ---------------- CSR build ----------------
__global__ void k_zero(int* __restrict__ a, int n) {
    int i = blockIdx.x * blockDim.x + threadIdx.x;
    if (i < n) a[i] = 0;
}
__global__ void k_hist(const int* __restrict__ dst, int* __restrict__ deg, int E) {
    int e = blockIdx.x * blockDim.x + threadIdx.x;
    if (e < E) atomicAdd(&deg[dst[e]], 1);
}
__global__ void k_scan1(const int* __restrict__ deg, int* __restrict__ bsum, int Nn) {
    __shared__ int s[256];
    int i = blockIdx.x * 256 + threadIdx.x;
    s[threadIdx.x] = (i < Nn) ? deg[i] : 0;
    __syncthreads();
    for (int o = 128; o; o >>= 1) {
        if (threadIdx.x < o) s[threadIdx.x] += s[threadIdx.x + o];
        __syncthreads();
    }
    if (threadIdx.x == 0) bsum[blockIdx.x] = s[0];
}
__global__ void k_scan2(int* __restrict__ bsum, int nb) {
    __shared__ int s[512];
    int t = threadIdx.x;
    int v = (t < nb) ? bsum[t] : 0;
    s[t] = v;
    __syncthreads();
    for (int o = 1; o < 512; o <<= 1) {
        int x = (t >= o) ? s[t - o] : 0;
        __syncthreads();
        s[t] += x;
        __syncthreads();
    }
    if (t < nb) bsum[t] = s[t] - v;  // exclusive
}
__global__ void k_scan3(const int* __restrict__ deg, const int* __restrict__ bsum,
                        int* __restrict__ off, int* __restrict__ cur, int Nn) {
    __shared__ int s[256];
    int i = blockIdx.x * 256 + threadIdx.x;
    int t = threadIdx.x;
    int v = (i < Nn) ? deg[i] : 0;
    s[t] = v;
    __syncthreads();
    for (int o = 1; o < 256; o <<= 1) {
        int x = (t >= o) ? s[t - o] : 0;
        __syncthreads();
        s[t] += x;
        __syncthreads();
    }
    if (i < Nn) {
        int excl = s[t] - v + bsum[blockIdx.x];
        off[i] = excl;
        cur[i] = excl;
    }
}
__global__ void k_scatter(const int* __restrict__ src, const int* __restrict__ dst,
                          int* __restrict__ cur, int2* __restrict__ pay, int E) {
    int e = blockIdx.x * blockDim.x + threadIdx.x;
    if (e >= E) return;
    int p = atomicAdd(&cur[dst[e]], 1);
    pay[p] = make_int2(src[e], e);
}

// ---------------- encoders ----------------
__global__ void k_node_enc(const int* __restrict__ x, const float* __restrict__ at,
                           float* __restrict__ node, int Nn) {
    int t = blockIdx.x * blockDim.x + threadIdx.x;
    if (t >= Nn * D) return;
    int i = t >> 6, j = t & 63;
    const int* xi = x + i * 9;
    float s = 0.f;
#pragma unroll
    for (int f = 0; f < 9; ++f) { int v = xi[f]; s += at[(f * 16 + v) * 64 + j]; }
    node[t] = s;
}

__global__ void __launch_bounds__(256) k_edge_enc2(const int* __restrict__ ea,
        const float* __restrict__ bt, const float* __restrict__ v0,
        float* __restrict__ edge, float4* __restrict__ aE4, int E) {
    int e = blockIdx.x * 8 + (threadIdx.x >> 5);
    int lane = threadIdx.x & 31;
    if (e >= E) return;
    int f0 = ea[e * 3], f1 = ea[e * 3 + 1], f2 = ea[e * 3 + 2];
    int c0 = 2 * lane, c1 = c0 + 1;
    float s0 = bt[f0 * 64 + c0] + bt[(8 + f1) * 64 + c0] + bt[(16 + f2) * 64 + c0];
    float s1 = bt[f0 * 64 + c1] + bt[(8 + f1) * 64 + c1] + bt[(16 + f2) * 64 + c1];
    ((float2*)(edge + e * 64))[lane] = make_float2(s0, s1);
    float p[4];
#pragma unroll
    for (int h = 0; h < 4; ++h) p[h] = s0 * v0[c0 * 4 + h] + s1 * v0[c1 * 4 + h];
#pragma unroll
    for (int o = 16; o; o >>= 1) {
#pragma unroll
        for (int h = 0; h < 4; ++h) p[h] += __shfl_xor_sync(0xffffffffu, p[h], o);
    }
    if (lane == 0)
        aE4[e] = make_float4(p[0] + v0[256], p[1] + v0[257], p[2] + v0[258], p[3] + v0[259]);
}

// ---------------- per-layer prep ----------------
__global__ void k_prep(const float* __restrict__ epW, const float* __restrict__ epb,
                       const float* __restrict__ attE, float* __restrict__ vall) {
    int l = blockIdx.x;
    const float* W = epW + l * 4096;
    const float* b = epb + l * 64;
    const float* aEv = attE + l * 64;
    float* vout = vall + l * 260;
    int t = threadIdx.x;
    if (t < 256) {
        int k = t >> 2, h = t & 3;
        float s = 0.f;
#pragma unroll
        for (int c = 0; c < 16; ++c) s += W[k * 64 + h * 16 + c] * aEv[h * 16 + c];
        vout[k * 4 + h] = s;
    }
    if (t < 4) {
        float s = 0.f;
#pragma unroll
        for (int c = 0; c < 16; ++c) s += b[t * 16 + c] * aEv[t * 16 + c];
        vout[256 + t] = s;
    }
}

// ---------------- xh = node @ W + a_src/a_dst --------------------------------
__global__ void __launch_bounds__(256, 2) k_xh_rb(const float* __restrict__ node,
        const float* __restrict__ W, const float* __restrict__ attS,
        const float* __restrict__ attD, float* __restrict__ xh,
        float* __restrict__ asrc, float* __restrict__ adst, int M) {
    __shared__ __align__(16) float sW[4096];
    __shared__ float sAS[64], sAD[64];
    for (int i = threadIdx.x; i < 4096; i += 256) sW[i] = W[i];
    if (threadIdx.x < 64) { sAS[threadIdx.x] = attS[threadIdx.x]; sAD[threadIdx.x] = attD[threadIdx.x]; }
    __syncthreads();
    int cg = threadIdx.x & 7, tq = threadIdx.x >> 3;
    int r0 = blockIdx.x * 128 + tq * 4;
    if (r0 >= M) return;
    ull acc[4][4];
#pragma unroll
    for (int t = 0; t < 4; ++t)
#pragma unroll
        for (int j = 0; j < 4; ++j) acc[t][j] = 0ull;
    rb8_mainloop(node, r0, M, (const ull*)sW, cg * 4, acc);
    int c0 = cg * 8;
#pragma unroll
    for (int t = 0; t < 4; ++t) {
        int r = r0 + t;
        float as = 0.f, ad = 0.f;
        float4 o[2];
#pragma unroll
        for (int q = 0; q < 2; ++q) {
            float2 v0 = upk(acc[t][2 * q]), v1 = upk(acc[t][2 * q + 1]);
            o[q] = make_float4(v0.x, v0.y, v1.x, v1.y);
            int c = c0 + 4 * q;
            as += v0.x * sAS[c] + v0.y * sAS[c + 1] + v1.x * sAS[c + 2] + v1.y * sAS[c + 3];
            ad += v0.x * sAD[c] + v0.y * sAD[c + 1] + v1.x * sAD[c + 2] + v1.y * sAD[c + 3];
        }
        as += __shfl_xor_sync(0xffffffffu, as, 1);
        ad += __shfl_xor_sync(0xffffffffu, ad, 1);
        if (r < M) {
            float4* xp = (float4*)(xh + (size_t)r * 64 + c0);
            xp[0] = o[0]; xp[1] = o[1];
            if ((cg & 1) == 0) {
                int h = cg >> 1;
                asrc[r * 4 + h] = as;
                adst[r * 4 + h] = ad;
            }
        }
    }
}

// --- CSR attention (online softmax) fused with LN/relu/residual node update ---
__global__ void __launch_bounds__(256) k_attn_fused(const int* __restrict__ off,
        const int* __restrict__ deg, const int2* __restrict__ pay,
        const float* __restrict__ asrc, const float* __restrict__ adst,
        const float* __restrict__ aE, const float* __restrict__ xh,
        const float* __restrict__ gatb, const float* __restrict__ lng,
        const float* __restrict__ lnb, float* __restrict__ node, int Nn) {
    int w = blockIdx.x * 8 + (threadIdx.x >> 5);
    int l = threadIdx.x & 31;
    if (w >= Nn) return;
    int beg = off[w], dg = deg[w];
    int h = l >> 3;
    float ad = adst[w * 4 + h];
    float mh = __int_as_float(0xff800000);
    float dh = 0.f;
    float2 acc = make_float2(0.f, 0.f);
    for (int i = 0; i < dg; ++i) {
        int2 p = pay[beg + i];
        float a = asrc[p.x * 4 + h] + ad + aE[p.y * 4 + h];
        a = a > 0.f ? a : 0.2f * a;
        float2 xv = ((const float2*)xh)[p.x * 32 + l];
        float mn = fmaxf(mh, a);
        float s = expf(mh - mn);   // 0 when mh == -inf
        float e = expf(a - mn);
        dh = dh * s + e;
        acc.x = acc.x * s + e * xv.x;
        acc.y = acc.y * s + e * xv.y;
        mh = mn;
    }
    float inv = 1.f / (dh + 1e-16f);
    float2 gb = __ldg((const float2*)gatb + l);
    float cvx = acc.x * inv + gb.x;
    float cvy = acc.y * inv + gb.y;
    float s = cvx + cvy, ss = cvx * cvx + cvy * cvy;
#pragma unroll
    for (int o = 16; o; o >>= 1) {
        s  += __shfl_xor_sync(0xffffffffu, s, o);
        ss += __shfl_xor_sync(0xffffffffu, ss, o);
    }
    float mu = s * (1.f / 64.f);
    float var = ss * (1.f / 64.f) - mu * mu;
    float r = rsqrtf(var + 1e-5f);
    float2 g = __ldg((const float2*)lng + l), b = __ldg((const float2*)lnb + l);
    float y0 = fmaxf((cvx - mu) * r * g.x + b.x, 0.f);
    float y1 = fmaxf((cvy - mu) * r * g.y + b.y, 0.f);
    float2* np = (float2*)node + w * 32 + l;
    float2 old = *np;
    *np = make_float2(old.x + y0, old.y + y1);
}

// ---------------- fused P+Q ----------------
__global__ void __launch_bounds__(256, 2) k_pq(const float* __restrict__ node,
        const float* __restrict__ Wa, const float* __restrict__ Wb,
        float* __restrict__ P, float* __restrict__ Q, int M) {
    __shared__ __align__(16) float sWa[4096];
    __shared__ __align__(16) float sWb[4096];
    for (int i = threadIdx.x; i < 4096; i += 256) { sWa[i] = Wa[i]; sWb[i] = Wb[i]; }
    __syncthreads();
    int cg = threadIdx.x & 7, tq = threadIdx.x >> 3;
    int r0 = blockIdx.x * 128 + tq * 4;
    if (r0 >= M) return;
    int c0 = cg * 8;
    ull acc[4][4];
#pragma unroll
    for (int t = 0; t < 4; ++t)
#pragma unroll
        for (int j = 0; j < 4; ++j) acc[t][j] = 0ull;
    rb8_mainloop(node, r0, M, (const ull*)sWa, cg * 4, acc);
#pragma unroll
    for (int t = 0; t < 4; ++t) {
        int r = r0 + t;
        if (r < M) {
            float4* op = (float4*)(P + (size_t)r * 64 + c0);
            float2 v0 = upk(acc[t][0]), v1 = upk(acc[t][1]);
            op[0] = make_float4(v0.x, v0.y, v1.x, v1.y);
            v0 = upk(acc[t][2]); v1 = upk(acc[t][3]);
            op[1] = make_float4(v0.x, v0.y, v1.x, v1.y);
        }
    }
#pragma unroll
    for (int t = 0; t < 4; ++t)
#pragma unroll
        for (int j = 0; j < 4; ++j) acc[t][j] = 0ull;
    rb8_mainloop(node, r0, M, (const ull*)sWb, cg * 4, acc);
#pragma unroll
    for (int t = 0; t < 4; ++t) {
        int r = r0 + t;
        if (r < M) {
            float4* op = (float4*)(Q + (size_t)r * 64 + c0);
            float2 v0 = upk(acc[t][0]), v1 = upk(acc[t][1]);
            op[0] = make_float4(v0.x, v0.y, v1.x, v1.y);
            v0 = upk(acc[t][2]); v1 = upk(acc[t][3]);
            op[1] = make_float4(v0.x, v0.y, v1.x, v1.y);
        }
    }
}

// ---------------- fused edge update (weights via L1-cached global) -----------
// dyn smem: sB[128] sV[260] sH[128*68]
template <int AEDGE>
__global__ void __launch_bounds__(256) k_eu_fused(const float* __restrict__ edge,
        const float* __restrict__ P, const float* __restrict__ Q,
        const int* __restrict__ src, const int* __restrict__ dst,
        const float* __restrict__ W1c, const float* __restrict__ b1,
        const float* __restrict__ W2, const float* __restrict__ b2,
        float* __restrict__ out, const float* __restrict__ vE,
        float* __restrict__ aE, int E) {
    extern __shared__ float sm[];
    float* sB = sm;
    float* sV = sm + 128;
    float* sH = sm + 388;
    if (threadIdx.x < 64) sB[threadIdx.x] = b1[threadIdx.x];
    else if (threadIdx.x < 128) sB[threadIdx.x] = b2[threadIdx.x - 64];
    if (AEDGE) { for (int i = threadIdx.x; i < 260; i += 256) sV[i] = vE[i]; }
    __syncthreads();
    int cg = threadIdx.x & 7, tq = threadIdx.x >> 3;
    int r0 = blockIdx.x * 128 + tq * 4;
    int c0 = cg * 8;
    int lr0 = tq * 4;
    int ss[4], dd[4];
#pragma unroll
    for (int t = 0; t < 4; ++t) {
        int r = r0 + t; if (r >= E) r = E - 1;
        ss[t] = src[r]; dd[t] = dst[r];
    }
    ull acc[4][4];
#pragma unroll
    for (int t = 0; t < 4; ++t) {
        const float4* Pp = (const float4*)(P + (size_t)ss[t] * 64 + c0);
        const float4* Qp = (const float4*)(Q + (size_t)dd[t] * 64 + c0);
#pragma unroll
        for (int q = 0; q < 2; ++q) {
            float4 pv = Pp[q], qv = Qp[q];
            const float* b = sB + c0 + 4 * q;
            acc[t][2 * q]     = pk2(pv.x + qv.x + b[0], pv.y + qv.y + b[1]);
            acc[t][2 * q + 1] = pk2(pv.z + qv.z + b[2], pv.w + qv.w + b[3]);
        }
    }
    rb8_mainloop_gw(edge, r0, E, (const ull*)W1c, cg * 2, acc);
#pragma unroll
    for (int t = 0; t < 4; ++t) {
        float* hp = sH + (lr0 + t) * 68 + c0;
#pragma unroll
        for (int q = 0; q < 2; ++q) {
            float2 v0 = upk(acc[t][2 * q]), v1 = upk(acc[t][2 * q + 1]);
            *(float4*)(hp + 4 * q) = make_float4(fmaxf(v0.x, 0.f), fmaxf(v0.y, 0.f),
                                                 fmaxf(v1.x, 0.f), fmaxf(v1.y, 0.f));
        }
    }
    __syncthreads();
#pragma unroll
    for (int j = 0; j < 4; ++j) {
        ull bi = pk2(sB[64 + c0 + 2 * j], sB[64 + c0 + 2 * j + 1]);
#pragma unroll
        for (int t = 0; t < 4; ++t) acc[t][j] = bi;
    }
    rb8_mainloop_sm_gw(sH, lr0, (const ull*)W2, cg * 2, acc);
#pragma unroll
    for (int t = 0; t < 4; ++t) {
        int r = r0 + t;
        float4 o[2];
#pragma unroll
        for (int q = 0; q < 2; ++q) {
            float2 v0 = upk(acc[t][2 * q]), v1 = upk(acc[t][2 * q + 1]);
            o[q] = make_float4(fmaxf(v0.x, 0.f), fmaxf(v0.y, 0.f),
                               fmaxf(v1.x, 0.f), fmaxf(v1.y, 0.f));
        }
        if (r < E) {
            float4* op = (float4*)(out + (size_t)r * 64 + c0);
            op[0] = o[0]; op[1] = o[1];
        }
        if (AEDGE) {
            float p[4] = {0.f, 0.f, 0.f, 0.f};
#pragma unroll
            for (int q = 0; q < 2; ++q) {
                const float* vv = sV + (c0 + 4 * q) * 4;
#pragma unroll
                for (int h = 0; h < 4; ++h)
                    p[h] += o[q].x * vv[h] + o[q].y * vv[4 + h] + o[q].z * vv[8 + h] + o[q].w * vv[12 + h];
            }
#pragma unroll
            for (int h = 0; h < 4; ++h) {
                p[h] += __shfl_xor_sync(0xffffffffu, p[h], 1);
                p[h] += __shfl_xor_sync(0xffffffffu, p[h], 2);
                p[h] += __shfl_xor_sync(0xffffffffu, p[h], 4);
            }
            if (r < E && cg < 4) aE[r * 4 + cg] = p[cg] + sV[256 + cg];
        }
    }
}

__global__ void k_copy(const float4* __restrict__ s, float4* __restrict__ d, int n4) {
    int i = blockIdx.x * blockDim.x + threadIdx.x;
    if (i < n4) d[i] = s[i];
}

// ---------------- launch ----------------
extern "C" void kernel_launch(void* const* d_in, const int* in_sizes, int n_in,
                              void* d_out, int out_size) {
    const int*   x     = (const int*)d_in[0];
    const int*   ea    = (const int*)d_in[1];
    const int*   ei    = (const int*)d_in[2];
    const float* atomT = (const float*)d_in[3];
    const float* bondT = (const float*)d_in[4];
    const float* gatW  = (const float*)d_in[5];
    const float* gatb  = (const float*)d_in[6];
    const float* attS  = (const float*)d_in[7];
    const float* attD  = (const float*)d_in[8];
    const float* attE  = (const float*)d_in[9];
    const float* epW   = (const float*)d_in[10];
    const float* epb   = (const float*)d_in[11];
    const float* lng   = (const float*)d_in[12];
    const float* lnb   = (const float*)d_in[13];
    const float* euW1  = (const float*)d_in[14];
    const float* eub1  = (const float*)d_in[15];
    const float* euW2  = (const float*)d_in[16];
    const float* eub2  = (const float*)d_in[17];

    int N = in_sizes[0] / 9;
    int E = in_sizes[1] / 3;
    const int* src  = ei;
    const int* dstp = ei + E;
    float* out = (float*)d_out;

    float *node, *xh, *P, *Q, *asrc, *adst, *edge, *v, *aE;
    int *deg, *off, *cur, *bsum;
    int2* pay;
    cudaGetSymbolAddress((void**)&node, g_node);
    cudaGetSymbolAddress((void**)&xh,   g_xh);
    cudaGetSymbolAddress((void**)&P,    g_P);
    cudaGetSymbolAddress((void**)&Q,    g_Q);
    cudaGetSymbolAddress((void**)&asrc, g_asrc);
    cudaGetSymbolAddress((void**)&adst, g_adst);
    cudaGetSymbolAddress((void**)&edge, g_edge);
    cudaGetSymbolAddress((void**)&v,    g_v);
    cudaGetSymbolAddress((void**)&aE,   g_aE);
    cudaGetSymbolAddress((void**)&deg,  g_deg);
    cudaGetSymbolAddress((void**)&off,  g_off);
    cudaGetSymbolAddress((void**)&cur,  g_cur);
    cudaGetSymbolAddress((void**)&bsum, g_bsum);
    cudaGetSymbolAddress((void**)&pay,  g_pay);

    const int EU_SMEM = (388 + 128 * 68) * 4;  // 36368 bytes
    cudaFuncSetAttribute(k_eu_fused<0>, cudaFuncAttributeMaxDynamicSharedMemorySize, EU_SMEM);
    cudaFuncSetAttribute(k_eu_fused<1>, cudaFuncAttributeMaxDynamicSharedMemorySize, EU_SMEM);

    int nbN = (N + 255) / 256;
    int nbE = (E + 255) / 256;

    // CSR build (once per call)
    k_zero<<<nbN, 256>>>(deg, N);
    k_hist<<<nbE, 256>>>(dstp, deg, E);
    k_scan1<<<nbN, 256>>>(deg, bsum, N);
    k_scan2<<<1, 512>>>(bsum, nbN);
    k_scan3<<<nbN, 256>>>(deg, bsum, off, cur, N);
    k_scatter<<<nbE, 256>>>(src, dstp, cur, pay, E);

    k_prep<<<4, 256>>>(epW, epb, attE, v);
    k_node_enc<<<(N * 64 + 255) / 256, 256>>>(x, atomT, node, N);
    k_edge_enc2<<<(E + 7) / 8, 256>>>(ea, bondT, v, edge, (float4*)aE, E);

    int gN = (N + 127) / 128;
    int gE = (E + 127) / 128;
    int gW = (N + 7) / 8;

    for (int l = 0; l < 4; ++l) {
        k_xh_rb<<<gN, 256>>>(node, gatW + l * 4096, attS + l * 64, attD + l * 64,
                             xh, asrc, adst, N);
        k_attn_fused<<<gW, 256>>>(off, deg, pay, asrc, adst, aE, xh,
                                  gatb + l * 64, lng + l * 64, lnb + l * 64, node, N);
        k_pq<<<gN, 256>>>(node, euW1 + l * 12288, euW1 + l * 12288 + 4096, P, Q, N);
        if (l < 3) {
            k_eu_fused<1><<<gE, 256, EU_SMEM>>>(edge, P, Q, src, dstp,
                    euW1 + l * 12288 + 8192, eub1 + l * 64,
                    euW2 + l * 4096, eub2 + l * 64,
                    edge, v + (l + 1) * 260, aE, E);
        } else {
            k_eu_fused<0><<<gE, 256, EU_SMEM>>>(edge, P, Q, src, dstp,
                    euW1 + l * 12288 + 8192, eub1 + l * 64,
                    euW2 + l * 4096, eub2 + l * 64,
                    out + (size_t)N * 64, nullptr, nullptr, E);
        }
    }

    k_copy<<<(N * 16 + 255) / 256, 256>>>((const float4*)node, (float4*)out, N * 16);
}

// round 9
// speedup vs baseline: 2.0943x; 1.4503x over previous
#include <cuda_runtime.h>
#include <cuda_bf16.h>
#include <cstdint>
#include <math.h>

#define D 64
#define NMAX 100000
#define EMAX 1200000

typedef unsigned long long ull;

// ---------------- scratch (device globals; no allocation allowed) ----------------
__device__ float g_node[NMAX * D];
__device__ float g_xh[NMAX * D];
__device__ float g_P[NMAX * D];
__device__ float g_Q[NMAX * D];
__device__ float g_asrc[NMAX * 4];
__device__ float g_adst[NMAX * 4];
__device__ float g_edge[EMAX * D];
__device__ float g_aE[EMAX * 4];
__device__ float g_v[4 * 260];
// per layer: W1hi, W1lo, W2hi, W2lo, each [n=64][k=64] bf16 (transposed)
__device__ __align__(16) __nv_bfloat16 g_weu[4 * 4 * 4096];
// CSR scratch
__device__ int  g_deg[NMAX];
__device__ int  g_off[NMAX];
__device__ int  g_cur[NMAX];
__device__ int  g_bsum[512];
__device__ int2 g_pay[EMAX];

// ---------------- f32x2 helpers ----------------
__device__ __forceinline__ ull pk2(float x, float y) {
    ull r; asm("mov.b64 %0,{%1,%2};" : "=l"(r) : "f"(x), "f"(y)); return r;
}
__device__ __forceinline__ float2 upk(ull a) {
    float2 r; asm("mov.b64 {%0,%1},%2;" : "=f"(r.x), "=f"(r.y) : "l"(a)); return r;
}
__device__ __forceinline__ ull f2fma(ull a, ull b, ull c) {
    ull d; asm("fma.rn.f32x2 %0,%1,%2,%3;" : "=l"(d) : "l"(a), "l"(b), "l"(c)); return d;
}

// ---------------- HMMA: m16n8k16 row.col f32.bf16.bf16.f32 -------------------
#define MMA16816(dd, aa, b0, b1) \
    asm volatile("mma.sync.aligned.m16n8k16.row.col.f32.bf16.bf16.f32 " \
        "{%0,%1,%2,%3},{%4,%5,%6,%7},{%8,%9},{%0,%1,%2,%3};" \
        : "+f"((dd)[0]), "+f"((dd)[1]), "+f"((dd)[2]), "+f"((dd)[3]) \
        : "r"((aa)[0]), "r"((aa)[1]), "r"((aa)[2]), "r"((aa)[3]), "r"(b0), "r"(b1))

// bf16 hi/lo split of 8 consecutive floats into two uint4 (8 bf16 each)
__device__ __forceinline__ void cvt8(const float4 v0, const float4 v1, uint4& hi, uint4& lo) {
    __nv_bfloat162 h0 = __floats2bfloat162_rn(v0.x, v0.y);
    __nv_bfloat162 h1 = __floats2bfloat162_rn(v0.z, v0.w);
    __nv_bfloat162 h2 = __floats2bfloat162_rn(v1.x, v1.y);
    __nv_bfloat162 h3 = __floats2bfloat162_rn(v1.z, v1.w);
    float2 f0 = __bfloat1622float2(h0), f1 = __bfloat1622float2(h1);
    float2 f2 = __bfloat1622float2(h2), f3 = __bfloat1622float2(h3);
    __nv_bfloat162 l0 = __floats2bfloat162_rn(v0.x - f0.x, v0.y - f0.y);
    __nv_bfloat162 l1 = __floats2bfloat162_rn(v0.z - f1.x, v0.w - f1.y);
    __nv_bfloat162 l2 = __floats2bfloat162_rn(v1.x - f2.x, v1.y - f2.y);
    __nv_bfloat162 l3 = __floats2bfloat162_rn(v1.z - f3.x, v1.w - f3.y);
    hi = make_uint4(*(uint32_t*)&h0, *(uint32_t*)&h1, *(uint32_t*)&h2, *(uint32_t*)&h3);
    lo = make_uint4(*(uint32_t*)&l0, *(uint32_t*)&l1, *(uint32_t*)&l2, *(uint32_t*)&l3);
}
// split 2 floats -> hi pair + lo pair (each one uint32 = 2 bf16)
__device__ __forceinline__ void cvt2(float x, float y, uint32_t& hi, uint32_t& lo) {
    __nv_bfloat162 h = __floats2bfloat162_rn(x, y);
    float2 f = __bfloat1622float2(h);
    __nv_bfloat162 l = __floats2bfloat162_rn(x - f.x, y - f.y);
    hi = *(uint32_t*)&h; lo = *(uint32_t*)&l;
}

// ============ register-blocked FFMA mainloop (kept for N-row GEMMs) ==========
__device__ __forceinline__ void rb8_mainloop(const float* __restrict__ in,
        int r0, int M, const ull* __restrict__ sWu, int cg4, ull acc[4][4]) {
    const float4* in4 = (const float4*)in;
    int ri[4];
#pragma unroll
    for (int t = 0; t < 4; ++t) { int rr = r0 + t; ri[t] = (rr < M ? rr : M - 1) * 16; }
#pragma unroll 4
    for (int k4 = 0; k4 < 16; ++k4) {
        float4 a[4];
#pragma unroll
        for (int t = 0; t < 4; ++t) a[t] = in4[ri[t] + k4];
        const ull* wb = sWu + k4 * 128 + cg4;
#pragma unroll
        for (int kk = 0; kk < 4; ++kk) {
            ull wv[4];
            const ull* w = wb + kk * 32;
#pragma unroll
            for (int j = 0; j < 4; ++j) wv[j] = w[j];
#pragma unroll
            for (int t = 0; t < 4; ++t) {
                float av = (kk == 0) ? a[t].x : (kk == 1) ? a[t].y : (kk == 2) ? a[t].z : a[t].w;
                ull a2 = pk2(av, av);
#pragma unroll
                for (int j = 0; j < 4; ++j) acc[t][j] = f2fma(a2, wv[j], acc[t][j]);
            }
        }
    }
}

// ---------------- CSR build ----------------
__global__ void k_zero(int* __restrict__ a, int n) {
    int i = blockIdx.x * blockDim.x + threadIdx.x;
    if (i < n) a[i] = 0;
}
__global__ void k_hist(const int* __restrict__ dst, int* __restrict__ deg, int E) {
    int e = blockIdx.x * blockDim.x + threadIdx.x;
    if (e < E) atomicAdd(&deg[dst[e]], 1);
}
__global__ void k_scan1(const int* __restrict__ deg, int* __restrict__ bsum, int Nn) {
    __shared__ int s[256];
    int i = blockIdx.x * 256 + threadIdx.x;
    s[threadIdx.x] = (i < Nn) ? deg[i] : 0;
    __syncthreads();
    for (int o = 128; o; o >>= 1) {
        if (threadIdx.x < o) s[threadIdx.x] += s[threadIdx.x + o];
        __syncthreads();
    }
    if (threadIdx.x == 0) bsum[blockIdx.x] = s[0];
}
__global__ void k_scan2(int* __restrict__ bsum, int nb) {
    __shared__ int s[512];
    int t = threadIdx.x;
    int v = (t < nb) ? bsum[t] : 0;
    s[t] = v;
    __syncthreads();
    for (int o = 1; o < 512; o <<= 1) {
        int x = (t >= o) ? s[t - o] : 0;
        __syncthreads();
        s[t] += x;
        __syncthreads();
    }
    if (t < nb) bsum[t] = s[t] - v;
}
__global__ void k_scan3(const int* __restrict__ deg, const int* __restrict__ bsum,
                        int* __restrict__ off, int* __restrict__ cur, int Nn) {
    __shared__ int s[256];
    int i = blockIdx.x * 256 + threadIdx.x;
    int t = threadIdx.x;
    int v = (i < Nn) ? deg[i] : 0;
    s[t] = v;
    __syncthreads();
    for (int o = 1; o < 256; o <<= 1) {
        int x = (t >= o) ? s[t - o] : 0;
        __syncthreads();
        s[t] += x;
        __syncthreads();
    }
    if (i < Nn) {
        int excl = s[t] - v + bsum[blockIdx.x];
        off[i] = excl;
        cur[i] = excl;
    }
}
__global__ void k_scatter(const int* __restrict__ src, const int* __restrict__ dst,
                          int* __restrict__ cur, int2* __restrict__ pay, int E) {
    int e = blockIdx.x * blockDim.x + threadIdx.x;
    if (e >= E) return;
    int p = atomicAdd(&cur[dst[e]], 1);
    pay[p] = make_int2(src[e], e);
}

// ---------------- encoders ----------------
__global__ void k_node_enc(const int* __restrict__ x, const float* __restrict__ at,
                           float* __restrict__ node, int Nn) {
    int t = blockIdx.x * blockDim.x + threadIdx.x;
    if (t >= Nn * D) return;
    int i = t >> 6, j = t & 63;
    const int* xi = x + i * 9;
    float s = 0.f;
#pragma unroll
    for (int f = 0; f < 9; ++f) { int v = xi[f]; s += at[(f * 16 + v) * 64 + j]; }
    node[t] = s;
}

__global__ void __launch_bounds__(256) k_edge_enc2(const int* __restrict__ ea,
        const float* __restrict__ bt, const float* __restrict__ v0,
        float* __restrict__ edge, float4* __restrict__ aE4, int E) {
    int e = blockIdx.x * 8 + (threadIdx.x >> 5);
    int lane = threadIdx.x & 31;
    if (e >= E) return;
    int f0 = ea[e * 3], f1 = ea[e * 3 + 1], f2 = ea[e * 3 + 2];
    int c0 = 2 * lane, c1 = c0 + 1;
    float s0 = bt[f0 * 64 + c0] + bt[(8 + f1) * 64 + c0] + bt[(16 + f2) * 64 + c0];
    float s1 = bt[f0 * 64 + c1] + bt[(8 + f1) * 64 + c1] + bt[(16 + f2) * 64 + c1];
    ((float2*)(edge + e * 64))[lane] = make_float2(s0, s1);
    float p[4];
#pragma unroll
    for (int h = 0; h < 4; ++h) p[h] = s0 * v0[c0 * 4 + h] + s1 * v0[c1 * 4 + h];
#pragma unroll
    for (int o = 16; o; o >>= 1) {
#pragma unroll
        for (int h = 0; h < 4; ++h) p[h] += __shfl_xor_sync(0xffffffffu, p[h], o);
    }
    if (lane == 0)
        aE4[e] = make_float4(p[0] + v0[256], p[1] + v0[257], p[2] + v0[258], p[3] + v0[259]);
}

// ---------------- per-layer prep ----------------
__global__ void k_prep(const float* __restrict__ epW, const float* __restrict__ epb,
                       const float* __restrict__ attE, float* __restrict__ vall) {
    int l = blockIdx.x;
    const float* W = epW + l * 4096;
    const float* b = epb + l * 64;
    const float* aEv = attE + l * 64;
    float* vout = vall + l * 260;
    int t = threadIdx.x;
    if (t < 256) {
        int k = t >> 2, h = t & 3;
        float s = 0.f;
#pragma unroll
        for (int c = 0; c < 16; ++c) s += W[k * 64 + h * 16 + c] * aEv[h * 16 + c];
        vout[k * 4 + h] = s;
    }
    if (t < 4) {
        float s = 0.f;
#pragma unroll
        for (int c = 0; c < 16; ++c) s += b[t * 16 + c] * aEv[t * 16 + c];
        vout[256 + t] = s;
    }
}

// ---- weight pre-convert: fp32 W[k][n] -> bf16 hi/lo transposed [n][k] -------
__global__ void k_wconv(const float* __restrict__ euW1, const float* __restrict__ euW2,
                        __nv_bfloat16* __restrict__ wout) {
    int id = blockIdx.x * 256 + threadIdx.x;
    if (id >= 32768) return;
    int l = id >> 13, rem = id & 8191;
    int m = rem >> 12, kn = rem & 4095;      // m: 0 = W1c, 1 = W2
    int k = kn >> 6, n = kn & 63;
    float w = (m == 0) ? euW1[l * 12288 + 8192 + kn] : euW2[l * 4096 + kn];
    __nv_bfloat16 hi = __float2bfloat16_rn(w);
    __nv_bfloat16 lo = __float2bfloat16_rn(w - __bfloat162float(hi));
    size_t base = ((size_t)l * 4 + m * 2) * 4096 + n * 64 + k;
    wout[base] = hi;
    wout[base + 4096] = lo;
}

// ---------------- xh = node @ W + a_src/a_dst (FFMA) -------------------------
__global__ void __launch_bounds__(256, 2) k_xh_rb(const float* __restrict__ node,
        const float* __restrict__ W, const float* __restrict__ attS,
        const float* __restrict__ attD, float* __restrict__ xh,
        float* __restrict__ asrc, float* __restrict__ adst, int M) {
    __shared__ __align__(16) float sW[4096];
    __shared__ float sAS[64], sAD[64];
    for (int i = threadIdx.x; i < 4096; i += 256) sW[i] = W[i];
    if (threadIdx.x < 64) { sAS[threadIdx.x] = attS[threadIdx.x]; sAD[threadIdx.x] = attD[threadIdx.x]; }
    __syncthreads();
    int cg = threadIdx.x & 7, tq = threadIdx.x >> 3;
    int r0 = blockIdx.x * 128 + tq * 4;
    if (r0 >= M) return;
    ull acc[4][4];
#pragma unroll
    for (int t = 0; t < 4; ++t)
#pragma unroll
        for (int j = 0; j < 4; ++j) acc[t][j] = 0ull;
    rb8_mainloop(node, r0, M, (const ull*)sW, cg * 4, acc);
    int c0 = cg * 8;
#pragma unroll
    for (int t = 0; t < 4; ++t) {
        int r = r0 + t;
        float as = 0.f, ad = 0.f;
        float4 o[2];
#pragma unroll
        for (int q = 0; q < 2; ++q) {
            float2 v0 = upk(acc[t][2 * q]), v1 = upk(acc[t][2 * q + 1]);
            o[q] = make_float4(v0.x, v0.y, v1.x, v1.y);
            int c = c0 + 4 * q;
            as += v0.x * sAS[c] + v0.y * sAS[c + 1] + v1.x * sAS[c + 2] + v1.y * sAS[c + 3];
            ad += v0.x * sAD[c] + v0.y * sAD[c + 1] + v1.x * sAD[c + 2] + v1.y * sAD[c + 3];
        }
        as += __shfl_xor_sync(0xffffffffu, as, 1);
        ad += __shfl_xor_sync(0xffffffffu, ad, 1);
        if (r < M) {
            float4* xp = (float4*)(xh + (size_t)r * 64 + c0);
            xp[0] = o[0]; xp[1] = o[1];
            if ((cg & 1) == 0) {
                int h = cg >> 1;
                asrc[r * 4 + h] = as;
                adst[r * 4 + h] = ad;
            }
        }
    }
}

// --- CSR attention (online softmax) fused with LN/relu/residual node update ---
__global__ void __launch_bounds__(256) k_attn_fused(const int* __restrict__ off,
        const int* __restrict__ deg, const int2* __restrict__ pay,
        const float* __restrict__ asrc, const float* __restrict__ adst,
        const float* __restrict__ aE, const float* __restrict__ xh,
        const float* __restrict__ gatb, const float* __restrict__ lng,
        const float* __restrict__ lnb, float* __restrict__ node, int Nn) {
    int w = blockIdx.x * 8 + (threadIdx.x >> 5);
    int l = threadIdx.x & 31;
    if (w >= Nn) return;
    int beg = off[w], dg = deg[w];
    int h = l >> 3;
    float ad = adst[w * 4 + h];
    float mh = __int_as_float(0xff800000);
    float dh = 0.f;
    float2 acc = make_float2(0.f, 0.f);
    for (int i = 0; i < dg; ++i) {
        int2 p = pay[beg + i];
        float a = asrc[p.x * 4 + h] + ad + aE[p.y * 4 + h];
        a = a > 0.f ? a : 0.2f * a;
        float2 xv = ((const float2*)xh)[p.x * 32 + l];
        float mn = fmaxf(mh, a);
        float s = expf(mh - mn);
        float e = expf(a - mn);
        dh = dh * s + e;
        acc.x = acc.x * s + e * xv.x;
        acc.y = acc.y * s + e * xv.y;
        mh = mn;
    }
    float inv = 1.f / (dh + 1e-16f);
    float2 gb = __ldg((const float2*)gatb + l);
    float cvx = acc.x * inv + gb.x;
    float cvy = acc.y * inv + gb.y;
    float s = cvx + cvy, ss = cvx * cvx + cvy * cvy;
#pragma unroll
    for (int o = 16; o; o >>= 1) {
        s  += __shfl_xor_sync(0xffffffffu, s, o);
        ss += __shfl_xor_sync(0xffffffffu, ss, o);
    }
    float mu = s * (1.f / 64.f);
    float var = ss * (1.f / 64.f) - mu * mu;
    float r = rsqrtf(var + 1e-5f);
    float2 g = __ldg((const float2*)lng + l), b = __ldg((const float2*)lnb + l);
    float y0 = fmaxf((cvx - mu) * r * g.x + b.x, 0.f);
    float y1 = fmaxf((cvy - mu) * r * g.y + b.y, 0.f);
    float2* np = (float2*)node + w * 32 + l;
    float2 old = *np;
    *np = make_float2(old.x + y0, old.y + y1);
}

// ---------------- fused P+Q (FFMA) ----------------
__global__ void __launch_bounds__(256, 2) k_pq(const float* __restrict__ node,
        const float* __restrict__ Wa, const float* __restrict__ Wb,
        float* __restrict__ P, float* __restrict__ Q, int M) {
    __shared__ __align__(16) float sWa[4096];
    __shared__ __align__(16) float sWb[4096];
    for (int i = threadIdx.x; i < 4096; i += 256) { sWa[i] = Wa[i]; sWb[i] = Wb[i]; }
    __syncthreads();
    int cg = threadIdx.x & 7, tq = threadIdx.x >> 3;
    int r0 = blockIdx.x * 128 + tq * 4;
    if (r0 >= M) return;
    int c0 = cg * 8;
    ull acc[4][4];
#pragma unroll
    for (int t = 0; t < 4; ++t)
#pragma unroll
        for (int j = 0; j < 4; ++j) acc[t][j] = 0ull;
    rb8_mainloop(node, r0, M, (const ull*)sWa, cg * 4, acc);
#pragma unroll
    for (int t = 0; t < 4; ++t) {
        int r = r0 + t;
        if (r < M) {
            float4* op = (float4*)(P + (size_t)r * 64 + c0);
            float2 v0 = upk(acc[t][0]), v1 = upk(acc[t][1]);
            op[0] = make_float4(v0.x, v0.y, v1.x, v1.y);
            v0 = upk(acc[t][2]); v1 = upk(acc[t][3]);
            op[1] = make_float4(v0.x, v0.y, v1.x, v1.y);
        }
    }
#pragma unroll
    for (int t = 0; t < 4; ++t)
#pragma unroll
        for (int j = 0; j < 4; ++j) acc[t][j] = 0ull;
    rb8_mainloop(node, r0, M, (const ull*)sWb, cg * 4, acc);
#pragma unroll
    for (int t = 0; t < 4; ++t) {
        int r = r0 + t;
        if (r < M) {
            float4* op = (float4*)(Q + (size_t)r * 64 + c0);
            float2 v0 = upk(acc[t][0]), v1 = upk(acc[t][1]);
            op[0] = make_float4(v0.x, v0.y, v1.x, v1.y);
            v0 = upk(acc[t][2]); v1 = upk(acc[t][3]);
            op[1] = make_float4(v0.x, v0.y, v1.x, v1.y);
        }
    }
}

// ======= fused edge update via warp-level HMMA (bf16 hi/lo 3-term split) =====
// 256 threads / 8 warps; warp w owns rows [16w, 16w+16) of the 128-row tile.
// smem (dyn, elements of bf16, row stride 72):
//   A_hi [128][72] @ 0, A_lo @ 9216, W @ 18432: mats {W1hi,W1lo,W2hi,W2lo} x [64][72]
#define WSTR 72
template <int AEDGE>
__global__ void __launch_bounds__(256) k_eu_hmma(const float* __restrict__ edge,
        const float* __restrict__ P, const float* __restrict__ Q,
        const int* __restrict__ src, const int* __restrict__ dst,
        const __nv_bfloat16* __restrict__ wblk,
        const float* __restrict__ b1, const float* __restrict__ b2,
        float* __restrict__ out, const float* __restrict__ vE,
        float* __restrict__ aE, int E) {
    extern __shared__ __align__(16) char dyn[];
    __nv_bfloat16* aph = (__nv_bfloat16*)dyn;
    __nv_bfloat16* apl = aph + 128 * WSTR;
    __nv_bfloat16* swb = apl + 128 * WSTR;
    __shared__ float sB1[64], sB2[64], sV[260];

    int tid = threadIdx.x;
    int lane = tid & 31, warp = tid >> 5;
    int g = lane >> 2, t = lane & 3;
    int r0 = blockIdx.x * 128;

    if (tid < 64) { sB1[tid] = b1[tid]; sB2[tid] = b2[tid]; }
    if (AEDGE) { for (int i = tid; i < 260; i += 256) sV[i] = vE[i]; }
    // weights: 4 mats x [64][64] -> padded [64][72]
    for (int idx = tid; idx < 4096; idx += 256) {
        int mat = idx >> 10, rem = idx & 1023;
        int n = rem >> 4, k4 = rem & 15;
        uint2 wv = *(const uint2*)(wblk + (size_t)mat * 4096 + n * 64 + k4 * 4);
        *(uint2*)(swb + mat * 64 * WSTR + n * WSTR + k4 * 4) = wv;
    }
    // A tile: edge rows -> bf16 hi/lo (2 threads per row, 32 cols each)
    {
        int row = tid >> 1, half = tid & 1;
        int rr = r0 + row; if (rr >= E) rr = E - 1;
        const float4* er = (const float4*)(edge + (size_t)rr * 64) + half * 8;
        __nv_bfloat16* ah = aph + row * WSTR + half * 32;
        __nv_bfloat16* al = apl + row * WSTR + half * 32;
#pragma unroll
        for (int c = 0; c < 4; ++c) {
            uint4 hi, lo;
            cvt8(er[2 * c], er[2 * c + 1], hi, lo);
            *(uint2*)(ah + c * 8)     = make_uint2(hi.x, hi.y);
            *(uint2*)(ah + c * 8 + 4) = make_uint2(hi.z, hi.w);
            *(uint2*)(al + c * 8)     = make_uint2(lo.x, lo.y);
            *(uint2*)(al + c * 8 + 4) = make_uint2(lo.z, lo.w);
        }
    }
    __syncthreads();

    int ra = warp * 16 + g, rb = ra + 8;      // block-local rows of this thread
    bool va = (r0 + ra) < E, vb = (r0 + rb) < E;

    // ---------------- GEMM1: edge @ W1c ----------------
    float acc[8][4];
#pragma unroll
    for (int nt = 0; nt < 8; ++nt)
#pragma unroll
        for (int j = 0; j < 4; ++j) acc[nt][j] = 0.f;
    {
        const __nv_bfloat16* whi = swb;
        const __nv_bfloat16* wlo = swb + 64 * WSTR;
#pragma unroll
        for (int ks = 0; ks < 4; ++ks) {
            int k0 = ks * 16;
            int ab = ra * WSTR + k0 + 2 * t;
            uint32_t ah[4], al4[4];
            ah[0] = *(uint32_t*)(aph + ab);
            ah[1] = *(uint32_t*)(aph + ab + 8 * WSTR);
            ah[2] = *(uint32_t*)(aph + ab + 8);
            ah[3] = *(uint32_t*)(aph + ab + 8 * WSTR + 8);
            al4[0] = *(uint32_t*)(apl + ab);
            al4[1] = *(uint32_t*)(apl + ab + 8 * WSTR);
            al4[2] = *(uint32_t*)(apl + ab + 8);
            al4[3] = *(uint32_t*)(apl + ab + 8 * WSTR + 8);
#pragma unroll
            for (int nt = 0; nt < 8; ++nt) {
                int wo = (nt * 8 + g) * WSTR + k0 + 2 * t;
                uint32_t bh0 = *(uint32_t*)(whi + wo), bh1 = *(uint32_t*)(whi + wo + 8);
                uint32_t bl0 = *(uint32_t*)(wlo + wo), bl1 = *(uint32_t*)(wlo + wo + 8);
                MMA16816(acc[nt], ah, bh0, bh1);
                MMA16816(acc[nt], ah, bl0, bl1);
                MMA16816(acc[nt], al4, bh0, bh1);
            }
        }
    }
    // ---- epilogue1: h = relu(acc + P[src] + Q[dst] + b1) -> A tile (bf16 hi/lo)
    {
        int rga = r0 + ra; if (rga >= E) rga = E - 1;
        int rgb = r0 + rb; if (rgb >= E) rgb = E - 1;
        int sa = src[rga], da = dst[rga];
        int sb = src[rgb], db = dst[rgb];
        const float* Pa = P + (size_t)sa * 64;
        const float* Qa = Q + (size_t)da * 64;
        const float* Pb = P + (size_t)sb * 64;
        const float* Qb = Q + (size_t)db * 64;
#pragma unroll
        for (int nt = 0; nt < 8; ++nt) {
            int ca = nt * 8 + 2 * t;
            float2 pa = *(const float2*)(Pa + ca), qa = *(const float2*)(Qa + ca);
            float2 pb = *(const float2*)(Pb + ca), qb = *(const float2*)(Qb + ca);
            float u0 = fmaxf(acc[nt][0] + pa.x + qa.x + sB1[ca], 0.f);
            float u1 = fmaxf(acc[nt][1] + pa.y + qa.y + sB1[ca + 1], 0.f);
            float u2 = fmaxf(acc[nt][2] + pb.x + qb.x + sB1[ca], 0.f);
            float u3 = fmaxf(acc[nt][3] + pb.y + qb.y + sB1[ca + 1], 0.f);
            uint32_t hi, lo;
            cvt2(u0, u1, hi, lo);
            *(uint32_t*)(aph + ra * WSTR + ca) = hi;
            *(uint32_t*)(apl + ra * WSTR + ca) = lo;
            cvt2(u2, u3, hi, lo);
            *(uint32_t*)(aph + rb * WSTR + ca) = hi;
            *(uint32_t*)(apl + rb * WSTR + ca) = lo;
        }
    }
    __syncwarp();

    // ---------------- GEMM2: h @ W2 ----------------
#pragma unroll
    for (int nt = 0; nt < 8; ++nt)
#pragma unroll
        for (int j = 0; j < 4; ++j) acc[nt][j] = 0.f;
    {
        const __nv_bfloat16* whi = swb + 2 * 64 * WSTR;
        const __nv_bfloat16* wlo = swb + 3 * 64 * WSTR;
#pragma unroll
        for (int ks = 0; ks < 4; ++ks) {
            int k0 = ks * 16;
            int ab = ra * WSTR + k0 + 2 * t;
            uint32_t ah[4], al4[4];
            ah[0] = *(uint32_t*)(aph + ab);
            ah[1] = *(uint32_t*)(aph + ab + 8 * WSTR);
            ah[2] = *(uint32_t*)(aph + ab + 8);
            ah[3] = *(uint32_t*)(aph + ab + 8 * WSTR + 8);
            al4[0] = *(uint32_t*)(apl + ab);
            al4[1] = *(uint32_t*)(apl + ab + 8 * WSTR);
            al4[2] = *(uint32_t*)(apl + ab + 8);
            al4[3] = *(uint32_t*)(apl + ab + 8 * WSTR + 8);
#pragma unroll
            for (int nt = 0; nt < 8; ++nt) {
                int wo = (nt * 8 + g) * WSTR + k0 + 2 * t;
                uint32_t bh0 = *(uint32_t*)(whi + wo), bh1 = *(uint32_t*)(whi + wo + 8);
                uint32_t bl0 = *(uint32_t*)(wlo + wo), bl1 = *(uint32_t*)(wlo + wo + 8);
                MMA16816(acc[nt], ah, bh0, bh1);
                MMA16816(acc[nt], ah, bl0, bl1);
                MMA16816(acc[nt], al4, bh0, bh1);
            }
        }
    }
    // ---- epilogue2: out = relu(acc + b2), optional aE dot ----
    {
        float* oa = out + (size_t)(r0 + ra) * 64;
        float* ob = out + (size_t)(r0 + rb) * 64;
        float pa[4] = {0.f, 0.f, 0.f, 0.f}, pb[4] = {0.f, 0.f, 0.f, 0.f};
#pragma unroll
        for (int nt = 0; nt < 8; ++nt) {
            int ca = nt * 8 + 2 * t;
            float o0 = fmaxf(acc[nt][0] + sB2[ca], 0.f);
            float o1 = fmaxf(acc[nt][1] + sB2[ca + 1], 0.f);
            float o2 = fmaxf(acc[nt][2] + sB2[ca], 0.f);
            float o3 = fmaxf(acc[nt][3] + sB2[ca + 1], 0.f);
            if (va) *(float2*)(oa + ca) = make_float2(o0, o1);
            if (vb) *(float2*)(ob + ca) = make_float2(o2, o3);
            if (AEDGE) {
#pragma unroll
                for (int h = 0; h < 4; ++h) {
                    pa[h] += o0 * sV[ca * 4 + h] + o1 * sV[(ca + 1) * 4 + h];
                    pb[h] += o2 * sV[ca * 4 + h] + o3 * sV[(ca + 1) * 4 + h];
                }
            }
        }
        if (AEDGE) {
#pragma unroll
            for (int h = 0; h < 4; ++h) {
                pa[h] += __shfl_xor_sync(0xffffffffu, pa[h], 1);
                pa[h] += __shfl_xor_sync(0xffffffffu, pa[h], 2);
                pb[h] += __shfl_xor_sync(0xffffffffu, pb[h], 1);
                pb[h] += __shfl_xor_sync(0xffffffffu, pb[h], 2);
            }
            if (t == 0) {
                if (va) ((float4*)aE)[r0 + ra] = make_float4(pa[0] + sV[256], pa[1] + sV[257],
                                                             pa[2] + sV[258], pa[3] + sV[259]);
                if (vb) ((float4*)aE)[r0 + rb] = make_float4(pb[0] + sV[256], pb[1] + sV[257],
                                                             pb[2] + sV[258], pb[3] + sV[259]);
            }
        }
    }
}

__global__ void k_copy(const float4* __restrict__ s, float4* __restrict__ d, int n4) {
    int i = blockIdx.x * blockDim.x + threadIdx.x;
    if (i < n4) d[i] = s[i];
}

// ---------------- launch ----------------
extern "C" void kernel_launch(void* const* d_in, const int* in_sizes, int n_in,
                              void* d_out, int out_size) {
    const int*   x     = (const int*)d_in[0];
    const int*   ea    = (const int*)d_in[1];
    const int*   ei    = (const int*)d_in[2];
    const float* atomT = (const float*)d_in[3];
    const float* bondT = (const float*)d_in[4];
    const float* gatW  = (const float*)d_in[5];
    const float* gatb  = (const float*)d_in[6];
    const float* attS  = (const float*)d_in[7];
    const float* attD  = (const float*)d_in[8];
    const float* attE  = (const float*)d_in[9];
    const float* epW   = (const float*)d_in[10];
    const float* epb   = (const float*)d_in[11];
    const float* lng   = (const float*)d_in[12];
    const float* lnb   = (const float*)d_in[13];
    const float* euW1  = (const float*)d_in[14];
    const float* eub1  = (const float*)d_in[15];
    const float* euW2  = (const float*)d_in[16];
    const float* eub2  = (const float*)d_in[17];

    int N = in_sizes[0] / 9;
    int E = in_sizes[1] / 3;
    const int* src  = ei;
    const int* dstp = ei + E;
    float* out = (float*)d_out;

    float *node, *xh, *P, *Q, *asrc, *adst, *edge, *v, *aE;
    __nv_bfloat16* weu;
    int *deg, *off, *cur, *bsum;
    int2* pay;
    cudaGetSymbolAddress((void**)&node, g_node);
    cudaGetSymbolAddress((void**)&xh,   g_xh);
    cudaGetSymbolAddress((void**)&P,    g_P);
    cudaGetSymbolAddress((void**)&Q,    g_Q);
    cudaGetSymbolAddress((void**)&asrc, g_asrc);
    cudaGetSymbolAddress((void**)&adst, g_adst);
    cudaGetSymbolAddress((void**)&edge, g_edge);
    cudaGetSymbolAddress((void**)&v,    g_v);
    cudaGetSymbolAddress((void**)&aE,   g_aE);
    cudaGetSymbolAddress((void**)&weu,  g_weu);
    cudaGetSymbolAddress((void**)&deg,  g_deg);
    cudaGetSymbolAddress((void**)&off,  g_off);
    cudaGetSymbolAddress((void**)&cur,  g_cur);
    cudaGetSymbolAddress((void**)&bsum, g_bsum);
    cudaGetSymbolAddress((void**)&pay,  g_pay);

    const int EU_SMEM = (2 * 128 * WSTR + 4 * 64 * WSTR) * 2;  // 73728 bytes
    cudaFuncSetAttribute(k_eu_hmma<0>, cudaFuncAttributeMaxDynamicSharedMemorySize, EU_SMEM);
    cudaFuncSetAttribute(k_eu_hmma<1>, cudaFuncAttributeMaxDynamicSharedMemorySize, EU_SMEM);

    int nbN = (N + 255) / 256;
    int nbE = (E + 255) / 256;

    // CSR build
    k_zero<<<nbN, 256>>>(deg, N);
    k_hist<<<nbE, 256>>>(dstp, deg, E);
    k_scan1<<<nbN, 256>>>(deg, bsum, N);
    k_scan2<<<1, 512>>>(bsum, nbN);
    k_scan3<<<nbN, 256>>>(deg, bsum, off, cur, N);
    k_scatter<<<nbE, 256>>>(src, dstp, cur, pay, E);

    k_prep<<<4, 256>>>(epW, epb, attE, v);
    k_wconv<<<128, 256>>>(euW1, euW2, weu);
    k_node_enc<<<(N * 64 + 255) / 256, 256>>>(x, atomT, node, N);
    k_edge_enc2<<<(E + 7) / 8, 256>>>(ea, bondT, v, edge, (float4*)aE, E);

    int gN = (N + 127) / 128;
    int gE = (E + 127) / 128;
    int gW = (N + 7) / 8;

    for (int l = 0; l < 4; ++l) {
        k_xh_rb<<<gN, 256>>>(node, gatW + l * 4096, attS + l * 64, attD + l * 64,
                             xh, asrc, adst, N);
        k_attn_fused<<<gW, 256>>>(off, deg, pay, asrc, adst, aE, xh,
                                  gatb + l * 64, lng + l * 64, lnb + l * 64, node, N);
        k_pq<<<gN, 256>>>(node, euW1 + l * 12288, euW1 + l * 12288 + 4096, P, Q, N);
        const __nv_bfloat16* wb = weu + (size_t)l * 4 * 4096;
        if (l < 3) {
            k_eu_hmma<1><<<gE, 256, EU_SMEM>>>(edge, P, Q, src, dstp, wb,
                    eub1 + l * 64, eub2 + l * 64, edge, v + (l + 1) * 260, aE, E);
        } else {
            k_eu_hmma<0><<<gE, 256, EU_SMEM>>>(edge, P, Q, src, dstp, wb,
                    eub1 + l * 64, eub2 + l * 64, out + (size_t)N * 64,
                    nullptr, nullptr, E);
        }
    }

    k_copy<<<(N * 16 + 255) / 256, 256>>>((const float4*)node, (float4*)out, N * 16);
}

// round 10
// speedup vs baseline: 2.2754x; 1.0865x over previous
#include <cuda_runtime.h>
#include <cuda_bf16.h>
#include <cstdint>
#include <math.h>

#define D 64
#define NMAX 100000
#define EMAX 1200000

// ---------------- scratch (device globals; no allocation allowed) ----------------
__device__ float g_node[NMAX * D];
__device__ float g_xh[NMAX * D];
__device__ float g_P[NMAX * D];
__device__ float g_Q[NMAX * D];
__device__ float g_asrc[NMAX * 4];
__device__ float g_adst[NMAX * 4];
__device__ float g_edge[EMAX * D];
__device__ float g_aE[EMAX * 4];
__device__ float g_v[4 * 260];
// per layer 10 mats of 4096 bf16 (transposed [n][k]):
// gatW hi/lo | W1a hi/lo | W1b hi/lo | W1c hi/lo | W2 hi/lo
__device__ __align__(16) __nv_bfloat16 g_weu[4 * 10 * 4096];
// CSR scratch
__device__ int  g_deg[NMAX];
__device__ int  g_off[NMAX];
__device__ int  g_cur[NMAX];
__device__ int  g_bsum[512];
__device__ int2 g_pay[EMAX];

// ---------------- HMMA: m16n8k16 row.col f32.bf16.bf16.f32 -------------------
#define MMA16816(dd, aa, b0, b1) \
    asm volatile("mma.sync.aligned.m16n8k16.row.col.f32.bf16.bf16.f32 " \
        "{%0,%1,%2,%3},{%4,%5,%6,%7},{%8,%9},{%0,%1,%2,%3};" \
        : "+f"((dd)[0]), "+f"((dd)[1]), "+f"((dd)[2]), "+f"((dd)[3]) \
        : "r"((aa)[0]), "r"((aa)[1]), "r"((aa)[2]), "r"((aa)[3]), "r"(b0), "r"(b1))

// bf16 hi/lo split of 8 consecutive floats into two uint4 (8 bf16 each)
__device__ __forceinline__ void cvt8(const float4 v0, const float4 v1, uint4& hi, uint4& lo) {
    __nv_bfloat162 h0 = __floats2bfloat162_rn(v0.x, v0.y);
    __nv_bfloat162 h1 = __floats2bfloat162_rn(v0.z, v0.w);
    __nv_bfloat162 h2 = __floats2bfloat162_rn(v1.x, v1.y);
    __nv_bfloat162 h3 = __floats2bfloat162_rn(v1.z, v1.w);
    float2 f0 = __bfloat1622float2(h0), f1 = __bfloat1622float2(h1);
    float2 f2 = __bfloat1622float2(h2), f3 = __bfloat1622float2(h3);
    __nv_bfloat162 l0 = __floats2bfloat162_rn(v0.x - f0.x, v0.y - f0.y);
    __nv_bfloat162 l1 = __floats2bfloat162_rn(v0.z - f1.x, v0.w - f1.y);
    __nv_bfloat162 l2 = __floats2bfloat162_rn(v1.x - f2.x, v1.y - f2.y);
    __nv_bfloat162 l3 = __floats2bfloat162_rn(v1.z - f3.x, v1.w - f3.y);
    hi = make_uint4(*(uint32_t*)&h0, *(uint32_t*)&h1, *(uint32_t*)&h2, *(uint32_t*)&h3);
    lo = make_uint4(*(uint32_t*)&l0, *(uint32_t*)&l1, *(uint32_t*)&l2, *(uint32_t*)&l3);
}
__device__ __forceinline__ void cvt2(float x, float y, uint32_t& hi, uint32_t& lo) {
    __nv_bfloat162 h = __floats2bfloat162_rn(x, y);
    float2 f = __bfloat1622float2(h);
    __nv_bfloat162 l = __floats2bfloat162_rn(x - f.x, y - f.y);
    hi = *(uint32_t*)&h; lo = *(uint32_t*)&l;
}

#define WSTR 72
// one 64-wide hi/lo-split GEMM pass over the 128-row smem tile; acc += A @ W^T
__device__ __forceinline__ void hmma_gemm64(const __nv_bfloat16* __restrict__ aph,
        const __nv_bfloat16* __restrict__ apl, const __nv_bfloat16* __restrict__ whi,
        const __nv_bfloat16* __restrict__ wlo, int ra, int g, int t, float acc[8][4]) {
#pragma unroll
    for (int ks = 0; ks < 4; ++ks) {
        int k0 = ks * 16;
        int ab = ra * WSTR + k0 + 2 * t;
        uint32_t ah[4], al4[4];
        ah[0] = *(uint32_t*)(aph + ab);
        ah[1] = *(uint32_t*)(aph + ab + 8 * WSTR);
        ah[2] = *(uint32_t*)(aph + ab + 8);
        ah[3] = *(uint32_t*)(aph + ab + 8 * WSTR + 8);
        al4[0] = *(uint32_t*)(apl + ab);
        al4[1] = *(uint32_t*)(apl + ab + 8 * WSTR);
        al4[2] = *(uint32_t*)(apl + ab + 8);
        al4[3] = *(uint32_t*)(apl + ab + 8 * WSTR + 8);
#pragma unroll
        for (int nt = 0; nt < 8; ++nt) {
            int wo = (nt * 8 + g) * WSTR + k0 + 2 * t;
            uint32_t bh0 = *(uint32_t*)(whi + wo), bh1 = *(uint32_t*)(whi + wo + 8);
            uint32_t bl0 = *(uint32_t*)(wlo + wo), bl1 = *(uint32_t*)(wlo + wo + 8);
            MMA16816(acc[nt], ah, bh0, bh1);
            MMA16816(acc[nt], ah, bl0, bl1);
            MMA16816(acc[nt], al4, bh0, bh1);
        }
    }
}
// fill A tile (hi/lo) from fp32 rows: 2 threads per row, 32 cols each
__device__ __forceinline__ void fill_atile(const float* __restrict__ in, int r0, int M,
        __nv_bfloat16* __restrict__ aph, __nv_bfloat16* __restrict__ apl, int tid) {
    int row = tid >> 1, half = tid & 1;
    int rr = r0 + row; if (rr >= M) rr = M - 1;
    const float4* er = (const float4*)(in + (size_t)rr * 64) + half * 8;
    __nv_bfloat16* ah = aph + row * WSTR + half * 32;
    __nv_bfloat16* al = apl + row * WSTR + half * 32;
#pragma unroll
    for (int c = 0; c < 4; ++c) {
        uint4 hi, lo;
        cvt8(er[2 * c], er[2 * c + 1], hi, lo);
        *(uint2*)(ah + c * 8)     = make_uint2(hi.x, hi.y);
        *(uint2*)(ah + c * 8 + 4) = make_uint2(hi.z, hi.w);
        *(uint2*)(al + c * 8)     = make_uint2(lo.x, lo.y);
        *(uint2*)(al + c * 8 + 4) = make_uint2(lo.z, lo.w);
    }
}

// ---------------- CSR build ----------------
__global__ void k_zero(int* __restrict__ a, int n) {
    int i = blockIdx.x * blockDim.x + threadIdx.x;
    if (i < n) a[i] = 0;
}
__global__ void k_hist(const int* __restrict__ dst, int* __restrict__ deg, int E) {
    int e = blockIdx.x * blockDim.x + threadIdx.x;
    if (e < E) atomicAdd(&deg[dst[e]], 1);
}
__global__ void k_scan1(const int* __restrict__ deg, int* __restrict__ bsum, int Nn) {
    __shared__ int s[256];
    int i = blockIdx.x * 256 + threadIdx.x;
    s[threadIdx.x] = (i < Nn) ? deg[i] : 0;
    __syncthreads();
    for (int o = 128; o; o >>= 1) {
        if (threadIdx.x < o) s[threadIdx.x] += s[threadIdx.x + o];
        __syncthreads();
    }
    if (threadIdx.x == 0) bsum[blockIdx.x] = s[0];
}
__global__ void k_scan2(int* __restrict__ bsum, int nb) {
    __shared__ int s[512];
    int t = threadIdx.x;
    int v = (t < nb) ? bsum[t] : 0;
    s[t] = v;
    __syncthreads();
    for (int o = 1; o < 512; o <<= 1) {
        int x = (t >= o) ? s[t - o] : 0;
        __syncthreads();
        s[t] += x;
        __syncthreads();
    }
    if (t < nb) bsum[t] = s[t] - v;
}
__global__ void k_scan3(const int* __restrict__ deg, const int* __restrict__ bsum,
                        int* __restrict__ off, int* __restrict__ cur, int Nn) {
    __shared__ int s[256];
    int i = blockIdx.x * 256 + threadIdx.x;
    int t = threadIdx.x;
    int v = (i < Nn) ? deg[i] : 0;
    s[t] = v;
    __syncthreads();
    for (int o = 1; o < 256; o <<= 1) {
        int x = (t >= o) ? s[t - o] : 0;
        __syncthreads();
        s[t] += x;
        __syncthreads();
    }
    if (i < Nn) {
        int excl = s[t] - v + bsum[blockIdx.x];
        off[i] = excl;
        cur[i] = excl;
    }
}
__global__ void k_scatter(const int* __restrict__ src, const int* __restrict__ dst,
                          int* __restrict__ cur, int2* __restrict__ pay, int E) {
    int e = blockIdx.x * blockDim.x + threadIdx.x;
    if (e >= E) return;
    int p = atomicAdd(&cur[dst[e]], 1);
    pay[p] = make_int2(src[e], e);
}

// ---------------- encoders ----------------
__global__ void k_node_enc(const int* __restrict__ x, const float* __restrict__ at,
                           float* __restrict__ node, int Nn) {
    int t = blockIdx.x * blockDim.x + threadIdx.x;
    if (t >= Nn * D) return;
    int i = t >> 6, j = t & 63;
    const int* xi = x + i * 9;
    float s = 0.f;
#pragma unroll
    for (int f = 0; f < 9; ++f) { int v = xi[f]; s += at[(f * 16 + v) * 64 + j]; }
    node[t] = s;
}

__global__ void __launch_bounds__(256) k_edge_enc2(const int* __restrict__ ea,
        const float* __restrict__ bt, const float* __restrict__ v0,
        float* __restrict__ edge, float4* __restrict__ aE4, int E) {
    int e = blockIdx.x * 8 + (threadIdx.x >> 5);
    int lane = threadIdx.x & 31;
    if (e >= E) return;
    int f0 = ea[e * 3], f1 = ea[e * 3 + 1], f2 = ea[e * 3 + 2];
    int c0 = 2 * lane, c1 = c0 + 1;
    float s0 = bt[f0 * 64 + c0] + bt[(8 + f1) * 64 + c0] + bt[(16 + f2) * 64 + c0];
    float s1 = bt[f0 * 64 + c1] + bt[(8 + f1) * 64 + c1] + bt[(16 + f2) * 64 + c1];
    ((float2*)(edge + e * 64))[lane] = make_float2(s0, s1);
    float p[4];
#pragma unroll
    for (int h = 0; h < 4; ++h) p[h] = s0 * v0[c0 * 4 + h] + s1 * v0[c1 * 4 + h];
#pragma unroll
    for (int o = 16; o; o >>= 1) {
#pragma unroll
        for (int h = 0; h < 4; ++h) p[h] += __shfl_xor_sync(0xffffffffu, p[h], o);
    }
    if (lane == 0)
        aE4[e] = make_float4(p[0] + v0[256], p[1] + v0[257], p[2] + v0[258], p[3] + v0[259]);
}

// ---------------- per-layer prep ----------------
__global__ void k_prep(const float* __restrict__ epW, const float* __restrict__ epb,
                       const float* __restrict__ attE, float* __restrict__ vall) {
    int l = blockIdx.x;
    const float* W = epW + l * 4096;
    const float* b = epb + l * 64;
    const float* aEv = attE + l * 64;
    float* vout = vall + l * 260;
    int t = threadIdx.x;
    if (t < 256) {
        int k = t >> 2, h = t & 3;
        float s = 0.f;
#pragma unroll
        for (int c = 0; c < 16; ++c) s += W[k * 64 + h * 16 + c] * aEv[h * 16 + c];
        vout[k * 4 + h] = s;
    }
    if (t < 4) {
        float s = 0.f;
#pragma unroll
        for (int c = 0; c < 16; ++c) s += b[t * 16 + c] * aEv[t * 16 + c];
        vout[256 + t] = s;
    }
}

// ---- weight pre-convert: 5 mats/layer fp32 [k][n] -> bf16 hi/lo transposed [n][k]
__global__ void k_wconv(const float* __restrict__ gatW, const float* __restrict__ euW1,
                        const float* __restrict__ euW2, __nv_bfloat16* __restrict__ wout) {
    int id = blockIdx.x * 256 + threadIdx.x;
    if (id >= 4 * 5 * 4096) return;
    int l = id / (5 * 4096), rem = id % (5 * 4096);
    int m = rem >> 12, kn = rem & 4095;
    int k = kn >> 6, n = kn & 63;
    float w;
    if (m == 0)      w = gatW[l * 4096 + kn];
    else if (m == 1) w = euW1[l * 12288 + kn];
    else if (m == 2) w = euW1[l * 12288 + 4096 + kn];
    else if (m == 3) w = euW1[l * 12288 + 8192 + kn];
    else             w = euW2[l * 4096 + kn];
    __nv_bfloat16 hi = __float2bfloat16_rn(w);
    __nv_bfloat16 lo = __float2bfloat16_rn(w - __bfloat162float(hi));
    size_t base = ((size_t)l * 10 + m * 2) * 4096 + n * 64 + k;
    wout[base] = hi;
    wout[base + 4096] = lo;
}

// ---------------- xh = node @ gatW + a_src/a_dst (HMMA) ----------------------
// dyn smem: A_hi[128][72] | A_lo | W{hi,lo}[64][72]
__global__ void __launch_bounds__(256) k_xh_hmma(const float* __restrict__ node,
        const __nv_bfloat16* __restrict__ wblk, const float* __restrict__ attS,
        const float* __restrict__ attD, float* __restrict__ xh,
        float4* __restrict__ asrc4, float4* __restrict__ adst4, int M) {
    extern __shared__ __align__(16) char dyn[];
    __nv_bfloat16* aph = (__nv_bfloat16*)dyn;
    __nv_bfloat16* apl = aph + 128 * WSTR;
    __nv_bfloat16* swb = apl + 128 * WSTR;
    __shared__ float sAS[64], sAD[64];
    int tid = threadIdx.x;
    int lane = tid & 31, warp = tid >> 5;
    int g = lane >> 2, t = lane & 3;
    int r0 = blockIdx.x * 128;
    if (tid < 64) { sAS[tid] = attS[tid]; sAD[tid] = attD[tid]; }
    for (int idx = tid; idx < 2048; idx += 256) {
        int mat = idx >> 10, rem = idx & 1023;
        int n = rem >> 4, k4 = rem & 15;
        uint2 wv = *(const uint2*)(wblk + (size_t)mat * 4096 + n * 64 + k4 * 4);
        *(uint2*)(swb + mat * 64 * WSTR + n * WSTR + k4 * 4) = wv;
    }
    fill_atile(node, r0, M, aph, apl, tid);
    __syncthreads();

    int ra = warp * 16 + g, rb = ra + 8;
    bool va = (r0 + ra) < M, vb = (r0 + rb) < M;
    float acc[8][4];
#pragma unroll
    for (int nt = 0; nt < 8; ++nt)
#pragma unroll
        for (int j = 0; j < 4; ++j) acc[nt][j] = 0.f;
    hmma_gemm64(aph, apl, swb, swb + 64 * WSTR, ra, g, t, acc);

    float* xa = xh + (size_t)(r0 + ra) * 64;
    float* xb = xh + (size_t)(r0 + rb) * 64;
    float asa[4] = {0,0,0,0}, ada[4] = {0,0,0,0}, asb[4] = {0,0,0,0}, adb[4] = {0,0,0,0};
#pragma unroll
    for (int nt = 0; nt < 8; ++nt) {
        int ca = nt * 8 + 2 * t;
        int h = nt >> 1;
        if (va) *(float2*)(xa + ca) = make_float2(acc[nt][0], acc[nt][1]);
        if (vb) *(float2*)(xb + ca) = make_float2(acc[nt][2], acc[nt][3]);
        asa[h] += acc[nt][0] * sAS[ca] + acc[nt][1] * sAS[ca + 1];
        ada[h] += acc[nt][0] * sAD[ca] + acc[nt][1] * sAD[ca + 1];
        asb[h] += acc[nt][2] * sAS[ca] + acc[nt][3] * sAS[ca + 1];
        adb[h] += acc[nt][2] * sAD[ca] + acc[nt][3] * sAD[ca + 1];
    }
#pragma unroll
    for (int h = 0; h < 4; ++h) {
        asa[h] += __shfl_xor_sync(0xffffffffu, asa[h], 1);
        asa[h] += __shfl_xor_sync(0xffffffffu, asa[h], 2);
        ada[h] += __shfl_xor_sync(0xffffffffu, ada[h], 1);
        ada[h] += __shfl_xor_sync(0xffffffffu, ada[h], 2);
        asb[h] += __shfl_xor_sync(0xffffffffu, asb[h], 1);
        asb[h] += __shfl_xor_sync(0xffffffffu, asb[h], 2);
        adb[h] += __shfl_xor_sync(0xffffffffu, adb[h], 1);
        adb[h] += __shfl_xor_sync(0xffffffffu, adb[h], 2);
    }
    if (t == 0) {
        if (va) {
            asrc4[r0 + ra] = make_float4(asa[0], asa[1], asa[2], asa[3]);
            adst4[r0 + ra] = make_float4(ada[0], ada[1], ada[2], ada[3]);
        }
        if (vb) {
            asrc4[r0 + rb] = make_float4(asb[0], asb[1], asb[2], asb[3]);
            adst4[r0 + rb] = make_float4(adb[0], adb[1], adb[2], adb[3]);
        }
    }
}

// ---------------- P/Q = node @ {W1a, W1b} (HMMA, shared A tile) ---------------
// dyn smem: A_hi | A_lo | W1a{hi,lo} W1b{hi,lo}
__global__ void __launch_bounds__(256) k_pq_hmma(const float* __restrict__ node,
        const __nv_bfloat16* __restrict__ wblk, float* __restrict__ P,
        float* __restrict__ Q, int M) {
    extern __shared__ __align__(16) char dyn[];
    __nv_bfloat16* aph = (__nv_bfloat16*)dyn;
    __nv_bfloat16* apl = aph + 128 * WSTR;
    __nv_bfloat16* swb = apl + 128 * WSTR;
    int tid = threadIdx.x;
    int lane = tid & 31, warp = tid >> 5;
    int g = lane >> 2, t = lane & 3;
    int r0 = blockIdx.x * 128;
    for (int idx = tid; idx < 4096; idx += 256) {
        int mat = idx >> 10, rem = idx & 1023;
        int n = rem >> 4, k4 = rem & 15;
        uint2 wv = *(const uint2*)(wblk + (size_t)mat * 4096 + n * 64 + k4 * 4);
        *(uint2*)(swb + mat * 64 * WSTR + n * WSTR + k4 * 4) = wv;
    }
    fill_atile(node, r0, M, aph, apl, tid);
    __syncthreads();

    int ra = warp * 16 + g, rb = ra + 8;
    bool va = (r0 + ra) < M, vb = (r0 + rb) < M;
    float acc[8][4];
#pragma unroll
    for (int tgt = 0; tgt < 2; ++tgt) {
#pragma unroll
        for (int nt = 0; nt < 8; ++nt)
#pragma unroll
            for (int j = 0; j < 4; ++j) acc[nt][j] = 0.f;
        const __nv_bfloat16* whi = swb + (2 * tgt) * 64 * WSTR;
        hmma_gemm64(aph, apl, whi, whi + 64 * WSTR, ra, g, t, acc);
        float* o = tgt == 0 ? P : Q;
        float* oa = o + (size_t)(r0 + ra) * 64;
        float* ob = o + (size_t)(r0 + rb) * 64;
#pragma unroll
        for (int nt = 0; nt < 8; ++nt) {
            int ca = nt * 8 + 2 * t;
            if (va) *(float2*)(oa + ca) = make_float2(acc[nt][0], acc[nt][1]);
            if (vb) *(float2*)(ob + ca) = make_float2(acc[nt][2], acc[nt][3]);
        }
    }
}

// --- CSR attention (online softmax) fused with LN/relu/residual node update ---
__global__ void __launch_bounds__(256) k_attn_fused(const int* __restrict__ off,
        const int* __restrict__ deg, const int2* __restrict__ pay,
        const float* __restrict__ asrc, const float* __restrict__ adst,
        const float* __restrict__ aE, const float* __restrict__ xh,
        const float* __restrict__ gatb, const float* __restrict__ lng,
        const float* __restrict__ lnb, float* __restrict__ node, int Nn) {
    int w = blockIdx.x * 8 + (threadIdx.x >> 5);
    int l = threadIdx.x & 31;
    if (w >= Nn) return;
    int beg = off[w], dg = deg[w];
    int h = l >> 3;
    float ad = adst[w * 4 + h];
    float mh = __int_as_float(0xff800000);
    float dh = 0.f;
    float2 acc = make_float2(0.f, 0.f);
    for (int i = 0; i < dg; ++i) {
        int2 p = pay[beg + i];
        float a = asrc[p.x * 4 + h] + ad + aE[p.y * 4 + h];
        a = a > 0.f ? a : 0.2f * a;
        float2 xv = ((const float2*)xh)[p.x * 32 + l];
        float mn = fmaxf(mh, a);
        float s = expf(mh - mn);
        float e = expf(a - mn);
        dh = dh * s + e;
        acc.x = acc.x * s + e * xv.x;
        acc.y = acc.y * s + e * xv.y;
        mh = mn;
    }
    float inv = 1.f / (dh + 1e-16f);
    float2 gb = __ldg((const float2*)gatb + l);
    float cvx = acc.x * inv + gb.x;
    float cvy = acc.y * inv + gb.y;
    float s = cvx + cvy, ss = cvx * cvx + cvy * cvy;
#pragma unroll
    for (int o = 16; o; o >>= 1) {
        s  += __shfl_xor_sync(0xffffffffu, s, o);
        ss += __shfl_xor_sync(0xffffffffu, ss, o);
    }
    float mu = s * (1.f / 64.f);
    float var = ss * (1.f / 64.f) - mu * mu;
    float r = rsqrtf(var + 1e-5f);
    float2 g = __ldg((const float2*)lng + l), b = __ldg((const float2*)lnb + l);
    float y0 = fmaxf((cvx - mu) * r * g.x + b.x, 0.f);
    float y1 = fmaxf((cvy - mu) * r * g.y + b.y, 0.f);
    float2* np = (float2*)node + w * 32 + l;
    float2 old = *np;
    *np = make_float2(old.x + y0, old.y + y1);
}

// ======= fused edge update via warp-level HMMA (bf16 hi/lo 3-term split) =====
template <int AEDGE>
__global__ void __launch_bounds__(256) k_eu_hmma(const float* __restrict__ edge,
        const float* __restrict__ P, const float* __restrict__ Q,
        const int* __restrict__ src, const int* __restrict__ dst,
        const __nv_bfloat16* __restrict__ wblk,
        const float* __restrict__ b1, const float* __restrict__ b2,
        float* __restrict__ out, const float* __restrict__ vE,
        float* __restrict__ aE, int E) {
    extern __shared__ __align__(16) char dyn[];
    __nv_bfloat16* aph = (__nv_bfloat16*)dyn;
    __nv_bfloat16* apl = aph + 128 * WSTR;
    __nv_bfloat16* swb = apl + 128 * WSTR;
    __shared__ float sB1[64], sB2[64], sV[260];

    int tid = threadIdx.x;
    int lane = tid & 31, warp = tid >> 5;
    int g = lane >> 2, t = lane & 3;
    int r0 = blockIdx.x * 128;

    if (tid < 64) { sB1[tid] = b1[tid]; sB2[tid] = b2[tid]; }
    if (AEDGE) { for (int i = tid; i < 260; i += 256) sV[i] = vE[i]; }
    for (int idx = tid; idx < 4096; idx += 256) {
        int mat = idx >> 10, rem = idx & 1023;
        int n = rem >> 4, k4 = rem & 15;
        uint2 wv = *(const uint2*)(wblk + (size_t)mat * 4096 + n * 64 + k4 * 4);
        *(uint2*)(swb + mat * 64 * WSTR + n * WSTR + k4 * 4) = wv;
    }
    fill_atile(edge, r0, E, aph, apl, tid);
    __syncthreads();

    int ra = warp * 16 + g, rb = ra + 8;
    bool va = (r0 + ra) < E, vb = (r0 + rb) < E;

    // ---------------- GEMM1: edge @ W1c ----------------
    float acc[8][4];
#pragma unroll
    for (int nt = 0; nt < 8; ++nt)
#pragma unroll
        for (int j = 0; j < 4; ++j) acc[nt][j] = 0.f;
    hmma_gemm64(aph, apl, swb, swb + 64 * WSTR, ra, g, t, acc);

    // ---- epilogue1: h = relu(acc + P[src] + Q[dst] + b1) -> A tile
    {
        int rga = r0 + ra; if (rga >= E) rga = E - 1;
        int rgb = r0 + rb; if (rgb >= E) rgb = E - 1;
        int sa = src[rga], da = dst[rga];
        int sb = src[rgb], db = dst[rgb];
        const float* Pa = P + (size_t)sa * 64;
        const float* Qa = Q + (size_t)da * 64;
        const float* Pb = P + (size_t)sb * 64;
        const float* Qb = Q + (size_t)db * 64;
#pragma unroll
        for (int nt = 0; nt < 8; ++nt) {
            int ca = nt * 8 + 2 * t;
            float2 pa = *(const float2*)(Pa + ca), qa = *(const float2*)(Qa + ca);
            float2 pb = *(const float2*)(Pb + ca), qb = *(const float2*)(Qb + ca);
            float u0 = fmaxf(acc[nt][0] + pa.x + qa.x + sB1[ca], 0.f);
            float u1 = fmaxf(acc[nt][1] + pa.y + qa.y + sB1[ca + 1], 0.f);
            float u2 = fmaxf(acc[nt][2] + pb.x + qb.x + sB1[ca], 0.f);
            float u3 = fmaxf(acc[nt][3] + pb.y + qb.y + sB1[ca + 1], 0.f);
            uint32_t hi, lo;
            cvt2(u0, u1, hi, lo);
            *(uint32_t*)(aph + ra * WSTR + ca) = hi;
            *(uint32_t*)(apl + ra * WSTR + ca) = lo;
            cvt2(u2, u3, hi, lo);
            *(uint32_t*)(aph + rb * WSTR + ca) = hi;
            *(uint32_t*)(apl + rb * WSTR + ca) = lo;
        }
    }
    __syncwarp();

    // ---------------- GEMM2: h @ W2 ----------------
#pragma unroll
    for (int nt = 0; nt < 8; ++nt)
#pragma unroll
        for (int j = 0; j < 4; ++j) acc[nt][j] = 0.f;
    hmma_gemm64(aph, apl, swb + 2 * 64 * WSTR, swb + 3 * 64 * WSTR, ra, g, t, acc);

    // ---- epilogue2: out = relu(acc + b2), optional aE dot ----
    {
        float* oa = out + (size_t)(r0 + ra) * 64;
        float* ob = out + (size_t)(r0 + rb) * 64;
        float pa[4] = {0.f, 0.f, 0.f, 0.f}, pb[4] = {0.f, 0.f, 0.f, 0.f};
#pragma unroll
        for (int nt = 0; nt < 8; ++nt) {
            int ca = nt * 8 + 2 * t;
            float o0 = fmaxf(acc[nt][0] + sB2[ca], 0.f);
            float o1 = fmaxf(acc[nt][1] + sB2[ca + 1], 0.f);
            float o2 = fmaxf(acc[nt][2] + sB2[ca], 0.f);
            float o3 = fmaxf(acc[nt][3] + sB2[ca + 1], 0.f);
            if (va) *(float2*)(oa + ca) = make_float2(o0, o1);
            if (vb) *(float2*)(ob + ca) = make_float2(o2, o3);
            if (AEDGE) {
#pragma unroll
                for (int h = 0; h < 4; ++h) {
                    pa[h] += o0 * sV[ca * 4 + h] + o1 * sV[(ca + 1) * 4 + h];
                    pb[h] += o2 * sV[ca * 4 + h] + o3 * sV[(ca + 1) * 4 + h];
                }
            }
        }
        if (AEDGE) {
#pragma unroll
            for (int h = 0; h < 4; ++h) {
                pa[h] += __shfl_xor_sync(0xffffffffu, pa[h], 1);
                pa[h] += __shfl_xor_sync(0xffffffffu, pa[h], 2);
                pb[h] += __shfl_xor_sync(0xffffffffu, pb[h], 1);
                pb[h] += __shfl_xor_sync(0xffffffffu, pb[h], 2);
            }
            if (t == 0) {
                if (va) ((float4*)aE)[r0 + ra] = make_float4(pa[0] + sV[256], pa[1] + sV[257],
                                                             pa[2] + sV[258], pa[3] + sV[259]);
                if (vb) ((float4*)aE)[r0 + rb] = make_float4(pb[0] + sV[256], pb[1] + sV[257],
                                                             pb[2] + sV[258], pb[3] + sV[259]);
            }
        }
    }
}

__global__ void k_copy(const float4* __restrict__ s, float4* __restrict__ d, int n4) {
    int i = blockIdx.x * blockDim.x + threadIdx.x;
    if (i < n4) d[i] = s[i];
}

// ---------------- launch ----------------
extern "C" void kernel_launch(void* const* d_in, const int* in_sizes, int n_in,
                              void* d_out, int out_size) {
    const int*   x     = (const int*)d_in[0];
    const int*   ea    = (const int*)d_in[1];
    const int*   ei    = (const int*)d_in[2];
    const float* atomT = (const float*)d_in[3];
    const float* bondT = (const float*)d_in[4];
    const float* gatW  = (const float*)d_in[5];
    const float* gatb  = (const float*)d_in[6];
    const float* attS  = (const float*)d_in[7];
    const float* attD  = (const float*)d_in[8];
    const float* attE  = (const float*)d_in[9];
    const float* epW   = (const float*)d_in[10];
    const float* epb   = (const float*)d_in[11];
    const float* lng   = (const float*)d_in[12];
    const float* lnb   = (const float*)d_in[13];
    const float* euW1  = (const float*)d_in[14];
    const float* eub1  = (const float*)d_in[15];
    const float* euW2  = (const float*)d_in[16];
    const float* eub2  = (const float*)d_in[17];

    int N = in_sizes[0] / 9;
    int E = in_sizes[1] / 3;
    const int* src  = ei;
    const int* dstp = ei + E;
    float* out = (float*)d_out;

    float *node, *xh, *P, *Q, *asrc, *adst, *edge, *v, *aE;
    __nv_bfloat16* weu;
    int *deg, *off, *cur, *bsum;
    int2* pay;
    cudaGetSymbolAddress((void**)&node, g_node);
    cudaGetSymbolAddress((void**)&xh,   g_xh);
    cudaGetSymbolAddress((void**)&P,    g_P);
    cudaGetSymbolAddress((void**)&Q,    g_Q);
    cudaGetSymbolAddress((void**)&asrc, g_asrc);
    cudaGetSymbolAddress((void**)&adst, g_adst);
    cudaGetSymbolAddress((void**)&edge, g_edge);
    cudaGetSymbolAddress((void**)&v,    g_v);
    cudaGetSymbolAddress((void**)&aE,   g_aE);
    cudaGetSymbolAddress((void**)&weu,  g_weu);
    cudaGetSymbolAddress((void**)&deg,  g_deg);
    cudaGetSymbolAddress((void**)&off,  g_off);
    cudaGetSymbolAddress((void**)&cur,  g_cur);
    cudaGetSymbolAddress((void**)&bsum, g_bsum);
    cudaGetSymbolAddress((void**)&pay,  g_pay);

    const int EU_SMEM = (2 * 128 * WSTR + 4 * 64 * WSTR) * 2;  // 73728 bytes
    const int XH_SMEM = (2 * 128 * WSTR + 2 * 64 * WSTR) * 2;  // 55296 bytes
    cudaFuncSetAttribute(k_eu_hmma<0>, cudaFuncAttributeMaxDynamicSharedMemorySize, EU_SMEM);
    cudaFuncSetAttribute(k_eu_hmma<1>, cudaFuncAttributeMaxDynamicSharedMemorySize, EU_SMEM);
    cudaFuncSetAttribute(k_pq_hmma, cudaFuncAttributeMaxDynamicSharedMemorySize, EU_SMEM);
    cudaFuncSetAttribute(k_xh_hmma, cudaFuncAttributeMaxDynamicSharedMemorySize, XH_SMEM);

    int nbN = (N + 255) / 256;
    int nbE = (E + 255) / 256;

    // CSR build
    k_zero<<<nbN, 256>>>(deg, N);
    k_hist<<<nbE, 256>>>(dstp, deg, E);
    k_scan1<<<nbN, 256>>>(deg, bsum, N);
    k_scan2<<<1, 512>>>(bsum, nbN);
    k_scan3<<<nbN, 256>>>(deg, bsum, off, cur, N);
    k_scatter<<<nbE, 256>>>(src, dstp, cur, pay, E);

    k_prep<<<4, 256>>>(epW, epb, attE, v);
    k_wconv<<<(4 * 5 * 4096 + 255) / 256, 256>>>(gatW, euW1, euW2, weu);
    k_node_enc<<<(N * 64 + 255) / 256, 256>>>(x, atomT, node, N);
    k_edge_enc2<<<(E + 7) / 8, 256>>>(ea, bondT, v, edge, (float4*)aE, E);

    int gN = (N + 127) / 128;
    int gE = (E + 127) / 128;
    int gW = (N + 7) / 8;

    for (int l = 0; l < 4; ++l) {
        const __nv_bfloat16* wl = weu + (size_t)l * 10 * 4096;
        k_xh_hmma<<<gN, 256, XH_SMEM>>>(node, wl, attS + l * 64, attD + l * 64,
                                        xh, (float4*)asrc, (float4*)adst, N);
        k_attn_fused<<<gW, 256>>>(off, deg, pay, asrc, adst, aE, xh,
                                  gatb + l * 64, lng + l * 64, lnb + l * 64, node, N);
        k_pq_hmma<<<gN, 256, EU_SMEM>>>(node, wl + 2 * 4096, P, Q, N);
        if (l < 3) {
            k_eu_hmma<1><<<gE, 256, EU_SMEM>>>(edge, P, Q, src, dstp, wl + 6 * 4096,
                    eub1 + l * 64, eub2 + l * 64, edge, v + (l + 1) * 260, aE, E);
        } else {
            k_eu_hmma<0><<<gE, 256, EU_SMEM>>>(edge, P, Q, src, dstp, wl + 6 * 4096,
                    eub1 + l * 64, eub2 + l * 64, out + (size_t)N * 64,
                    nullptr, nullptr, E);
        }
    }

    k_copy<<<(N * 16 + 255) / 256, 256>>>((const float4*)node, (float4*)out, N * 16);
}